// round 2
// baseline (speedup 1.0000x reference)
#include <cuda_runtime.h>
#include <cuda_bf16.h>
#include <mma.h>

using namespace nvcuda;

#define BATCH 2
#define SEQ   4096
#define DIM   512
#define NH    8
#define HD    64
#define LDS   68   // padded leading dim (floats) for 64-wide tiles
#define LDSB  36   // padded leading dim for 32-wide k-chunks (proj)

// Scratch: q,k in [B,H,N,HD] fp32 (16 MB each). __device__ globals per allocation rules.
__device__ float g_q[(size_t)BATCH * NH * SEQ * HD];
__device__ float g_k[(size_t)BATCH * NH * SEQ * HD];

using FragA  = wmma::fragment<wmma::matrix_a, 16, 16, 8, wmma::precision::tf32, wmma::row_major>;
using FragBc = wmma::fragment<wmma::matrix_b, 16, 16, 8, wmma::precision::tf32, wmma::col_major>;
using FragBr = wmma::fragment<wmma::matrix_b, 16, 16, 8, wmma::precision::tf32, wmma::row_major>;
using FragC  = wmma::fragment<wmma::accumulator, 16, 16, 8, float>;

// ---------------------------------------------------------------------------
// Projection: out = x @ W^T + b -> g_q/g_k in [B,H,N,HD].
// Grid: ((B*SEQ)/128 = 64, DIM/64 = 8), 256 threads (8 warps, 16 rows each).
// K-chunks of 32 with register prefetch (explicit tf32 round-to-nearest).
// ---------------------------------------------------------------------------
__global__ void __launch_bounds__(256, 2)
proj_kernel(const float* __restrict__ x, const float* __restrict__ W,
            const float* __restrict__ bias, int which)
{
    // As: 128x32 (LDSB), Bs: 64x32 (LDSB). Epilogue reuses buffer as 128xLDS.
    __shared__ __align__(128) float sm[128 * LDS];   // 34816 B, covers both uses
    float* As = sm;                     // 128*LDSB = 4608 floats
    float* Bs = sm + 128 * LDSB;        // 64*LDSB  = 2304 floats

    const int tid  = threadIdx.x;
    const int warp = tid >> 5;
    const int m0   = blockIdx.x * 128;
    const int e0   = blockIdx.y * 64;

    FragC acc[4];
#pragma unroll
    for (int n = 0; n < 4; n++) wmma::fill_fragment(acc[n], 0.0f);

    float xr[16], wr[8];
    // prefetch chunk 0
#pragma unroll
    for (int i = 0; i < 16; i++) {
        int idx = tid + i * 256, r = idx >> 5, c = idx & 31;
        xr[i] = x[(size_t)(m0 + r) * DIM + c];
    }
#pragma unroll
    for (int i = 0; i < 8; i++) {
        int idx = tid + i * 256, r = idx >> 5, c = idx & 31;
        wr[i] = W[(size_t)(e0 + r) * DIM + c];
    }

    for (int kt = 0; kt < 16; kt++) {
#pragma unroll
        for (int i = 0; i < 16; i++) {
            int idx = tid + i * 256, r = idx >> 5, c = idx & 31;
            As[r * LDSB + c] = wmma::__float_to_tf32(xr[i]);
        }
#pragma unroll
        for (int i = 0; i < 8; i++) {
            int idx = tid + i * 256, r = idx >> 5, c = idx & 31;
            Bs[r * LDSB + c] = wmma::__float_to_tf32(wr[i]);
        }
        __syncthreads();

        if (kt < 15) {
            const int k0 = (kt + 1) * 32;
#pragma unroll
            for (int i = 0; i < 16; i++) {
                int idx = tid + i * 256, r = idx >> 5, c = idx & 31;
                xr[i] = x[(size_t)(m0 + r) * DIM + k0 + c];
            }
#pragma unroll
            for (int i = 0; i < 8; i++) {
                int idx = tid + i * 256, r = idx >> 5, c = idx & 31;
                wr[i] = W[(size_t)(e0 + r) * DIM + k0 + c];
            }
        }

#pragma unroll
        for (int kk = 0; kk < 4; kk++) {
            FragA a;
            wmma::load_matrix_sync(a, As + warp * 16 * LDSB + kk * 8, LDSB);
#pragma unroll
            for (int n = 0; n < 4; n++) {
                FragBc b;
                wmma::load_matrix_sync(b, Bs + n * 16 * LDSB + kk * 8, LDSB);
                wmma::mma_sync(acc[n], a, b, acc[n]);
            }
        }
        __syncthreads();
    }

    // Epilogue: acc -> smem (128xLDS) -> +bias -> gmem [B,H,N,HD]
#pragma unroll
    for (int n = 0; n < 4; n++)
        wmma::store_matrix_sync(sm + warp * 16 * LDS + n * 16, acc[n], LDS, wmma::mem_row_major);
    __syncthreads();

    float* dst = which ? g_k : g_q;
    const int h = blockIdx.y;
#pragma unroll
    for (int i = 0; i < 32; i++) {
        int idx = tid + i * 256;
        int r = idx >> 6, c = idx & 63;
        int m = m0 + r;
        int b = m >> 12;
        int nn = m & (SEQ - 1);
        dst[(((size_t)b * NH + h) * SEQ + nn) * HD + c] = sm[r * LDS + c] + bias[e0 + c];
    }
}

// ---------------------------------------------------------------------------
// Attention: per (b,h,q-tile of 128 rows). v = k (faithful bug). Logits are
// small, so no max-subtraction: accumulate O_unnorm and rowsum, divide at end.
// exp() applied directly on S accumulator fragments; P hits smem exactly once.
// K tiles register-prefetched (explicit tf32 RN conversion at STS).
// Grid: (SEQ/128=32, NH, BATCH), 256 threads. Dynamic smem 87.6 KB.
// ---------------------------------------------------------------------------
__global__ void __launch_bounds__(256, 2)
attn_kernel(float* __restrict__ out)
{
    extern __shared__ float sm[];
    float* Qs     = sm;                   // 128*LDS (pre-scaled by 512^-0.5)
    float* Ks     = sm + 128 * LDS;       // 64*LDS  (K tile == V tile)
    float* Ps     = sm + 192 * LDS;       // 128*LDS (P, then O)
    float* rowinv = sm + 320 * LDS;       // 128

    const int tid  = threadIdx.x;
    const int warp = tid >> 5;
    const int bh   = blockIdx.z * NH + blockIdx.y;
    const int q0   = blockIdx.x * 128;

    const float* qb = g_q + (size_t)bh * SEQ * HD + (size_t)q0 * HD;
    const float* kb = g_k + (size_t)bh * SEQ * HD;

    const float scale = 0.04419417382415922f;  // 512^-0.5 (full D, faithful quirk)

    // Q tile: 128x64, folded scale, tf32-rounded
#pragma unroll
    for (int i = 0; i < 32; i++) {
        int idx = tid + i * 256;
        int r = idx >> 6, c = idx & 63;
        Qs[r * LDS + c] = wmma::__float_to_tf32(qb[idx] * scale);
    }

    FragC oacc[4];
#pragma unroll
    for (int n = 0; n < 4; n++) wmma::fill_fragment(oacc[n], 0.0f);

    // K tile prefetch registers (64x64 / 256 thr = 16 each)
    float kr[16];
#pragma unroll
    for (int i = 0; i < 16; i++) kr[i] = kb[tid + i * 256];

    const int srow  = tid >> 1;
    const int shalf = (tid & 1) * 32;
    float     rsum  = 0.0f;

    for (int kt = 0; kt < SEQ / 64; kt++) {
        // stage K tile (regs -> smem, tf32 RN)
#pragma unroll
        for (int i = 0; i < 16; i++) {
            int idx = tid + i * 256;
            int r = idx >> 6, c = idx & 63;
            Ks[r * LDS + c] = wmma::__float_to_tf32(kr[i]);
        }
        __syncthreads();   // (A) K tile + (iter 0) Q tile visible

        // prefetch next K tile — overlaps with both mmas below
        if (kt < SEQ / 64 - 1) {
            const float* kp = kb + (size_t)(kt + 1) * 64 * HD;
#pragma unroll
            for (int i = 0; i < 16; i++) kr[i] = kp[tid + i * 256];
        }

        // S = Q K^T  (each warp: 16 rows x 64 cols)
        FragC sacc[4];
#pragma unroll
        for (int n = 0; n < 4; n++) wmma::fill_fragment(sacc[n], 0.0f);
#pragma unroll
        for (int kk = 0; kk < 8; kk++) {
            FragA a;
            wmma::load_matrix_sync(a, Qs + warp * 16 * LDS + kk * 8, LDS);
#pragma unroll
            for (int n = 0; n < 4; n++) {
                FragBc b;
                wmma::load_matrix_sync(b, Ks + n * 16 * LDS + kk * 8, LDS);
                wmma::mma_sync(sacc[n], a, b, sacc[n]);
            }
        }

        // P = exp(S) elementwise on fragments (uniform op), tf32-rounded,
        // then stored to smem exactly once.
#pragma unroll
        for (int n = 0; n < 4; n++) {
#pragma unroll
            for (int e = 0; e < sacc[n].num_elements; e++)
                sacc[n].x[e] = wmma::__float_to_tf32(__expf(sacc[n].x[e]));
            wmma::store_matrix_sync(Ps + warp * 16 * LDS + n * 16, sacc[n], LDS,
                                    wmma::mem_row_major);
        }
        __syncthreads();   // (B) P visible

        // rowsum (fp32, from smem P)
        {
            const float* pp = Ps + srow * LDS + shalf;
            float part = 0.0f;
#pragma unroll
            for (int c = 0; c < 32; c++) part += pp[c];
            rsum += part;
        }

        // O += P @ V   (V == K tile, row-major)
#pragma unroll
        for (int kk = 0; kk < 8; kk++) {
            FragA a;
            wmma::load_matrix_sync(a, Ps + warp * 16 * LDS + kk * 8, LDS);
#pragma unroll
            for (int n = 0; n < 4; n++) {
                FragBr b;
                wmma::load_matrix_sync(b, Ks + kk * 8 * LDS + n * 16, LDS);
                wmma::mma_sync(oacc[n], a, b, oacc[n]);
            }
        }
        __syncthreads();   // (C) Ks/Ps free for next iteration
    }

    // combine row halves (threads tid, tid^1 share a row)
    rsum += __shfl_xor_sync(0xffffffffu, rsum, 1);
    if ((tid & 1) == 0) rowinv[srow] = 1.0f / rsum;

#pragma unroll
    for (int n = 0; n < 4; n++)
        wmma::store_matrix_sync(Ps + warp * 16 * LDS + n * 16, oacc[n], LDS,
                                wmma::mem_row_major);
    __syncthreads();

    float* ob = out + ((size_t)blockIdx.z * SEQ + q0) * DIM + blockIdx.y * HD;
#pragma unroll
    for (int i = 0; i < 32; i++) {
        int idx = tid + i * 256;
        int r = idx >> 6, c = idx & 63;
        ob[(size_t)r * DIM + c] = Ps[r * LDS + c] * rowinv[r];
    }
}

// ---------------------------------------------------------------------------
extern "C" void kernel_launch(void* const* d_in, const int* in_sizes, int n_in,
                              void* d_out, int out_size)
{
    const float* x  = (const float*)d_in[0];
    const float* Wq = (const float*)d_in[1];
    const float* bq = (const float*)d_in[2];
    const float* Wk = (const float*)d_in[3];
    const float* bk = (const float*)d_in[4];
    float* out = (float*)d_out;

    dim3 pg((BATCH * SEQ) / 128, DIM / 64);
    proj_kernel<<<pg, 256>>>(x, Wq, bq, 0);
    proj_kernel<<<pg, 256>>>(x, Wk, bk, 1);

    const int smem_bytes = (320 * LDS + 128) * (int)sizeof(float);  // 87552
    cudaFuncSetAttribute(attn_kernel, cudaFuncAttributeMaxDynamicSharedMemorySize, smem_bytes);
    dim3 ag(SEQ / 128, NH, BATCH);
    attn_kernel<<<ag, 256, smem_bytes>>>(out);
}

// round 3
// speedup vs baseline: 1.0903x; 1.0903x over previous
#include <cuda_runtime.h>
#include <cuda_bf16.h>
#include <mma.h>

using namespace nvcuda;

#define BATCH 2
#define SEQ   4096
#define DIM   512
#define NH    8
#define HD    64
#define LDS   68   // padded leading dim (floats) for 64-wide tiles
#define LDSB  36   // padded leading dim for 32-wide k-chunks (proj)

// Scratch: q,k in [B,H,N,HD] fp32 (16 MB each). __device__ globals per allocation rules.
__device__ float g_q[(size_t)BATCH * NH * SEQ * HD];
__device__ float g_k[(size_t)BATCH * NH * SEQ * HD];

using FragA  = wmma::fragment<wmma::matrix_a, 16, 16, 8, wmma::precision::tf32, wmma::row_major>;
using FragBc = wmma::fragment<wmma::matrix_b, 16, 16, 8, wmma::precision::tf32, wmma::col_major>;
using FragBr = wmma::fragment<wmma::matrix_b, 16, 16, 8, wmma::precision::tf32, wmma::row_major>;
using FragC  = wmma::fragment<wmma::accumulator, 16, 16, 8, float>;

// ---------------------------------------------------------------------------
// Projection: out = x @ W^T + b -> g_q/g_k in [B,H,N,HD]. (unchanged from R2,
// it improved there: 98us, occ 22%)
// ---------------------------------------------------------------------------
__global__ void __launch_bounds__(256, 2)
proj_kernel(const float* __restrict__ x, const float* __restrict__ W,
            const float* __restrict__ bias, int which)
{
    __shared__ __align__(128) float sm[128 * LDS];
    float* As = sm;
    float* Bs = sm + 128 * LDSB;

    const int tid  = threadIdx.x;
    const int warp = tid >> 5;
    const int m0   = blockIdx.x * 128;
    const int e0   = blockIdx.y * 64;

    FragC acc[4];
#pragma unroll
    for (int n = 0; n < 4; n++) wmma::fill_fragment(acc[n], 0.0f);

    float xr[16], wr[8];
#pragma unroll
    for (int i = 0; i < 16; i++) {
        int idx = tid + i * 256, r = idx >> 5, c = idx & 31;
        xr[i] = x[(size_t)(m0 + r) * DIM + c];
    }
#pragma unroll
    for (int i = 0; i < 8; i++) {
        int idx = tid + i * 256, r = idx >> 5, c = idx & 31;
        wr[i] = W[(size_t)(e0 + r) * DIM + c];
    }

    for (int kt = 0; kt < 16; kt++) {
#pragma unroll
        for (int i = 0; i < 16; i++) {
            int idx = tid + i * 256, r = idx >> 5, c = idx & 31;
            As[r * LDSB + c] = wmma::__float_to_tf32(xr[i]);
        }
#pragma unroll
        for (int i = 0; i < 8; i++) {
            int idx = tid + i * 256, r = idx >> 5, c = idx & 31;
            Bs[r * LDSB + c] = wmma::__float_to_tf32(wr[i]);
        }
        __syncthreads();

        if (kt < 15) {
            const int k0 = (kt + 1) * 32;
#pragma unroll
            for (int i = 0; i < 16; i++) {
                int idx = tid + i * 256, r = idx >> 5, c = idx & 31;
                xr[i] = x[(size_t)(m0 + r) * DIM + k0 + c];
            }
#pragma unroll
            for (int i = 0; i < 8; i++) {
                int idx = tid + i * 256, r = idx >> 5, c = idx & 31;
                wr[i] = W[(size_t)(e0 + r) * DIM + k0 + c];
            }
        }

#pragma unroll
        for (int kk = 0; kk < 4; kk++) {
            FragA a;
            wmma::load_matrix_sync(a, As + warp * 16 * LDSB + kk * 8, LDSB);
#pragma unroll
            for (int n = 0; n < 4; n++) {
                FragBc b;
                wmma::load_matrix_sync(b, Bs + n * 16 * LDSB + kk * 8, LDSB);
                wmma::mma_sync(acc[n], a, b, acc[n]);
            }
        }
        __syncthreads();
    }

#pragma unroll
    for (int n = 0; n < 4; n++)
        wmma::store_matrix_sync(sm + warp * 16 * LDS + n * 16, acc[n], LDS, wmma::mem_row_major);
    __syncthreads();

    float* dst = which ? g_k : g_q;
    const int h = blockIdx.y;
#pragma unroll
    for (int i = 0; i < 32; i++) {
        int idx = tid + i * 256;
        int r = idx >> 6, c = idx & 63;
        int m = m0 + r;
        int b = m >> 12;
        int nn = m & (SEQ - 1);
        dst[(((size_t)b * NH + h) * SEQ + nn) * HD + c] = sm[r * LDS + c] + bias[e0 + c];
    }
}

// ---------------------------------------------------------------------------
// Attention, restructured:
//  - Q A-fragments resident in registers (loaded once)
//  - K double-buffered in smem, staged LDG->RN-cvt->STS (no reg buffer)
//  - P is warp-private: store_matrix -> __syncwarp -> load_matrix, no barrier
//  - rowsum read from warp's own P rows, no barrier
//  - exactly ONE __syncthreads per k-tile
// Grid: (SEQ/128=32, NH, BATCH), 256 threads (8 warps x 16 q-rows).
// Dynamic smem: (2*64 + 128)*LDS + 128 floats = 70144 B -> 2 CTA/SM.
// ---------------------------------------------------------------------------
__global__ void __launch_bounds__(256, 2)
attn_kernel(float* __restrict__ out)
{
    extern __shared__ float sm[];
    float* Ks0    = sm;                    //  64*LDS, buffer 0
    float* Ks1    = sm + 64 * LDS;         //  64*LDS, buffer 1
    float* Ps     = sm + 128 * LDS;        // 128*LDS: Q staging, then P, then O
    float* rowinv = sm + 256 * LDS;        // 128

    const int tid  = threadIdx.x;
    const int warp = tid >> 5;
    const int lane = tid & 31;
    const int bh   = blockIdx.z * NH + blockIdx.y;
    const int q0   = blockIdx.x * 128;

    const float* qb = g_q + (size_t)bh * SEQ * HD + (size_t)q0 * HD;
    const float* kb = g_k + (size_t)bh * SEQ * HD;

    const float scale = 0.04419417382415922f;  // 512^-0.5 (full D, faithful quirk)

    // --- Prologue: Q tile (scaled, RN tf32) -> Ps, then into register fragments
#pragma unroll
    for (int i = 0; i < 32; i++) {
        int idx = tid + i * 256;
        int r = idx >> 6, c = idx & 63;
        Ps[r * LDS + c] = wmma::__float_to_tf32(qb[idx] * scale);
    }
    __syncthreads();

    FragA qa[8];
#pragma unroll
    for (int kk = 0; kk < 8; kk++)
        wmma::load_matrix_sync(qa[kk], Ps + warp * 16 * LDS + kk * 8, LDS);
    // (each warp read only its own 16 rows of Ps; safe to overwrite them later)

    // Stage K tile 0 into Ks0
#pragma unroll
    for (int i = 0; i < 16; i++) {
        int idx = tid + i * 256;
        int r = idx >> 6, c = idx & 63;
        Ks0[r * LDS + c] = wmma::__float_to_tf32(kb[idx]);
    }
    __syncthreads();

    FragC oacc[4];
#pragma unroll
    for (int n = 0; n < 4; n++) wmma::fill_fragment(oacc[n], 0.0f);

    float rsum = 0.0f;
    float* Pw = Ps + warp * 16 * LDS;   // warp-private P rows

    for (int kt = 0; kt < SEQ / 64; kt++) {
        float* cur = (kt & 1) ? Ks1 : Ks0;
        float* nxt = (kt & 1) ? Ks0 : Ks1;

        // Stage next K tile (overwrites buffer everyone finished with at the
        // barrier ending iter kt-1). LDG latency overlaps other warps' mma.
        if (kt < SEQ / 64 - 1) {
            const float* kp = kb + (size_t)(kt + 1) * 64 * HD;
#pragma unroll
            for (int i = 0; i < 16; i++) {
                int idx = tid + i * 256;
                int r = idx >> 6, c = idx & 63;
                nxt[r * LDS + c] = wmma::__float_to_tf32(kp[idx]);
            }
        }

        // S = Q K^T  (Q from registers)
        FragC sacc[4];
#pragma unroll
        for (int n = 0; n < 4; n++) wmma::fill_fragment(sacc[n], 0.0f);
#pragma unroll
        for (int kk = 0; kk < 8; kk++) {
#pragma unroll
            for (int n = 0; n < 4; n++) {
                FragBc b;
                wmma::load_matrix_sync(b, cur + n * 16 * LDS + kk * 8, LDS);
                wmma::mma_sync(sacc[n], qa[kk], b, sacc[n]);
            }
        }

        // P = exp(S), RN tf32, stored to warp-private smem rows (no barrier)
#pragma unroll
        for (int n = 0; n < 4; n++) {
#pragma unroll
            for (int e = 0; e < sacc[n].num_elements; e++)
                sacc[n].x[e] = wmma::__float_to_tf32(__expf(sacc[n].x[e]));
            wmma::store_matrix_sync(Pw + n * 16, sacc[n], LDS, wmma::mem_row_major);
        }
        __syncwarp();

        // rowsum from warp's own P rows (2 lanes per row, 32 cols each)
        {
            const float* pp = Pw + (lane >> 1) * LDS + (lane & 1) * 32;
            float part = 0.0f;
#pragma unroll
            for (int c = 0; c < 32; c++) part += pp[c];
            rsum += part;
        }

        // O += P @ V  (V == K tile; A = warp-private P rows)
#pragma unroll
        for (int kk = 0; kk < 8; kk++) {
            FragA a;
            wmma::load_matrix_sync(a, Pw + kk * 8, LDS);
#pragma unroll
            for (int n = 0; n < 4; n++) {
                FragBr b;
                wmma::load_matrix_sync(b, cur + kk * 8 * LDS + n * 16, LDS);
                wmma::mma_sync(oacc[n], a, b, oacc[n]);
            }
        }

        __syncthreads();   // the single barrier: next-iter reads of nxt + reuse of cur
    }

    // finalize rowsums: lanes 2m,2m+1 hold halves of row warp*16+m
    rsum += __shfl_xor_sync(0xffffffffu, rsum, 1);
    if ((lane & 1) == 0) rowinv[warp * 16 + (lane >> 1)] = 1.0f / rsum;

#pragma unroll
    for (int n = 0; n < 4; n++)
        wmma::store_matrix_sync(Pw + n * 16, oacc[n], LDS, wmma::mem_row_major);
    __syncthreads();

    float* ob = out + ((size_t)blockIdx.z * SEQ + q0) * DIM + blockIdx.y * HD;
#pragma unroll
    for (int i = 0; i < 32; i++) {
        int idx = tid + i * 256;
        int r = idx >> 6, c = idx & 63;
        ob[(size_t)r * DIM + c] = Ps[r * LDS + c] * rowinv[r];
    }
}

// ---------------------------------------------------------------------------
extern "C" void kernel_launch(void* const* d_in, const int* in_sizes, int n_in,
                              void* d_out, int out_size)
{
    const float* x  = (const float*)d_in[0];
    const float* Wq = (const float*)d_in[1];
    const float* bq = (const float*)d_in[2];
    const float* Wk = (const float*)d_in[3];
    const float* bk = (const float*)d_in[4];
    float* out = (float*)d_out;

    dim3 pg((BATCH * SEQ) / 128, DIM / 64);
    proj_kernel<<<pg, 256>>>(x, Wq, bq, 0);
    proj_kernel<<<pg, 256>>>(x, Wk, bk, 1);

    const int smem_bytes = (256 * LDS + 128) * (int)sizeof(float);  // 70144
    cudaFuncSetAttribute(attn_kernel, cudaFuncAttributeMaxDynamicSharedMemorySize, smem_bytes);
    dim3 ag(SEQ / 128, NH, BATCH);
    attn_kernel<<<ag, 256, smem_bytes>>>(out);
}

// round 5
// speedup vs baseline: 2.8717x; 2.6338x over previous
#include <cuda_runtime.h>
#include <cuda_bf16.h>
#include <mma.h>
#include <cstdint>

using namespace nvcuda;

#define BATCH 2
#define SEQ   4096
#define DIM   512
#define NH    8
#define HD    64
#define LDS   68
#define LDSB  36

// Does this device-code pass support tcgen05 (sm_103a feature set)?
#if defined(__CUDA_ARCH__) && defined(__CUDA_ARCH_HAS_FEATURE__)
#if __CUDA_ARCH_HAS_FEATURE__(SM103_ALL)
#define TC_OK 1
#endif
#endif
#ifndef TC_OK
#define TC_OK 0
#endif

__device__ float g_q[(size_t)BATCH * NH * SEQ * HD];
__device__ float g_k[(size_t)BATCH * NH * SEQ * HD];

using FragA  = wmma::fragment<wmma::matrix_a, 16, 16, 8, wmma::precision::tf32, wmma::row_major>;
using FragBc = wmma::fragment<wmma::matrix_b, 16, 16, 8, wmma::precision::tf32, wmma::col_major>;
using FragBr = wmma::fragment<wmma::matrix_b, 16, 16, 8, wmma::precision::tf32, wmma::row_major>;
using FragC  = wmma::fragment<wmma::accumulator, 16, 16, 8, float>;

// ---------------------------------------------------------------------------
// Projection (R2 version: 98us each)
// ---------------------------------------------------------------------------
__global__ void __launch_bounds__(256, 2)
proj_kernel(const float* __restrict__ x, const float* __restrict__ W,
            const float* __restrict__ bias, int which)
{
    __shared__ __align__(128) float sm[128 * LDS];
    float* As = sm;
    float* Bs = sm + 128 * LDSB;

    const int tid  = threadIdx.x;
    const int warp = tid >> 5;
    const int m0   = blockIdx.x * 128;
    const int e0   = blockIdx.y * 64;

    FragC acc[4];
#pragma unroll
    for (int n = 0; n < 4; n++) wmma::fill_fragment(acc[n], 0.0f);

    float xr[16], wr[8];
#pragma unroll
    for (int i = 0; i < 16; i++) {
        int idx = tid + i * 256, r = idx >> 5, c = idx & 31;
        xr[i] = x[(size_t)(m0 + r) * DIM + c];
    }
#pragma unroll
    for (int i = 0; i < 8; i++) {
        int idx = tid + i * 256, r = idx >> 5, c = idx & 31;
        wr[i] = W[(size_t)(e0 + r) * DIM + c];
    }

    for (int kt = 0; kt < 16; kt++) {
#pragma unroll
        for (int i = 0; i < 16; i++) {
            int idx = tid + i * 256, r = idx >> 5, c = idx & 31;
            As[r * LDSB + c] = wmma::__float_to_tf32(xr[i]);
        }
#pragma unroll
        for (int i = 0; i < 8; i++) {
            int idx = tid + i * 256, r = idx >> 5, c = idx & 31;
            Bs[r * LDSB + c] = wmma::__float_to_tf32(wr[i]);
        }
        __syncthreads();

        if (kt < 15) {
            const int k0 = (kt + 1) * 32;
#pragma unroll
            for (int i = 0; i < 16; i++) {
                int idx = tid + i * 256, r = idx >> 5, c = idx & 31;
                xr[i] = x[(size_t)(m0 + r) * DIM + k0 + c];
            }
#pragma unroll
            for (int i = 0; i < 8; i++) {
                int idx = tid + i * 256, r = idx >> 5, c = idx & 31;
                wr[i] = W[(size_t)(e0 + r) * DIM + k0 + c];
            }
        }

#pragma unroll
        for (int kk = 0; kk < 4; kk++) {
            FragA a;
            wmma::load_matrix_sync(a, As + warp * 16 * LDSB + kk * 8, LDSB);
#pragma unroll
            for (int n = 0; n < 4; n++) {
                FragBc b;
                wmma::load_matrix_sync(b, Bs + n * 16 * LDSB + kk * 8, LDSB);
                wmma::mma_sync(acc[n], a, b, acc[n]);
            }
        }
        __syncthreads();
    }

#pragma unroll
    for (int n = 0; n < 4; n++)
        wmma::store_matrix_sync(sm + warp * 16 * LDS + n * 16, acc[n], LDS, wmma::mem_row_major);
    __syncthreads();

    float* dst = which ? g_k : g_q;
    const int h = blockIdx.y;
#pragma unroll
    for (int i = 0; i < 32; i++) {
        int idx = tid + i * 256;
        int r = idx >> 6, c = idx & 63;
        int m = m0 + r;
        int b = m >> 12;
        int nn = m & (SEQ - 1);
        dst[(((size_t)b * NH + h) * SEQ + nn) * HD + c] = sm[r * LDS + c] + bias[e0 + c];
    }
}

// ===========================================================================
// helpers
// ===========================================================================
__device__ __forceinline__ uint32_t smem_u32(const void* p) {
    uint32_t a;
    asm("{ .reg .u64 t; cvta.to.shared.u64 t, %1; cvt.u32.u64 %0, t; }" : "=r"(a) : "l"(p));
    return a;
}
__device__ __forceinline__ float cvt_tf32(float x) {
    float r; asm("cvt.rna.tf32.f32 %0, %1;" : "=f"(r) : "f"(x)); return r;
}

#if TC_OK
__device__ __forceinline__ uint32_t elect_one() {
    uint32_t p;
    asm volatile("{\n .reg .pred p;\n elect.sync _|p, 0xFFFFFFFF;\n selp.b32 %0, 1, 0, p;\n}" : "=r"(p));
    return p;
}
__device__ __forceinline__ void mbar_init(uint32_t mbar, uint32_t cnt) {
    asm volatile("mbarrier.init.shared.b64 [%0], %1;" :: "r"(mbar), "r"(cnt) : "memory");
}
__device__ __forceinline__ void mbar_inval(uint32_t mbar) {
    asm volatile("mbarrier.inval.shared.b64 [%0];" :: "r"(mbar) : "memory");
}
__device__ __forceinline__ void mbar_wait(uint32_t mbar, uint32_t parity) {
    asm volatile(
        "{\n .reg .pred P;\n"
        "W%=: mbarrier.try_wait.parity.acquire.cta.shared::cta.b64 P, [%0], %1, 0x989680;\n"
        " @P bra D%=;\n bra W%=;\n D%=:\n}"
        :: "r"(mbar), "r"(parity) : "memory");
}
__device__ __forceinline__ void tc_alloc(uint32_t smem_dst, uint32_t ncols) {
    asm volatile("tcgen05.alloc.cta_group::1.sync.aligned.shared::cta.b32 [%0], %1;"
                 :: "r"(smem_dst), "r"(ncols) : "memory");
}
__device__ __forceinline__ void tc_dealloc(uint32_t tmem, uint32_t ncols) {
    asm volatile("tcgen05.dealloc.cta_group::1.sync.aligned.b32 %0, %1;" :: "r"(tmem), "r"(ncols));
}
__device__ __forceinline__ void tc_commit(uint32_t mbar) {
    asm volatile("tcgen05.commit.cta_group::1.mbarrier::arrive::one.shared::cluster.b64 [%0];"
                 :: "r"(mbar) : "memory");
}
__device__ __forceinline__ void fence_before() { asm volatile("tcgen05.fence::before_thread_sync;" ::: "memory"); }
__device__ __forceinline__ void fence_after()  { asm volatile("tcgen05.fence::after_thread_sync;" ::: "memory"); }
__device__ __forceinline__ void fence_async()  { asm volatile("fence.proxy.async.shared::cta;" ::: "memory"); }
__device__ __forceinline__ void tc_wait_ld()   { asm volatile("tcgen05.wait::ld.sync.aligned;" ::: "memory"); }

__device__ __forceinline__ void mma_tf32_ss(uint32_t d, uint64_t a, uint64_t b,
                                            uint32_t idesc, uint32_t en) {
    asm volatile(
        "{\n .reg .pred p;\n setp.ne.u32 p, %5, 0;\n"
        " tcgen05.mma.cta_group::1.kind::tf32 [%0], %1, %2, %3, {%4, %4, %4, %4}, p;\n}"
        :: "r"(d), "l"(a), "l"(b), "r"(idesc), "r"(0u), "r"(en) : "memory");
}

__device__ __forceinline__ void ld32(uint32_t* r, uint32_t addr) {
    asm volatile(
        "tcgen05.ld.sync.aligned.32x32b.x32.b32 "
        "{%0,%1,%2,%3,%4,%5,%6,%7,%8,%9,%10,%11,%12,%13,%14,%15,"
        "%16,%17,%18,%19,%20,%21,%22,%23,%24,%25,%26,%27,%28,%29,%30,%31}, [%32];"
        : "=r"(r[0]),"=r"(r[1]),"=r"(r[2]),"=r"(r[3]),"=r"(r[4]),"=r"(r[5]),"=r"(r[6]),"=r"(r[7]),
          "=r"(r[8]),"=r"(r[9]),"=r"(r[10]),"=r"(r[11]),"=r"(r[12]),"=r"(r[13]),"=r"(r[14]),"=r"(r[15]),
          "=r"(r[16]),"=r"(r[17]),"=r"(r[18]),"=r"(r[19]),"=r"(r[20]),"=r"(r[21]),"=r"(r[22]),"=r"(r[23]),
          "=r"(r[24]),"=r"(r[25]),"=r"(r[26]),"=r"(r[27]),"=r"(r[28]),"=r"(r[29]),"=r"(r[30]),"=r"(r[31])
        : "r"(addr));
}

// SMEM descriptor: SW128 K-major, SBO=64, LBO=1, version=1 (Blackwell)
__device__ __forceinline__ uint64_t make_desc(uint32_t addr) {
    const uint64_t base = (uint64_t(2) << 61) | (uint64_t(1) << 46) |
                          (uint64_t(64) << 32) | (uint64_t(1) << 16);
    return base | ((uint64_t)(addr >> 4) & 0x3FFF);
}
#endif  // TC_OK helpers

// ===========================================================================
// Attention kernel. ONE symbol, two bodies:
//   TC_OK: tcgen05 tf32 SS pipeline (TMEM S/O, triple-buffered K/VT).
//   else : wmma fallback (R3 structure) — compiles in the compute_103 pass.
// Launch config (both): grid (SEQ/128, NH, BATCH), 256 thr, smem SM_TOTAL.
// ===========================================================================
#define SM_TMEMP  0
#define SM_MBAR   8
#define SM_Q      1024
#define SM_K0     33792
#define SM_VT0    82944
#define SM_P      132096
#define SM_RSA    164864
#define SM_RSB    165376
#define SM_TOTAL  166400

#define IDESC_TF32 ((1u<<4) | (2u<<7) | (2u<<10) | (8u<<17) | (8u<<24))  // F32 acc, tf32 a/b, N=64, M=128

__global__ void __launch_bounds__(256, 1)
attn_kernel(float* __restrict__ out)
{
#if TC_OK
    // ------------------------- tcgen05 path -------------------------------
    extern __shared__ __align__(1024) char smem[];
    const uint32_t sb = smem_u32(smem);

    const int tid  = threadIdx.x;
    const int wid  = tid >> 5;
    const int lane = tid & 31;
    const int sub  = wid & 3;
    const int half = wid >> 2;
    const int row  = sub * 32 + lane;

    const int bh = blockIdx.z * NH + blockIdx.y;
    const int q0 = blockIdx.x * 128;
    const float* qb = g_q + (size_t)bh * SEQ * HD + (size_t)q0 * HD;
    const float* kb = g_k + (size_t)bh * SEQ * HD;
    const float scale = 0.04419417382415922f;  // 512^-0.5

    if (wid == 0) tc_alloc(sb + SM_TMEMP, 128);

    // Stage Q (128x64, scale folded, tf32 RN, blocked SW128; 16 atom-rows/col-block)
    {
        const float4* q4 = (const float4*)qb;
#pragma unroll
        for (int i = 0; i < 8; i++) {
            int idx4 = tid + i * 256;
            int eb = idx4 * 4;
            int r = eb >> 6, c = eb & 63;
            float4 v = q4[idx4];
            uint32_t atom = (uint32_t)((r >> 3) + ((c >> 5) << 4));
            uint32_t off = atom * 1024 + (r & 7) * 128 + (c & 31) * 4;
            off ^= (uint32_t)(r & 7) << 4;
            *(float4*)(smem + SM_Q + off) = make_float4(
                cvt_tf32(v.x * scale), cvt_tf32(v.y * scale),
                cvt_tf32(v.z * scale), cvt_tf32(v.w * scale));
        }
    }
    // Stage K/VT tile 0 (64x64 each; 8 atom-rows/col-block)
    {
        const float4* k4 = (const float4*)kb;
#pragma unroll
        for (int i = 0; i < 4; i++) {
            int idx4 = tid + i * 256;
            int eb = idx4 * 4;
            int key = eb >> 6, h0 = eb & 63;
            float4 v = k4[idx4];
            float f[4] = {cvt_tf32(v.x), cvt_tf32(v.y), cvt_tf32(v.z), cvt_tf32(v.w)};
            uint32_t atomk = (uint32_t)((key >> 3) + ((h0 >> 5) << 3));
            uint32_t offk = atomk * 1024 + (key & 7) * 128 + (h0 & 31) * 4;
            offk ^= (uint32_t)(key & 7) << 4;
            *(float4*)(smem + SM_K0 + offk) = make_float4(f[0], f[1], f[2], f[3]);
#pragma unroll
            for (int j = 0; j < 4; j++) {
                int hd = h0 + j;
                uint32_t atomv = (uint32_t)((hd >> 3) + ((key >> 5) << 3));
                uint32_t offv = atomv * 1024 + (hd & 7) * 128 + (key & 31) * 4;
                offv ^= (uint32_t)(hd & 7) << 4;
                *(float*)(smem + SM_VT0 + offv) = f[j];
            }
        }
    }

    if (tid == 0) mbar_init(sb + SM_MBAR, 1);
    fence_async();
    fence_before();
    __syncthreads();

    uint32_t tmem;
    asm volatile("ld.shared.b32 %0, [%1];" : "=r"(tmem) : "r"(sb + SM_TMEMP));
    const uint32_t S_T = tmem;
    const uint32_t O_T = tmem + 64;
    const uint32_t mbar = sb + SM_MBAR;
    const uint64_t qd = make_desc(sb + SM_Q);
    const uint64_t pd = make_desc(sb + SM_P);

    // Prologue: S(0), commit #1
    if (wid == 0) {
        fence_after();
        if (elect_one()) {
            uint64_t kd = make_desc(sb + SM_K0);
#pragma unroll
            for (int s = 0; s < 8; s++) {
                uint64_t qo = (s < 4) ? (uint64_t)(s * 2) : (uint64_t)(1024 + (s - 4) * 2);
                uint64_t ko = (s < 4) ? (uint64_t)(s * 2) : (uint64_t)(512 + (s - 4) * 2);
                mma_tf32_ss(S_T, qd + qo, kd + ko, IDESC_TF32, s > 0);
            }
            tc_commit(mbar);
        }
    }

    float rsum = 0.0f;
    const uint32_t sld = S_T + (uint32_t)(half * 32);

    for (int kt = 0; kt < SEQ / 64; kt++) {
        const int nb = (kt + 1) % 3;
        const int cb = kt % 3;

        if (kt < SEQ / 64 - 1) {
            const float4* k4 = (const float4*)(kb + (size_t)(kt + 1) * 64 * HD);
            char* Kb = smem + SM_K0 + nb * 16384;
            char* Vb = smem + SM_VT0 + nb * 16384;
#pragma unroll
            for (int i = 0; i < 4; i++) {
                int idx4 = tid + i * 256;
                int eb = idx4 * 4;
                int key = eb >> 6, h0 = eb & 63;
                float4 v = k4[idx4];
                float f[4] = {cvt_tf32(v.x), cvt_tf32(v.y), cvt_tf32(v.z), cvt_tf32(v.w)};
                uint32_t atomk = (uint32_t)((key >> 3) + ((h0 >> 5) << 3));
                uint32_t offk = atomk * 1024 + (key & 7) * 128 + (h0 & 31) * 4;
                offk ^= (uint32_t)(key & 7) << 4;
                *(float4*)(Kb + offk) = make_float4(f[0], f[1], f[2], f[3]);
#pragma unroll
                for (int j = 0; j < 4; j++) {
                    int hd = h0 + j;
                    uint32_t atomv = (uint32_t)((hd >> 3) + ((key >> 5) << 3));
                    uint32_t offv = atomv * 1024 + (hd & 7) * 128 + (key & 31) * 4;
                    offv ^= (uint32_t)(hd & 7) << 4;
                    *(float*)(Vb + offv) = f[j];
                }
            }
        }

        mbar_wait(mbar, (uint32_t)(kt & 1));   // flip kt+1: S(kt) [and O(kt-1)] done
        fence_after();

        uint32_t sr[32];
        ld32(sr, sld);
        tc_wait_ld();

        float e[32];
#pragma unroll
        for (int c = 0; c < 32; c++) {
            e[c] = __expf(__uint_as_float(sr[c]));
            rsum += e[c];
        }
        {
            uint32_t atomp = (uint32_t)((row >> 3) + (half << 4));
            uint32_t basep = atomp * 1024 + (row & 7) * 128;
            uint32_t swx = (uint32_t)(row & 7) << 4;
#pragma unroll
            for (int j = 0; j < 32; j += 4) {
                uint32_t off = (basep + j * 4) ^ swx;
                *(float4*)(smem + SM_P + off) = make_float4(
                    cvt_tf32(e[j]), cvt_tf32(e[j + 1]), cvt_tf32(e[j + 2]), cvt_tf32(e[j + 3]));
            }
        }

        fence_async();
        fence_before();
        __syncthreads();

        if (wid == 0) {
            fence_after();
            if (elect_one()) {
                uint64_t vd = make_desc(sb + SM_VT0 + cb * 16384);
#pragma unroll
                for (int s = 0; s < 8; s++) {
                    uint64_t po = (s < 4) ? (uint64_t)(s * 2) : (uint64_t)(1024 + (s - 4) * 2);
                    uint64_t vo = (s < 4) ? (uint64_t)(s * 2) : (uint64_t)(512 + (s - 4) * 2);
                    mma_tf32_ss(O_T, pd + po, vd + vo, IDESC_TF32, (kt > 0) || (s > 0));
                }
                if (kt < SEQ / 64 - 1) {
                    uint64_t kd = make_desc(sb + SM_K0 + nb * 16384);
#pragma unroll
                    for (int s = 0; s < 8; s++) {
                        uint64_t qo = (s < 4) ? (uint64_t)(s * 2) : (uint64_t)(1024 + (s - 4) * 2);
                        uint64_t ko = (s < 4) ? (uint64_t)(s * 2) : (uint64_t)(512 + (s - 4) * 2);
                        mma_tf32_ss(S_T, qd + qo, kd + ko, IDESC_TF32, s > 0);
                    }
                }
                tc_commit(mbar);
            }
        }
    }

    mbar_wait(mbar, 0u);   // flip 65: O(63) done
    fence_after();

    *(float*)(smem + (half ? SM_RSB : SM_RSA) + row * 4) = rsum;

    uint32_t orr[32];
    ld32(orr, O_T + (uint32_t)(half * 32));
    tc_wait_ld();
    __syncthreads();

    float inv = 1.0f / (*(float*)(smem + SM_RSA + row * 4) +
                        *(float*)(smem + SM_RSB + row * 4));

    float* ob = out + ((size_t)blockIdx.z * SEQ + q0 + row) * DIM
                    + blockIdx.y * HD + half * 32;
#pragma unroll
    for (int j = 0; j < 32; j += 4) {
        *(float4*)(ob + j) = make_float4(__uint_as_float(orr[j]) * inv,
                                         __uint_as_float(orr[j + 1]) * inv,
                                         __uint_as_float(orr[j + 2]) * inv,
                                         __uint_as_float(orr[j + 3]) * inv);
    }

    fence_before();
    __syncthreads();
    if (tid == 0) mbar_inval(mbar);
    if (wid == 0) tc_dealloc(tmem, 128);

#else
    // ------------------------- wmma fallback (R3) -------------------------
    extern __shared__ float smf[];
    float* Ks0    = smf;
    float* Ks1    = smf + 64 * LDS;
    float* Ps     = smf + 128 * LDS;
    float* rowinv = smf + 256 * LDS;

    const int tid  = threadIdx.x;
    const int warp = tid >> 5;
    const int lane = tid & 31;
    const int bh   = blockIdx.z * NH + blockIdx.y;
    const int q0   = blockIdx.x * 128;

    const float* qb = g_q + (size_t)bh * SEQ * HD + (size_t)q0 * HD;
    const float* kb = g_k + (size_t)bh * SEQ * HD;
    const float scale = 0.04419417382415922f;

#pragma unroll
    for (int i = 0; i < 32; i++) {
        int idx = tid + i * 256;
        int r = idx >> 6, c = idx & 63;
        Ps[r * LDS + c] = wmma::__float_to_tf32(qb[idx] * scale);
    }
    __syncthreads();

    FragA qa[8];
#pragma unroll
    for (int kk = 0; kk < 8; kk++)
        wmma::load_matrix_sync(qa[kk], Ps + warp * 16 * LDS + kk * 8, LDS);

#pragma unroll
    for (int i = 0; i < 16; i++) {
        int idx = tid + i * 256;
        int r = idx >> 6, c = idx & 63;
        Ks0[r * LDS + c] = wmma::__float_to_tf32(kb[idx]);
    }
    __syncthreads();

    FragC oacc[4];
#pragma unroll
    for (int n = 0; n < 4; n++) wmma::fill_fragment(oacc[n], 0.0f);

    float rsum = 0.0f;
    float* Pw = Ps + warp * 16 * LDS;

    for (int kt = 0; kt < SEQ / 64; kt++) {
        float* cur = (kt & 1) ? Ks1 : Ks0;
        float* nxt = (kt & 1) ? Ks0 : Ks1;

        if (kt < SEQ / 64 - 1) {
            const float* kp = kb + (size_t)(kt + 1) * 64 * HD;
#pragma unroll
            for (int i = 0; i < 16; i++) {
                int idx = tid + i * 256;
                int r = idx >> 6, c = idx & 63;
                nxt[r * LDS + c] = wmma::__float_to_tf32(kp[idx]);
            }
        }

        FragC sacc[4];
#pragma unroll
        for (int n = 0; n < 4; n++) wmma::fill_fragment(sacc[n], 0.0f);
#pragma unroll
        for (int kk = 0; kk < 8; kk++) {
#pragma unroll
            for (int n = 0; n < 4; n++) {
                FragBc b;
                wmma::load_matrix_sync(b, cur + n * 16 * LDS + kk * 8, LDS);
                wmma::mma_sync(sacc[n], qa[kk], b, sacc[n]);
            }
        }

#pragma unroll
        for (int n = 0; n < 4; n++) {
#pragma unroll
            for (int e = 0; e < sacc[n].num_elements; e++)
                sacc[n].x[e] = wmma::__float_to_tf32(__expf(sacc[n].x[e]));
            wmma::store_matrix_sync(Pw + n * 16, sacc[n], LDS, wmma::mem_row_major);
        }
        __syncwarp();

        {
            const float* pp = Pw + (lane >> 1) * LDS + (lane & 1) * 32;
            float part = 0.0f;
#pragma unroll
            for (int c = 0; c < 32; c++) part += pp[c];
            rsum += part;
        }

#pragma unroll
        for (int kk = 0; kk < 8; kk++) {
            FragA a;
            wmma::load_matrix_sync(a, Pw + kk * 8, LDS);
#pragma unroll
            for (int n = 0; n < 4; n++) {
                FragBr b;
                wmma::load_matrix_sync(b, cur + kk * 8 * LDS + n * 16, LDS);
                wmma::mma_sync(oacc[n], a, b, oacc[n]);
            }
        }

        __syncthreads();
    }

    rsum += __shfl_xor_sync(0xffffffffu, rsum, 1);
    if ((lane & 1) == 0) rowinv[warp * 16 + (lane >> 1)] = 1.0f / rsum;

#pragma unroll
    for (int n = 0; n < 4; n++)
        wmma::store_matrix_sync(Pw + n * 16, oacc[n], LDS, wmma::mem_row_major);
    __syncthreads();

    float* ob = out + ((size_t)blockIdx.z * SEQ + q0) * DIM + blockIdx.y * HD;
#pragma unroll
    for (int i = 0; i < 32; i++) {
        int idx = tid + i * 256;
        int r = idx >> 6, c = idx & 63;
        ob[(size_t)r * DIM + c] = Ps[r * LDS + c] * rowinv[r];
    }
#endif
}

// ---------------------------------------------------------------------------
extern "C" void kernel_launch(void* const* d_in, const int* in_sizes, int n_in,
                              void* d_out, int out_size)
{
    const float* x  = (const float*)d_in[0];
    const float* Wq = (const float*)d_in[1];
    const float* bq = (const float*)d_in[2];
    const float* Wk = (const float*)d_in[3];
    const float* bk = (const float*)d_in[4];
    float* out = (float*)d_out;

    dim3 pg((BATCH * SEQ) / 128, DIM / 64);
    proj_kernel<<<pg, 256>>>(x, Wq, bq, 0);
    proj_kernel<<<pg, 256>>>(x, Wk, bk, 1);

    cudaFuncSetAttribute(attn_kernel, cudaFuncAttributeMaxDynamicSharedMemorySize, SM_TOTAL);
    dim3 ag(SEQ / 128, NH, BATCH);
    attn_kernel<<<ag, 256, SM_TOTAL>>>(out);
}

// round 6
// speedup vs baseline: 3.7360x; 1.3010x over previous
#include <cuda_runtime.h>
#include <cuda_bf16.h>
#include <mma.h>
#include <cstdint>

using namespace nvcuda;

#define BATCH 2
#define SEQ   4096
#define DIM   512
#define NH    8
#define HD    64
#define LDS   68
#define LDSB  36

#if defined(__CUDA_ARCH__) && defined(__CUDA_ARCH_HAS_FEATURE__)
#if __CUDA_ARCH_HAS_FEATURE__(SM103_ALL)
#define TC_OK 1
#endif
#endif
#ifndef TC_OK
#define TC_OK 0
#endif

__device__ float g_q[(size_t)BATCH * NH * SEQ * HD];
__device__ float g_k[(size_t)BATCH * NH * SEQ * HD];

using FragA  = wmma::fragment<wmma::matrix_a, 16, 16, 8, wmma::precision::tf32, wmma::row_major>;
using FragBc = wmma::fragment<wmma::matrix_b, 16, 16, 8, wmma::precision::tf32, wmma::col_major>;
using FragBr = wmma::fragment<wmma::matrix_b, 16, 16, 8, wmma::precision::tf32, wmma::row_major>;
using FragC  = wmma::fragment<wmma::accumulator, 16, 16, 8, float>;

// ===========================================================================
// helpers
// ===========================================================================
__device__ __forceinline__ uint32_t smem_u32(const void* p) {
    uint32_t a;
    asm("{ .reg .u64 t; cvta.to.shared.u64 t, %1; cvt.u32.u64 %0, t; }" : "=r"(a) : "l"(p));
    return a;
}
__device__ __forceinline__ float cvt_tf32(float x) {
    float r; asm("cvt.rna.tf32.f32 %0, %1;" : "=f"(r) : "f"(x)); return r;
}

#if TC_OK
__device__ __forceinline__ uint32_t elect_one() {
    uint32_t p;
    asm volatile("{\n .reg .pred p;\n elect.sync _|p, 0xFFFFFFFF;\n selp.b32 %0, 1, 0, p;\n}" : "=r"(p));
    return p;
}
__device__ __forceinline__ void mbar_init(uint32_t mbar, uint32_t cnt) {
    asm volatile("mbarrier.init.shared.b64 [%0], %1;" :: "r"(mbar), "r"(cnt) : "memory");
}
__device__ __forceinline__ void mbar_inval(uint32_t mbar) {
    asm volatile("mbarrier.inval.shared.b64 [%0];" :: "r"(mbar) : "memory");
}
__device__ __forceinline__ void mbar_wait(uint32_t mbar, uint32_t parity) {
    asm volatile(
        "{\n .reg .pred P;\n"
        "W%=: mbarrier.try_wait.parity.acquire.cta.shared::cta.b64 P, [%0], %1, 0x989680;\n"
        " @P bra D%=;\n bra W%=;\n D%=:\n}"
        :: "r"(mbar), "r"(parity) : "memory");
}
__device__ __forceinline__ void tc_alloc(uint32_t smem_dst, uint32_t ncols) {
    asm volatile("tcgen05.alloc.cta_group::1.sync.aligned.shared::cta.b32 [%0], %1;"
                 :: "r"(smem_dst), "r"(ncols) : "memory");
}
__device__ __forceinline__ void tc_dealloc(uint32_t tmem, uint32_t ncols) {
    asm volatile("tcgen05.dealloc.cta_group::1.sync.aligned.b32 %0, %1;" :: "r"(tmem), "r"(ncols));
}
__device__ __forceinline__ void tc_commit(uint32_t mbar) {
    asm volatile("tcgen05.commit.cta_group::1.mbarrier::arrive::one.shared::cluster.b64 [%0];"
                 :: "r"(mbar) : "memory");
}
__device__ __forceinline__ void fence_before() { asm volatile("tcgen05.fence::before_thread_sync;" ::: "memory"); }
__device__ __forceinline__ void fence_after()  { asm volatile("tcgen05.fence::after_thread_sync;" ::: "memory"); }
__device__ __forceinline__ void fence_async()  { asm volatile("fence.proxy.async.shared::cta;" ::: "memory"); }
__device__ __forceinline__ void tc_wait_ld()   { asm volatile("tcgen05.wait::ld.sync.aligned;" ::: "memory"); }

__device__ __forceinline__ void mma_tf32_ss(uint32_t d, uint64_t a, uint64_t b,
                                            uint32_t idesc, uint32_t en) {
    asm volatile(
        "{\n .reg .pred p;\n setp.ne.u32 p, %5, 0;\n"
        " tcgen05.mma.cta_group::1.kind::tf32 [%0], %1, %2, %3, {%4, %4, %4, %4}, p;\n}"
        :: "r"(d), "l"(a), "l"(b), "r"(idesc), "r"(0u), "r"(en) : "memory");
}

__device__ __forceinline__ void ld32(uint32_t* r, uint32_t addr) {
    asm volatile(
        "tcgen05.ld.sync.aligned.32x32b.x32.b32 "
        "{%0,%1,%2,%3,%4,%5,%6,%7,%8,%9,%10,%11,%12,%13,%14,%15,"
        "%16,%17,%18,%19,%20,%21,%22,%23,%24,%25,%26,%27,%28,%29,%30,%31}, [%32];"
        : "=r"(r[0]),"=r"(r[1]),"=r"(r[2]),"=r"(r[3]),"=r"(r[4]),"=r"(r[5]),"=r"(r[6]),"=r"(r[7]),
          "=r"(r[8]),"=r"(r[9]),"=r"(r[10]),"=r"(r[11]),"=r"(r[12]),"=r"(r[13]),"=r"(r[14]),"=r"(r[15]),
          "=r"(r[16]),"=r"(r[17]),"=r"(r[18]),"=r"(r[19]),"=r"(r[20]),"=r"(r[21]),"=r"(r[22]),"=r"(r[23]),
          "=r"(r[24]),"=r"(r[25]),"=r"(r[26]),"=r"(r[27]),"=r"(r[28]),"=r"(r[29]),"=r"(r[30]),"=r"(r[31])
        : "r"(addr));
}

__device__ __forceinline__ uint64_t make_desc(uint32_t addr) {
    const uint64_t base = (uint64_t(2) << 61) | (uint64_t(1) << 46) |
                          (uint64_t(64) << 32) | (uint64_t(1) << 16);
    return base | ((uint64_t)(addr >> 4) & 0x3FFF);
}
#endif  // TC_OK

#define IDESC_TF32 ((1u<<4) | (2u<<7) | (2u<<10) | (8u<<17) | (8u<<24))  // F32 acc, tf32 a/b, N=64, M=128

// descriptor K-step offsets (16B units): A tiles are 128 rows (16 atoms/col-block),
// B tiles are 64 rows (8 atoms/col-block)
#define AOFF(s) ((s) < 4 ? (uint64_t)((s) * 2) : (uint64_t)(1024 + ((s) - 4) * 2))
#define BOFF(s) ((s) < 4 ? (uint64_t)((s) * 2) : (uint64_t)(512  + ((s) - 4) * 2))

// ===========================================================================
// Projection: out = x @ W^T + b -> g_q (z=0) / g_k (z=1), layout [B,H,N,HD].
// Grid (64, 8, 2), 256 threads, dynamic smem PJ_TOTAL.
//   TC path: tcgen05 tf32 SS, K-chunks of 32, ring-of-3 buffers + mbar ring.
//   fallback: wmma (R2 body).
// ===========================================================================
#define PJ_TMEMP   0
#define PJ_BAR(i)  (8 + (i) * 8)
#define PJ_X       1024
#define PJ_XSTR    16384
#define PJ_W       (1024 + 3 * 16384)   /* 50176 */
#define PJ_WSTR    8192
#define PJ_TOTAL   74880

__global__ void __launch_bounds__(256, 2)
proj_kernel(const float* __restrict__ x,
            const float* __restrict__ Wq, const float* __restrict__ bq,
            const float* __restrict__ Wk, const float* __restrict__ bk)
{
    const int which = blockIdx.z;
    const float* W    = which ? Wk : Wq;
    const float* bias = which ? bk : bq;

#if TC_OK
    extern __shared__ __align__(1024) char smem[];
    const uint32_t sb = smem_u32(smem);

    const int tid  = threadIdx.x;
    const int wid  = tid >> 5;
    const int lane = tid & 31;
    const int half = wid >> 2;
    const int row  = (wid & 3) * 32 + lane;
    const int m0   = blockIdx.x * 128;
    const int e0   = blockIdx.y * 64;

    if (wid == 0) tc_alloc(sb + PJ_TMEMP, 64);
    if (tid == 0) {
        mbar_init(sb + PJ_BAR(0), 1);
        mbar_init(sb + PJ_BAR(1), 1);
        mbar_init(sb + PJ_BAR(2), 1);
    }

    // stage a 128x32 X chunk (k0 = chunk*32) into xbuf b / 64x32 W chunk into wbuf b
    auto stageX = [&](int k0, int b) {
#pragma unroll
        for (int i = 0; i < 4; i++) {
            int idx4 = tid + i * 256;            // 1024 float4
            int r = idx4 >> 3, c4 = (idx4 & 7) * 4;
            float4 v = *(const float4*)(x + (size_t)(m0 + r) * DIM + k0 + c4);
            uint32_t off = ((uint32_t)(r >> 3) * 1024 + (r & 7) * 128 + c4 * 4)
                           ^ ((uint32_t)(r & 7) << 4);
            *(float4*)(smem + PJ_X + b * PJ_XSTR + off) = make_float4(
                cvt_tf32(v.x), cvt_tf32(v.y), cvt_tf32(v.z), cvt_tf32(v.w));
        }
    };
    auto stageW = [&](int k0, int b) {
#pragma unroll
        for (int i = 0; i < 2; i++) {
            int idx4 = tid + i * 256;            // 512 float4
            int r = idx4 >> 3, c4 = (idx4 & 7) * 4;
            float4 v = *(const float4*)(W + (size_t)(e0 + r) * DIM + k0 + c4);
            uint32_t off = ((uint32_t)(r >> 3) * 1024 + (r & 7) * 128 + c4 * 4)
                           ^ ((uint32_t)(r & 7) << 4);
            *(float4*)(smem + PJ_W + b * PJ_WSTR + off) = make_float4(
                cvt_tf32(v.x), cvt_tf32(v.y), cvt_tf32(v.z), cvt_tf32(v.w));
        }
    };

    stageX(0, 0);  stageW(0, 0);
    stageX(32, 1); stageW(32, 1);
    fence_async();
    fence_before();
    __syncthreads();

    uint32_t tmem;
    asm volatile("ld.shared.b32 %0, [%1];" : "=r"(tmem) : "r"(sb + PJ_TMEMP));

    int ph0 = 0, ph1 = 0, ph2 = 0;
#pragma unroll
    for (int c = 0; c < 16; c++) {
        // issue chunk c (4 dispatches, K=8 each) on buf c%3
        if (wid == 0) {
            fence_after();
            if (elect_one()) {
                uint64_t ad = make_desc(sb + PJ_X + (c % 3) * PJ_XSTR);
                uint64_t bd = make_desc(sb + PJ_W + (c % 3) * PJ_WSTR);
#pragma unroll
                for (int s = 0; s < 4; s++)
                    mma_tf32_ss(tmem, ad + s * 2, bd + s * 2, IDESC_TF32, (c > 0) || (s > 0));
                tc_commit(sb + PJ_BAR(c % 3));
            }
        }
        if (c + 2 < 16) {
            const int b2 = (c + 2) % 3;
            if (c + 2 >= 3) {   // previous occupant of b2 is chunk c-1; wait its flip
                if (b2 == 0)      { mbar_wait(sb + PJ_BAR(0), (uint32_t)ph0); ph0 ^= 1; }
                else if (b2 == 1) { mbar_wait(sb + PJ_BAR(1), (uint32_t)ph1); ph1 ^= 1; }
                else              { mbar_wait(sb + PJ_BAR(2), (uint32_t)ph2); ph2 ^= 1; }
            }
            stageX((c + 2) * 32, b2);
            stageW((c + 2) * 32, b2);
            fence_async();
            fence_before();
            __syncthreads();
        }
    }

    // final: chunk 15 commits bar(15%3=0); wait with tracked phase
    mbar_wait(sb + PJ_BAR(0), (uint32_t)ph0);
    fence_after();

    uint32_t orr[32];
    ld32(orr, tmem + (uint32_t)(half * 32));
    tc_wait_ld();

    const int m = m0 + row;
    const int b = m >> 12;
    const int nn = m & (SEQ - 1);
    float* dst = (which ? g_k : g_q)
               + (((size_t)b * NH + blockIdx.y) * SEQ + nn) * HD + half * 32;
    const float* bp = bias + e0 + half * 32;
#pragma unroll
    for (int j = 0; j < 32; j += 4)
        *(float4*)(dst + j) = make_float4(__uint_as_float(orr[j])     + bp[j],
                                          __uint_as_float(orr[j + 1]) + bp[j + 1],
                                          __uint_as_float(orr[j + 2]) + bp[j + 2],
                                          __uint_as_float(orr[j + 3]) + bp[j + 3]);

    fence_before();
    __syncthreads();
    if (tid == 0) { mbar_inval(sb + PJ_BAR(0)); mbar_inval(sb + PJ_BAR(1)); mbar_inval(sb + PJ_BAR(2)); }
    if (wid == 0) tc_dealloc(tmem, 64);

#else
    // -------- wmma fallback (R2 body, dynamic smem) --------
    extern __shared__ float smf[];
    float* As = smf;
    float* Bs = smf + 128 * LDSB;

    const int tid  = threadIdx.x;
    const int warp = tid >> 5;
    const int m0   = blockIdx.x * 128;
    const int e0   = blockIdx.y * 64;

    FragC acc[4];
#pragma unroll
    for (int n = 0; n < 4; n++) wmma::fill_fragment(acc[n], 0.0f);

    float xr[16], wr[8];
#pragma unroll
    for (int i = 0; i < 16; i++) {
        int idx = tid + i * 256, r = idx >> 5, c = idx & 31;
        xr[i] = x[(size_t)(m0 + r) * DIM + c];
    }
#pragma unroll
    for (int i = 0; i < 8; i++) {
        int idx = tid + i * 256, r = idx >> 5, c = idx & 31;
        wr[i] = W[(size_t)(e0 + r) * DIM + c];
    }

    for (int kt = 0; kt < 16; kt++) {
#pragma unroll
        for (int i = 0; i < 16; i++) {
            int idx = tid + i * 256, r = idx >> 5, c = idx & 31;
            As[r * LDSB + c] = wmma::__float_to_tf32(xr[i]);
        }
#pragma unroll
        for (int i = 0; i < 8; i++) {
            int idx = tid + i * 256, r = idx >> 5, c = idx & 31;
            Bs[r * LDSB + c] = wmma::__float_to_tf32(wr[i]);
        }
        __syncthreads();

        if (kt < 15) {
            const int k0 = (kt + 1) * 32;
#pragma unroll
            for (int i = 0; i < 16; i++) {
                int idx = tid + i * 256, r = idx >> 5, c = idx & 31;
                xr[i] = x[(size_t)(m0 + r) * DIM + k0 + c];
            }
#pragma unroll
            for (int i = 0; i < 8; i++) {
                int idx = tid + i * 256, r = idx >> 5, c = idx & 31;
                wr[i] = W[(size_t)(e0 + r) * DIM + k0 + c];
            }
        }

#pragma unroll
        for (int kk = 0; kk < 4; kk++) {
            FragA a;
            wmma::load_matrix_sync(a, As + warp * 16 * LDSB + kk * 8, LDSB);
#pragma unroll
            for (int n = 0; n < 4; n++) {
                FragBc b;
                wmma::load_matrix_sync(b, Bs + n * 16 * LDSB + kk * 8, LDSB);
                wmma::mma_sync(acc[n], a, b, acc[n]);
            }
        }
        __syncthreads();
    }

#pragma unroll
    for (int n = 0; n < 4; n++)
        wmma::store_matrix_sync(smf + warp * 16 * LDS + n * 16, acc[n], LDS, wmma::mem_row_major);
    __syncthreads();

    float* dst = which ? g_k : g_q;
    const int h = blockIdx.y;
#pragma unroll
    for (int i = 0; i < 32; i++) {
        int idx = tid + i * 256;
        int r = idx >> 6, c = idx & 63;
        int m = m0 + r;
        int b = m >> 12;
        int nn = m & (SEQ - 1);
        dst[(((size_t)b * NH + h) * SEQ + nn) * HD + c] = smf[r * LDS + c] + bias[e0 + c];
    }
#endif
}

// ===========================================================================
// Attention. Grid (32, 8, 2), 256 threads, dynamic smem ATTN_TOTAL.
// TC path: S double-buffered in TMEM (S0@0,S1@64,O@128; alloc 256), split
// S-bar/O-bar, P double-buffered, K triple / VT triple buffered, K(kt+2)
// LDG-prefetched into registers at iteration top.
// ===========================================================================
#define AT_TMEMP  0
#define AT_SBAR   8
#define AT_OBAR   16
#define AT_RSA    32
#define AT_RSB    544
#define AT_Q      1024
#define AT_K      33792                    /* 3 x 16384 */
#define AT_VT     82944                    /* 3 x 16384 */
#define AT_P      132096                   /* 2 x 32768 */
#define ATTN_TOTAL 197632

__global__ void __launch_bounds__(256, 1)
attn_kernel(float* __restrict__ out)
{
#if TC_OK
    extern __shared__ __align__(1024) char smem[];
    const uint32_t sb = smem_u32(smem);

    const int tid  = threadIdx.x;
    const int wid  = tid >> 5;
    const int lane = tid & 31;
    const int half = wid >> 2;
    const int row  = (wid & 3) * 32 + lane;

    const int bh = blockIdx.z * NH + blockIdx.y;
    const int q0 = blockIdx.x * 128;
    const float* qb = g_q + (size_t)bh * SEQ * HD + (size_t)q0 * HD;
    const float* kb = g_k + (size_t)bh * SEQ * HD;
    const float scale = 0.04419417382415922f;  // 512^-0.5

    if (wid == 0) tc_alloc(sb + AT_TMEMP, 256);

    // Stage Q (128x64, scale folded, tf32, blocked SW128; 16 atoms/col-block)
    {
        const float4* q4 = (const float4*)qb;
#pragma unroll
        for (int i = 0; i < 8; i++) {
            int idx4 = tid + i * 256;
            int eb = idx4 * 4;
            int r = eb >> 6, c = eb & 63;
            float4 v = q4[idx4];
            uint32_t atom = (uint32_t)((r >> 3) + ((c >> 5) << 4));
            uint32_t off = (atom * 1024 + (r & 7) * 128 + (c & 31) * 4)
                           ^ ((uint32_t)(r & 7) << 4);
            *(float4*)(smem + AT_Q + off) = make_float4(
                cvt_tf32(v.x * scale), cvt_tf32(v.y * scale),
                cvt_tf32(v.z * scale), cvt_tf32(v.w * scale));
        }
    }

    // stage K/VT tile `t` into buffer b (values already loaded in kr[4] float4s)
    auto stageKV = [&](const float4* kr, int b) {
        char* Kb = smem + AT_K  + b * 16384;
        char* Vb = smem + AT_VT + b * 16384;
#pragma unroll
        for (int i = 0; i < 4; i++) {
            int idx4 = tid + i * 256;
            int eb = idx4 * 4;
            int key = eb >> 6, h0 = eb & 63;
            float4 v = kr[i];
            float f[4] = {cvt_tf32(v.x), cvt_tf32(v.y), cvt_tf32(v.z), cvt_tf32(v.w)};
            uint32_t offk = ((uint32_t)((key >> 3) + ((h0 >> 5) << 3)) * 1024
                             + (key & 7) * 128 + (h0 & 31) * 4) ^ ((uint32_t)(key & 7) << 4);
            *(float4*)(Kb + offk) = make_float4(f[0], f[1], f[2], f[3]);
#pragma unroll
            for (int j = 0; j < 4; j++) {
                int hd = h0 + j;
                uint32_t offv = ((uint32_t)((hd >> 3) + ((key >> 5) << 3)) * 1024
                                 + (hd & 7) * 128 + (key & 31) * 4) ^ ((uint32_t)(hd & 7) << 4);
                *(float*)(Vb + offv) = f[j];
            }
        }
    };

    // Prologue: stage tiles 0 and 1
    {
        float4 kr[4];
#pragma unroll
        for (int i = 0; i < 4; i++) kr[i] = ((const float4*)kb)[tid + i * 256];
        stageKV(kr, 0);
#pragma unroll
        for (int i = 0; i < 4; i++) kr[i] = ((const float4*)(kb + (size_t)64 * HD))[tid + i * 256];
        stageKV(kr, 1);
    }

    if (tid == 0) { mbar_init(sb + AT_SBAR, 1); mbar_init(sb + AT_OBAR, 1); }
    fence_async();
    fence_before();
    __syncthreads();

    uint32_t tmem;
    asm volatile("ld.shared.b32 %0, [%1];" : "=r"(tmem) : "r"(sb + AT_TMEMP));
    const uint32_t O_T  = tmem + 128;
    const uint32_t sbar = sb + AT_SBAR;
    const uint32_t obar = sb + AT_OBAR;
    const uint64_t qd   = make_desc(sb + AT_Q);

    // issue S(0) -> S-buf 0
    if (wid == 0) {
        fence_after();
        if (elect_one()) {
            uint64_t kd = make_desc(sb + AT_K);
#pragma unroll
            for (int s = 0; s < 8; s++)
                mma_tf32_ss(tmem, qd + AOFF(s), kd + BOFF(s), IDESC_TF32, s > 0);
            tc_commit(sbar);
        }
    }

    float rsum = 0.0f;

    for (int kt = 0; kt < SEQ / 64; kt++) {
        // 0. early LDG of K(kt+2)
        float4 kr[4];
        const bool do_stage = (kt + 2 < SEQ / 64);
        if (do_stage) {
            const float4* k4 = (const float4*)(kb + (size_t)(kt + 2) * 64 * HD);
#pragma unroll
            for (int i = 0; i < 4; i++) kr[i] = k4[tid + i * 256];
        }

        // 1. wait S(kt)   (flip kt+1, parity kt&1)
        mbar_wait(sbar, (uint32_t)(kt & 1));
        fence_after();

        // 2. issue S(kt+1) on the other S buffer immediately
        if (kt < SEQ / 64 - 1 && wid == 0) {
            if (elect_one()) {
                uint64_t kd = make_desc(sb + AT_K + ((kt + 1) % 3) * 16384);
                uint32_t dstS = tmem + (uint32_t)(((kt + 1) & 1) * 64);
#pragma unroll
                for (int s = 0; s < 8; s++)
                    mma_tf32_ss(dstS, qd + AOFF(s), kd + BOFF(s), IDESC_TF32, s > 0);
                tc_commit(sbar);
            }
        }

        // 3. LDTM S(kt) -> exp -> STS P(kt&1)  (overlaps S(kt+1) and O(kt-1) mmas)
        uint32_t sr[32];
        ld32(sr, tmem + (uint32_t)((kt & 1) * 64 + half * 32));
        tc_wait_ld();

        float e[32];
#pragma unroll
        for (int c = 0; c < 32; c++) {
            e[c] = __expf(__uint_as_float(sr[c]));
            rsum += e[c];
        }
        {
            char* Pb = smem + AT_P + (kt & 1) * 32768;
            uint32_t basep = ((uint32_t)((row >> 3) + (half << 4))) * 1024 + (row & 7) * 128;
            uint32_t swx = (uint32_t)(row & 7) << 4;
#pragma unroll
            for (int j = 0; j < 32; j += 4) {
                uint32_t off = (basep + j * 4) ^ swx;
                *(float4*)(Pb + off) = make_float4(
                    cvt_tf32(e[j]), cvt_tf32(e[j + 1]), cvt_tf32(e[j + 2]), cvt_tf32(e[j + 3]));
            }
        }

        // 4. wait O(kt-1)  (flip kt, parity (kt-1)&1 == (kt+1)&1) — frees VT buf (kt-1)%3
        if (kt >= 1) mbar_wait(obar, (uint32_t)((kt + 1) & 1));

        // 5. stage K/VT(kt+2) into buf (kt+2)%3 (== (kt-1)%3 for VT, now free)
        if (do_stage) stageKV(kr, (kt + 2) % 3);

        fence_async();
        fence_before();
        __syncthreads();

        // 6. issue O(kt) with P(kt&1) and VT(kt%3)
        if (wid == 0) {
            fence_after();
            if (elect_one()) {
                uint64_t pdk = make_desc(sb + AT_P + (kt & 1) * 32768);
                uint64_t vd  = make_desc(sb + AT_VT + (kt % 3) * 16384);
#pragma unroll
                for (int s = 0; s < 8; s++)
                    mma_tf32_ss(O_T, pdk + AOFF(s), vd + BOFF(s), IDESC_TF32, (kt > 0) || (s > 0));
                tc_commit(obar);
            }
        }
    }

    // final: O(63) = flip 64, parity 63&1 = 1
    mbar_wait(obar, 1u);
    fence_after();

    *(float*)(smem + (half ? AT_RSB : AT_RSA) + row * 4) = rsum;

    uint32_t orr[32];
    ld32(orr, O_T + (uint32_t)(half * 32));
    tc_wait_ld();
    __syncthreads();

    float inv = 1.0f / (*(float*)(smem + AT_RSA + row * 4) +
                        *(float*)(smem + AT_RSB + row * 4));

    float* ob = out + ((size_t)blockIdx.z * SEQ + q0 + row) * DIM
                    + blockIdx.y * HD + half * 32;
#pragma unroll
    for (int j = 0; j < 32; j += 4)
        *(float4*)(ob + j) = make_float4(__uint_as_float(orr[j]) * inv,
                                         __uint_as_float(orr[j + 1]) * inv,
                                         __uint_as_float(orr[j + 2]) * inv,
                                         __uint_as_float(orr[j + 3]) * inv);

    fence_before();
    __syncthreads();
    if (tid == 0) { mbar_inval(sbar); mbar_inval(obar); }
    if (wid == 0) tc_dealloc(tmem, 256);

#else
    // -------- wmma fallback (R3 body) --------
    extern __shared__ float smf[];
    float* Ks0    = smf;
    float* Ks1    = smf + 64 * LDS;
    float* Ps     = smf + 128 * LDS;
    float* rowinv = smf + 256 * LDS;

    const int tid  = threadIdx.x;
    const int warp = tid >> 5;
    const int lane = tid & 31;
    const int bh   = blockIdx.z * NH + blockIdx.y;
    const int q0   = blockIdx.x * 128;

    const float* qb = g_q + (size_t)bh * SEQ * HD + (size_t)q0 * HD;
    const float* kb = g_k + (size_t)bh * SEQ * HD;
    const float scale = 0.04419417382415922f;

#pragma unroll
    for (int i = 0; i < 32; i++) {
        int idx = tid + i * 256;
        int r = idx >> 6, c = idx & 63;
        Ps[r * LDS + c] = wmma::__float_to_tf32(qb[idx] * scale);
    }
    __syncthreads();

    FragA qa[8];
#pragma unroll
    for (int kk = 0; kk < 8; kk++)
        wmma::load_matrix_sync(qa[kk], Ps + warp * 16 * LDS + kk * 8, LDS);

#pragma unroll
    for (int i = 0; i < 16; i++) {
        int idx = tid + i * 256;
        int r = idx >> 6, c = idx & 63;
        Ks0[r * LDS + c] = wmma::__float_to_tf32(kb[idx]);
    }
    __syncthreads();

    FragC oacc[4];
#pragma unroll
    for (int n = 0; n < 4; n++) wmma::fill_fragment(oacc[n], 0.0f);

    float rsum = 0.0f;
    float* Pw = Ps + warp * 16 * LDS;

    for (int kt = 0; kt < SEQ / 64; kt++) {
        float* cur = (kt & 1) ? Ks1 : Ks0;
        float* nxt = (kt & 1) ? Ks0 : Ks1;

        if (kt < SEQ / 64 - 1) {
            const float* kp = kb + (size_t)(kt + 1) * 64 * HD;
#pragma unroll
            for (int i = 0; i < 16; i++) {
                int idx = tid + i * 256;
                int r = idx >> 6, c = idx & 63;
                nxt[r * LDS + c] = wmma::__float_to_tf32(kp[idx]);
            }
        }

        FragC sacc[4];
#pragma unroll
        for (int n = 0; n < 4; n++) wmma::fill_fragment(sacc[n], 0.0f);
#pragma unroll
        for (int kk = 0; kk < 8; kk++) {
#pragma unroll
            for (int n = 0; n < 4; n++) {
                FragBc b;
                wmma::load_matrix_sync(b, cur + n * 16 * LDS + kk * 8, LDS);
                wmma::mma_sync(sacc[n], qa[kk], b, sacc[n]);
            }
        }

#pragma unroll
        for (int n = 0; n < 4; n++) {
#pragma unroll
            for (int e = 0; e < sacc[n].num_elements; e++)
                sacc[n].x[e] = wmma::__float_to_tf32(__expf(sacc[n].x[e]));
            wmma::store_matrix_sync(Pw + n * 16, sacc[n], LDS, wmma::mem_row_major);
        }
        __syncwarp();

        {
            const float* pp = Pw + (lane >> 1) * LDS + (lane & 1) * 32;
            float part = 0.0f;
#pragma unroll
            for (int c = 0; c < 32; c++) part += pp[c];
            rsum += part;
        }

#pragma unroll
        for (int kk = 0; kk < 8; kk++) {
            FragA a;
            wmma::load_matrix_sync(a, Pw + kk * 8, LDS);
#pragma unroll
            for (int n = 0; n < 4; n++) {
                FragBr b;
                wmma::load_matrix_sync(b, cur + kk * 8 * LDS + n * 16, LDS);
                wmma::mma_sync(oacc[n], a, b, oacc[n]);
            }
        }

        __syncthreads();
    }

    rsum += __shfl_xor_sync(0xffffffffu, rsum, 1);
    if ((lane & 1) == 0) rowinv[warp * 16 + (lane >> 1)] = 1.0f / rsum;

#pragma unroll
    for (int n = 0; n < 4; n++)
        wmma::store_matrix_sync(Pw + n * 16, oacc[n], LDS, wmma::mem_row_major);
    __syncthreads();

    float* ob = out + ((size_t)blockIdx.z * SEQ + q0) * DIM + blockIdx.y * HD;
#pragma unroll
    for (int i = 0; i < 32; i++) {
        int idx = tid + i * 256;
        int r = idx >> 6, c = idx & 63;
        ob[(size_t)r * DIM + c] = Ps[r * LDS + c] * rowinv[r];
    }
#endif
}

// ---------------------------------------------------------------------------
extern "C" void kernel_launch(void* const* d_in, const int* in_sizes, int n_in,
                              void* d_out, int out_size)
{
    const float* x  = (const float*)d_in[0];
    const float* Wq = (const float*)d_in[1];
    const float* bq = (const float*)d_in[2];
    const float* Wk = (const float*)d_in[3];
    const float* bk = (const float*)d_in[4];
    float* out = (float*)d_out;

    cudaFuncSetAttribute(proj_kernel, cudaFuncAttributeMaxDynamicSharedMemorySize, PJ_TOTAL);
    dim3 pg((BATCH * SEQ) / 128, DIM / 64, 2);
    proj_kernel<<<pg, 256, PJ_TOTAL>>>(x, Wq, bq, Wk, bk);

    cudaFuncSetAttribute(attn_kernel, cudaFuncAttributeMaxDynamicSharedMemorySize, ATTN_TOTAL);
    dim3 ag(SEQ / 128, NH, BATCH);
    attn_kernel<<<ag, 256, ATTN_TOTAL>>>(out);
}

// round 8
// speedup vs baseline: 4.2859x; 1.1472x over previous
#include <cuda_runtime.h>
#include <cuda_bf16.h>
#include <mma.h>
#include <cstdint>

using namespace nvcuda;

#define BATCH 2
#define SEQ   4096
#define DIM   512
#define NH    8
#define HD    64
#define LDS   68
#define LDSB  36

#if defined(__CUDA_ARCH__) && defined(__CUDA_ARCH_HAS_FEATURE__)
#if __CUDA_ARCH_HAS_FEATURE__(SM103_ALL)
#define TC_OK 1
#endif
#endif
#ifndef TC_OK
#define TC_OK 0
#endif

__device__ float g_q[(size_t)BATCH * NH * SEQ * HD];
__device__ float g_k[(size_t)BATCH * NH * SEQ * HD];

using FragA  = wmma::fragment<wmma::matrix_a, 16, 16, 8, wmma::precision::tf32, wmma::row_major>;
using FragBc = wmma::fragment<wmma::matrix_b, 16, 16, 8, wmma::precision::tf32, wmma::col_major>;
using FragBr = wmma::fragment<wmma::matrix_b, 16, 16, 8, wmma::precision::tf32, wmma::row_major>;
using FragC  = wmma::fragment<wmma::accumulator, 16, 16, 8, float>;

// ===========================================================================
// helpers
// ===========================================================================
__device__ __forceinline__ uint32_t smem_u32(const void* p) {
    uint32_t a;
    asm("{ .reg .u64 t; cvta.to.shared.u64 t, %1; cvt.u32.u64 %0, t; }" : "=r"(a) : "l"(p));
    return a;
}
__device__ __forceinline__ float cvt_tf32(float x) {
    float r; asm("cvt.rna.tf32.f32 %0, %1;" : "=f"(r) : "f"(x)); return r;
}

#if TC_OK
__device__ __forceinline__ uint32_t elect_one() {
    uint32_t p;
    asm volatile("{\n .reg .pred p;\n elect.sync _|p, 0xFFFFFFFF;\n selp.b32 %0, 1, 0, p;\n}" : "=r"(p));
    return p;
}
__device__ __forceinline__ void mbar_init(uint32_t mbar, uint32_t cnt) {
    asm volatile("mbarrier.init.shared.b64 [%0], %1;" :: "r"(mbar), "r"(cnt) : "memory");
}
__device__ __forceinline__ void mbar_inval(uint32_t mbar) {
    asm volatile("mbarrier.inval.shared.b64 [%0];" :: "r"(mbar) : "memory");
}
__device__ __forceinline__ void mbar_wait(uint32_t mbar, uint32_t parity) {
    asm volatile(
        "{\n .reg .pred P;\n"
        "W%=: mbarrier.try_wait.parity.acquire.cta.shared::cta.b64 P, [%0], %1, 0x989680;\n"
        " @P bra D%=;\n bra W%=;\n D%=:\n}"
        :: "r"(mbar), "r"(parity) : "memory");
}
__device__ __forceinline__ void tc_alloc(uint32_t smem_dst, uint32_t ncols) {
    asm volatile("tcgen05.alloc.cta_group::1.sync.aligned.shared::cta.b32 [%0], %1;"
                 :: "r"(smem_dst), "r"(ncols) : "memory");
}
__device__ __forceinline__ void tc_dealloc(uint32_t tmem, uint32_t ncols) {
    asm volatile("tcgen05.dealloc.cta_group::1.sync.aligned.b32 %0, %1;" :: "r"(tmem), "r"(ncols));
}
__device__ __forceinline__ void tc_commit(uint32_t mbar) {
    asm volatile("tcgen05.commit.cta_group::1.mbarrier::arrive::one.shared::cluster.b64 [%0];"
                 :: "r"(mbar) : "memory");
}
__device__ __forceinline__ void fence_before() { asm volatile("tcgen05.fence::before_thread_sync;" ::: "memory"); }
__device__ __forceinline__ void fence_after()  { asm volatile("tcgen05.fence::after_thread_sync;" ::: "memory"); }
__device__ __forceinline__ void fence_async()  { asm volatile("fence.proxy.async.shared::cta;" ::: "memory"); }
__device__ __forceinline__ void tc_wait_ld()   { asm volatile("tcgen05.wait::ld.sync.aligned;" ::: "memory"); }

__device__ __forceinline__ void mma_tf32_ss(uint32_t d, uint64_t a, uint64_t b,
                                            uint32_t idesc, uint32_t en) {
    asm volatile(
        "{\n .reg .pred p;\n setp.ne.u32 p, %5, 0;\n"
        " tcgen05.mma.cta_group::1.kind::tf32 [%0], %1, %2, %3, {%4, %4, %4, %4}, p;\n}"
        :: "r"(d), "l"(a), "l"(b), "r"(idesc), "r"(0u), "r"(en) : "memory");
}

__device__ __forceinline__ void ld32(uint32_t* r, uint32_t addr) {
    asm volatile(
        "tcgen05.ld.sync.aligned.32x32b.x32.b32 "
        "{%0,%1,%2,%3,%4,%5,%6,%7,%8,%9,%10,%11,%12,%13,%14,%15,"
        "%16,%17,%18,%19,%20,%21,%22,%23,%24,%25,%26,%27,%28,%29,%30,%31}, [%32];"
        : "=r"(r[0]),"=r"(r[1]),"=r"(r[2]),"=r"(r[3]),"=r"(r[4]),"=r"(r[5]),"=r"(r[6]),"=r"(r[7]),
          "=r"(r[8]),"=r"(r[9]),"=r"(r[10]),"=r"(r[11]),"=r"(r[12]),"=r"(r[13]),"=r"(r[14]),"=r"(r[15]),
          "=r"(r[16]),"=r"(r[17]),"=r"(r[18]),"=r"(r[19]),"=r"(r[20]),"=r"(r[21]),"=r"(r[22]),"=r"(r[23]),
          "=r"(r[24]),"=r"(r[25]),"=r"(r[26]),"=r"(r[27]),"=r"(r[28]),"=r"(r[29]),"=r"(r[30]),"=r"(r[31])
        : "r"(addr));
}

// K-major SW128 descriptor: SBO=64, LBO=1, version=1
__device__ __forceinline__ uint64_t make_desc(uint32_t addr) {
    const uint64_t base = (uint64_t(2) << 61) | (uint64_t(1) << 46) |
                          (uint64_t(64) << 32) | (uint64_t(1) << 16);
    return base | ((uint64_t)(addr >> 4) & 0x3FFF);
}
#endif  // TC_OK

#define IDESC_TF32 ((1u<<4) | (2u<<7) | (2u<<10) | (8u<<17) | (8u<<24))  // F32 acc, tf32 a/b, N=64, M=128

// descriptor K-step offsets (16B units): A tiles 128 rows (16 atoms/col-block),
// B tiles 64 rows (8 atoms/col-block)
#define AOFF(s) ((s) < 4 ? (uint64_t)((s) * 2) : (uint64_t)(1024 + ((s) - 4) * 2))
#define BOFF(s) ((s) < 4 ? (uint64_t)((s) * 2) : (uint64_t)(512  + ((s) - 4) * 2))

// ===========================================================================
// Projection (unchanged from R6, ~40us total): grid (64, 8, 2), 256 thr.
// ===========================================================================
#define PJ_TMEMP   0
#define PJ_BAR(i)  (8 + (i) * 8)
#define PJ_X       1024
#define PJ_XSTR    16384
#define PJ_W       (1024 + 3 * 16384)
#define PJ_WSTR    8192
#define PJ_TOTAL   74880

__global__ void __launch_bounds__(256, 2)
proj_kernel(const float* __restrict__ x,
            const float* __restrict__ Wq, const float* __restrict__ bq,
            const float* __restrict__ Wk, const float* __restrict__ bk)
{
    const int which = blockIdx.z;
    const float* W    = which ? Wk : Wq;
    const float* bias = which ? bk : bq;

#if TC_OK
    extern __shared__ __align__(1024) char smem[];
    const uint32_t sb = smem_u32(smem);

    const int tid  = threadIdx.x;
    const int wid  = tid >> 5;
    const int lane = tid & 31;
    const int half = wid >> 2;
    const int row  = (wid & 3) * 32 + lane;
    const int m0   = blockIdx.x * 128;
    const int e0   = blockIdx.y * 64;

    if (wid == 0) tc_alloc(sb + PJ_TMEMP, 64);
    if (tid == 0) {
        mbar_init(sb + PJ_BAR(0), 1);
        mbar_init(sb + PJ_BAR(1), 1);
        mbar_init(sb + PJ_BAR(2), 1);
    }

    auto stageX = [&](int k0, int b) {
#pragma unroll
        for (int i = 0; i < 4; i++) {
            int idx4 = tid + i * 256;
            int r = idx4 >> 3, c4 = (idx4 & 7) * 4;
            float4 v = *(const float4*)(x + (size_t)(m0 + r) * DIM + k0 + c4);
            uint32_t off = ((uint32_t)(r >> 3) * 1024 + (r & 7) * 128 + c4 * 4)
                           ^ ((uint32_t)(r & 7) << 4);
            *(float4*)(smem + PJ_X + b * PJ_XSTR + off) = make_float4(
                cvt_tf32(v.x), cvt_tf32(v.y), cvt_tf32(v.z), cvt_tf32(v.w));
        }
    };
    auto stageW = [&](int k0, int b) {
#pragma unroll
        for (int i = 0; i < 2; i++) {
            int idx4 = tid + i * 256;
            int r = idx4 >> 3, c4 = (idx4 & 7) * 4;
            float4 v = *(const float4*)(W + (size_t)(e0 + r) * DIM + k0 + c4);
            uint32_t off = ((uint32_t)(r >> 3) * 1024 + (r & 7) * 128 + c4 * 4)
                           ^ ((uint32_t)(r & 7) << 4);
            *(float4*)(smem + PJ_W + b * PJ_WSTR + off) = make_float4(
                cvt_tf32(v.x), cvt_tf32(v.y), cvt_tf32(v.z), cvt_tf32(v.w));
        }
    };

    stageX(0, 0);  stageW(0, 0);
    stageX(32, 1); stageW(32, 1);
    fence_async();
    fence_before();
    __syncthreads();

    uint32_t tmem;
    asm volatile("ld.shared.b32 %0, [%1];" : "=r"(tmem) : "r"(sb + PJ_TMEMP));

    int ph0 = 0, ph1 = 0, ph2 = 0;
#pragma unroll
    for (int c = 0; c < 16; c++) {
        if (wid == 0) {
            fence_after();
            if (elect_one()) {
                uint64_t ad = make_desc(sb + PJ_X + (c % 3) * PJ_XSTR);
                uint64_t bd = make_desc(sb + PJ_W + (c % 3) * PJ_WSTR);
#pragma unroll
                for (int s = 0; s < 4; s++)
                    mma_tf32_ss(tmem, ad + s * 2, bd + s * 2, IDESC_TF32, (c > 0) || (s > 0));
                tc_commit(sb + PJ_BAR(c % 3));
            }
        }
        if (c + 2 < 16) {
            const int b2 = (c + 2) % 3;
            if (c + 2 >= 3) {
                if (b2 == 0)      { mbar_wait(sb + PJ_BAR(0), (uint32_t)ph0); ph0 ^= 1; }
                else if (b2 == 1) { mbar_wait(sb + PJ_BAR(1), (uint32_t)ph1); ph1 ^= 1; }
                else              { mbar_wait(sb + PJ_BAR(2), (uint32_t)ph2); ph2 ^= 1; }
            }
            stageX((c + 2) * 32, b2);
            stageW((c + 2) * 32, b2);
            fence_async();
            fence_before();
            __syncthreads();
        }
    }

    mbar_wait(sb + PJ_BAR(0), (uint32_t)ph0);
    fence_after();

    uint32_t orr[32];
    ld32(orr, tmem + (uint32_t)(half * 32));
    tc_wait_ld();

    const int m = m0 + row;
    const int b = m >> 12;
    const int nn = m & (SEQ - 1);
    float* dst = (which ? g_k : g_q)
               + (((size_t)b * NH + blockIdx.y) * SEQ + nn) * HD + half * 32;
    const float* bp = bias + e0 + half * 32;
#pragma unroll
    for (int j = 0; j < 32; j += 4)
        *(float4*)(dst + j) = make_float4(__uint_as_float(orr[j])     + bp[j],
                                          __uint_as_float(orr[j + 1]) + bp[j + 1],
                                          __uint_as_float(orr[j + 2]) + bp[j + 2],
                                          __uint_as_float(orr[j + 3]) + bp[j + 3]);

    fence_before();
    __syncthreads();
    if (tid == 0) { mbar_inval(sb + PJ_BAR(0)); mbar_inval(sb + PJ_BAR(1)); mbar_inval(sb + PJ_BAR(2)); }
    if (wid == 0) tc_dealloc(tmem, 64);

#else
    // -------- wmma fallback --------
    extern __shared__ float smf[];
    float* As = smf;
    float* Bs = smf + 128 * LDSB;

    const int tid  = threadIdx.x;
    const int warp = tid >> 5;
    const int m0   = blockIdx.x * 128;
    const int e0   = blockIdx.y * 64;

    FragC acc[4];
#pragma unroll
    for (int n = 0; n < 4; n++) wmma::fill_fragment(acc[n], 0.0f);

    float xr[16], wr[8];
#pragma unroll
    for (int i = 0; i < 16; i++) {
        int idx = tid + i * 256, r = idx >> 5, c = idx & 31;
        xr[i] = x[(size_t)(m0 + r) * DIM + c];
    }
#pragma unroll
    for (int i = 0; i < 8; i++) {
        int idx = tid + i * 256, r = idx >> 5, c = idx & 31;
        wr[i] = W[(size_t)(e0 + r) * DIM + c];
    }

    for (int kt = 0; kt < 16; kt++) {
#pragma unroll
        for (int i = 0; i < 16; i++) {
            int idx = tid + i * 256, r = idx >> 5, c = idx & 31;
            As[r * LDSB + c] = wmma::__float_to_tf32(xr[i]);
        }
#pragma unroll
        for (int i = 0; i < 8; i++) {
            int idx = tid + i * 256, r = idx >> 5, c = idx & 31;
            Bs[r * LDSB + c] = wmma::__float_to_tf32(wr[i]);
        }
        __syncthreads();

        if (kt < 15) {
            const int k0 = (kt + 1) * 32;
#pragma unroll
            for (int i = 0; i < 16; i++) {
                int idx = tid + i * 256, r = idx >> 5, c = idx & 31;
                xr[i] = x[(size_t)(m0 + r) * DIM + k0 + c];
            }
#pragma unroll
            for (int i = 0; i < 8; i++) {
                int idx = tid + i * 256, r = idx >> 5, c = idx & 31;
                wr[i] = W[(size_t)(e0 + r) * DIM + k0 + c];
            }
        }

#pragma unroll
        for (int kk = 0; kk < 4; kk++) {
            FragA a;
            wmma::load_matrix_sync(a, As + warp * 16 * LDSB + kk * 8, LDSB);
#pragma unroll
            for (int n = 0; n < 4; n++) {
                FragBc b;
                wmma::load_matrix_sync(b, Bs + n * 16 * LDSB + kk * 8, LDSB);
                wmma::mma_sync(acc[n], a, b, acc[n]);
            }
        }
        __syncthreads();
    }

#pragma unroll
    for (int n = 0; n < 4; n++)
        wmma::store_matrix_sync(smf + warp * 16 * LDS + n * 16, acc[n], LDS, wmma::mem_row_major);
    __syncthreads();

    float* dst = which ? g_k : g_q;
    const int h = blockIdx.y;
#pragma unroll
    for (int i = 0; i < 32; i++) {
        int idx = tid + i * 256;
        int r = idx >> 6, c = idx & 63;
        int m = m0 + r;
        int b = m >> 12;
        int nn = m & (SEQ - 1);
        dst[(((size_t)b * NH + h) * SEQ + nn) * HD + c] = smf[r * LDS + c] + bias[e0 + c];
    }
#endif
}

// ===========================================================================
// Attention. Grid (32, 8, 2), 256 threads. TC path: S double-buffered in
// TMEM, K triple-buffered, VT double-buffered (staged CONFLICT-FREE from the
// K smem tile: 4x LDS.32 -> 1x STS.128), P double-buffered.
// ===========================================================================
#define AT_TMEMP  0
#define AT_SBAR   8
#define AT_OBAR   16
#define AT_RSA    32
#define AT_RSB    544
#define AT_Q      1024
#define AT_K      33792                    /* 3 x 16384 */
#define AT_VT     82944                    /* 2 x 16384 */
#define AT_P      115712                   /* 2 x 32768 */
#define ATTN_TOTAL 181248

__global__ void __launch_bounds__(256, 1)
attn_kernel(float* __restrict__ out)
{
#if TC_OK
    extern __shared__ __align__(1024) char smem[];
    const uint32_t sb = smem_u32(smem);

    const int tid  = threadIdx.x;
    const int wid  = tid >> 5;
    const int lane = tid & 31;
    const int half = wid >> 2;
    const int row  = (wid & 3) * 32 + lane;

    const int bh = blockIdx.z * NH + blockIdx.y;
    const int q0 = blockIdx.x * 128;
    const float* qb = g_q + (size_t)bh * SEQ * HD + (size_t)q0 * HD;
    const float* kb = g_k + (size_t)bh * SEQ * HD;
    const float scale = 0.04419417382415922f;  // 512^-0.5

    if (wid == 0) tc_alloc(sb + AT_TMEMP, 256);

    // Stage Q (128x64, scale folded, tf32, blocked SW128; 16 atoms/col-block)
    {
        const float4* q4 = (const float4*)qb;
#pragma unroll
        for (int i = 0; i < 8; i++) {
            int idx4 = tid + i * 256;
            int eb = idx4 * 4;
            int r = eb >> 6, c = eb & 63;
            float4 v = q4[idx4];
            uint32_t atom = (uint32_t)((r >> 3) + ((c >> 5) << 4));
            uint32_t off = (atom * 1024 + (r & 7) * 128 + (c & 31) * 4)
                           ^ ((uint32_t)(r & 7) << 4);
            *(float4*)(smem + AT_Q + off) = make_float4(
                cvt_tf32(v.x * scale), cvt_tf32(v.y * scale),
                cvt_tf32(v.z * scale), cvt_tf32(v.w * scale));
        }
    }

    // stage K tile into buffer b (values pre-loaded in kr)
    auto stageK = [&](const float4* kr, int b) {
        char* Kb = smem + AT_K + b * 16384;
#pragma unroll
        for (int i = 0; i < 4; i++) {
            int idx4 = tid + i * 256;
            int eb = idx4 * 4;
            int key = eb >> 6, h0 = eb & 63;
            float4 v = kr[i];
            uint32_t offk = ((uint32_t)((key >> 3) + ((h0 >> 5) << 3)) * 1024
                             + (key & 7) * 128 + (h0 & 31) * 4) ^ ((uint32_t)(key & 7) << 4);
            *(float4*)(Kb + offk) = make_float4(
                cvt_tf32(v.x), cvt_tf32(v.y), cvt_tf32(v.z), cvt_tf32(v.w));
        }
    };

    // Stage VT buffer vbuf from K buffer kbuf (smem transpose, conflict-free):
    // per thread: 4x (4 LDS.32 [distinct banks] + 1 STS.128 [4-phase floor]).
    auto stageVT = [&](int kbuf, int vbuf) {
        char* Kb = smem + AT_K  + kbuf * 16384;
        char* Vb = smem + AT_VT + vbuf * 16384;
#pragma unroll
        for (int j = 0; j < 4; j++) {
            int idx = tid + j * 256;             // 0..1023 float4s of VT
            int hd = idx & 63, kq = idx >> 6;    // keys 4kq..4kq+3
            float v[4];
#pragma unroll
            for (int r = 0; r < 4; r++) {
                int key = kq * 4 + r;
                uint32_t offr = ((uint32_t)((key >> 3) + ((hd >> 5) << 3)) * 1024
                                 + (key & 7) * 128 + (hd & 31) * 4)
                                ^ ((uint32_t)(key & 7) << 4);
                v[r] = *(const float*)(Kb + offr);
            }
            uint32_t offw = ((uint32_t)((hd >> 3) + ((kq >> 3) << 3)) * 1024
                             + (hd & 7) * 128 + ((kq * 4) & 31) * 4)
                            ^ ((uint32_t)(hd & 7) << 4);
            *(float4*)(Vb + offw) = make_float4(v[0], v[1], v[2], v[3]);
        }
    };

    // Prologue: stage K tiles 0 and 1
    {
        float4 kr[4];
#pragma unroll
        for (int i = 0; i < 4; i++) kr[i] = ((const float4*)kb)[tid + i * 256];
        stageK(kr, 0);
#pragma unroll
        for (int i = 0; i < 4; i++) kr[i] = ((const float4*)(kb + (size_t)64 * HD))[tid + i * 256];
        stageK(kr, 1);
    }

    if (tid == 0) { mbar_init(sb + AT_SBAR, 1); mbar_init(sb + AT_OBAR, 1); }
    fence_async();
    fence_before();
    __syncthreads();

    uint32_t tmem;
    asm volatile("ld.shared.b32 %0, [%1];" : "=r"(tmem) : "r"(sb + AT_TMEMP));
    const uint32_t O_T  = tmem + 128;
    const uint32_t sbar = sb + AT_SBAR;
    const uint32_t obar = sb + AT_OBAR;
    const uint64_t qd   = make_desc(sb + AT_Q);

    // issue S(0) -> S-buf 0 (K0 fenced by the sync above)
    if (wid == 0) {
        fence_after();
        if (elect_one()) {
            uint64_t kd = make_desc(sb + AT_K);
#pragma unroll
            for (int s = 0; s < 8; s++)
                mma_tf32_ss(tmem, qd + AOFF(s), kd + BOFF(s), IDESC_TF32, s > 0);
            tc_commit(sbar);
        }
    }

    // VT(0) from K0 (reads K0 after the sync; O(0) is issued only after the
    // iter-0 fence/sync, which covers these generic-proxy writes)
    stageVT(0, 0);

    float rsum = 0.0f;

    for (int kt = 0; kt < SEQ / 64; kt++) {
        // 0. early LDG of K(kt+2)
        float4 kr[4];
        const bool do_stage = (kt + 2 < SEQ / 64);
        if (do_stage) {
            const float4* k4 = (const float4*)(kb + (size_t)(kt + 2) * 64 * HD);
#pragma unroll
            for (int i = 0; i < 4; i++) kr[i] = k4[tid + i * 256];
        }

        // 1. wait S(kt)   (flip kt+1, parity kt&1)
        mbar_wait(sbar, (uint32_t)(kt & 1));
        fence_after();

        // 2. issue S(kt+1) on the other S buffer immediately
        if (kt < SEQ / 64 - 1 && wid == 0) {
            if (elect_one()) {
                uint64_t kd = make_desc(sb + AT_K + ((kt + 1) % 3) * 16384);
                uint32_t dstS = tmem + (uint32_t)(((kt + 1) & 1) * 64);
#pragma unroll
                for (int s = 0; s < 8; s++)
                    mma_tf32_ss(dstS, qd + AOFF(s), kd + BOFF(s), IDESC_TF32, s > 0);
                tc_commit(sbar);
            }
        }

        // 3. LDTM S(kt) -> exp -> STS P(kt&1)
        uint32_t sr[32];
        ld32(sr, tmem + (uint32_t)((kt & 1) * 64 + half * 32));
        tc_wait_ld();

        float e[32];
#pragma unroll
        for (int c = 0; c < 32; c++) {
            e[c] = __expf(__uint_as_float(sr[c]));
            rsum += e[c];
        }
        {
            char* Pb = smem + AT_P + (kt & 1) * 32768;
            uint32_t basep = ((uint32_t)((row >> 3) + (half << 4))) * 1024 + (row & 7) * 128;
            uint32_t swx = (uint32_t)(row & 7) << 4;
#pragma unroll
            for (int j = 0; j < 32; j += 4) {
                uint32_t off = (basep + j * 4) ^ swx;
                *(float4*)(Pb + off) = make_float4(
                    cvt_tf32(e[j]), cvt_tf32(e[j + 1]), cvt_tf32(e[j + 2]), cvt_tf32(e[j + 3]));
            }
        }

        // 4. wait O(kt-1)  (flip kt, parity (kt+1)&1) — frees K buf (kt-1)%3
        //    and VT buf (kt-1)&1
        if (kt >= 1) mbar_wait(obar, (uint32_t)((kt + 1) & 1));

        // 5a. stage K(kt+2) into buf (kt+2)%3 (S(kt-1)/VT-read(kt-1) done)
        if (do_stage) stageK(kr, (kt + 2) % 3);
        // 5b. stage VT(kt+1) from K buf (kt+1)%3 into VT buf (kt+1)&1
        //     (K(kt+1) synced at iter kt-1; VT buf freed by step 4)
        if (kt + 1 < SEQ / 64) stageVT((kt + 1) % 3, (kt + 1) & 1);

        fence_async();
        fence_before();
        __syncthreads();

        // 6. issue O(kt): A = P(kt&1), B = VT buf (kt&1) [staged last iter]
        if (wid == 0) {
            fence_after();
            if (elect_one()) {
                uint64_t pdk = make_desc(sb + AT_P + (kt & 1) * 32768);
                uint64_t vd  = make_desc(sb + AT_VT + (kt & 1) * 16384);
#pragma unroll
                for (int s = 0; s < 8; s++)
                    mma_tf32_ss(O_T, pdk + AOFF(s), vd + BOFF(s), IDESC_TF32, (kt > 0) || (s > 0));
                tc_commit(obar);
            }
        }
    }

    // final: O(63) = flip 64, parity 1
    mbar_wait(obar, 1u);
    fence_after();

    *(float*)(smem + (half ? AT_RSB : AT_RSA) + row * 4) = rsum;

    uint32_t orr[32];
    ld32(orr, O_T + (uint32_t)(half * 32));
    tc_wait_ld();
    __syncthreads();

    float inv = 1.0f / (*(float*)(smem + AT_RSA + row * 4) +
                        *(float*)(smem + AT_RSB + row * 4));

    float* ob = out + ((size_t)blockIdx.z * SEQ + q0 + row) * DIM
                    + blockIdx.y * HD + half * 32;
#pragma unroll
    for (int j = 0; j < 32; j += 4)
        *(float4*)(ob + j) = make_float4(__uint_as_float(orr[j]) * inv,
                                         __uint_as_float(orr[j + 1]) * inv,
                                         __uint_as_float(orr[j + 2]) * inv,
                                         __uint_as_float(orr[j + 3]) * inv);

    fence_before();
    __syncthreads();
    if (tid == 0) { mbar_inval(sbar); mbar_inval(obar); }
    if (wid == 0) tc_dealloc(tmem, 256);

#else
    // -------- wmma fallback (R3 body) --------
    extern __shared__ float smf[];
    float* Ks0    = smf;
    float* Ks1    = smf + 64 * LDS;
    float* Ps     = smf + 128 * LDS;
    float* rowinv = smf + 256 * LDS;

    const int tid  = threadIdx.x;
    const int warp = tid >> 5;
    const int lane = tid & 31;
    const int bh   = blockIdx.z * NH + blockIdx.y;
    const int q0   = blockIdx.x * 128;

    const float* qb = g_q + (size_t)bh * SEQ * HD + (size_t)q0 * HD;
    const float* kb = g_k + (size_t)bh * SEQ * HD;
    const float scale = 0.04419417382415922f;

#pragma unroll
    for (int i = 0; i < 32; i++) {
        int idx = tid + i * 256;
        int r = idx >> 6, c = idx & 63;
        Ps[r * LDS + c] = wmma::__float_to_tf32(qb[idx] * scale);
    }
    __syncthreads();

    FragA qa[8];
#pragma unroll
    for (int kk = 0; kk < 8; kk++)
        wmma::load_matrix_sync(qa[kk], Ps + warp * 16 * LDS + kk * 8, LDS);

#pragma unroll
    for (int i = 0; i < 16; i++) {
        int idx = tid + i * 256;
        int r = idx >> 6, c = idx & 63;
        Ks0[r * LDS + c] = wmma::__float_to_tf32(kb[idx]);
    }
    __syncthreads();

    FragC oacc[4];
#pragma unroll
    for (int n = 0; n < 4; n++) wmma::fill_fragment(oacc[n], 0.0f);

    float rsum = 0.0f;
    float* Pw = Ps + warp * 16 * LDS;

    for (int kt = 0; kt < SEQ / 64; kt++) {
        float* cur = (kt & 1) ? Ks1 : Ks0;
        float* nxt = (kt & 1) ? Ks0 : Ks1;

        if (kt < SEQ / 64 - 1) {
            const float* kp = kb + (size_t)(kt + 1) * 64 * HD;
#pragma unroll
            for (int i = 0; i < 16; i++) {
                int idx = tid + i * 256;
                int r = idx >> 6, c = idx & 63;
                nxt[r * LDS + c] = wmma::__float_to_tf32(kp[idx]);
            }
        }

        FragC sacc[4];
#pragma unroll
        for (int n = 0; n < 4; n++) wmma::fill_fragment(sacc[n], 0.0f);
#pragma unroll
        for (int kk = 0; kk < 8; kk++) {
#pragma unroll
            for (int n = 0; n < 4; n++) {
                FragBc b;
                wmma::load_matrix_sync(b, cur + n * 16 * LDS + kk * 8, LDS);
                wmma::mma_sync(sacc[n], qa[kk], b, sacc[n]);
            }
        }

#pragma unroll
        for (int n = 0; n < 4; n++) {
#pragma unroll
            for (int e = 0; e < sacc[n].num_elements; e++)
                sacc[n].x[e] = wmma::__float_to_tf32(__expf(sacc[n].x[e]));
            wmma::store_matrix_sync(Pw + n * 16, sacc[n], LDS, wmma::mem_row_major);
        }
        __syncwarp();

        {
            const float* pp = Pw + (lane >> 1) * LDS + (lane & 1) * 32;
            float part = 0.0f;
#pragma unroll
            for (int c = 0; c < 32; c++) part += pp[c];
            rsum += part;
        }

#pragma unroll
        for (int kk = 0; kk < 8; kk++) {
            FragA a;
            wmma::load_matrix_sync(a, Pw + kk * 8, LDS);
#pragma unroll
            for (int n = 0; n < 4; n++) {
                FragBr b;
                wmma::load_matrix_sync(b, cur + kk * 8 * LDS + n * 16, LDS);
                wmma::mma_sync(oacc[n], a, b, oacc[n]);
            }
        }

        __syncthreads();
    }

    rsum += __shfl_xor_sync(0xffffffffu, rsum, 1);
    if ((lane & 1) == 0) rowinv[warp * 16 + (lane >> 1)] = 1.0f / rsum;

#pragma unroll
    for (int n = 0; n < 4; n++)
        wmma::store_matrix_sync(Pw + n * 16, oacc[n], LDS, wmma::mem_row_major);
    __syncthreads();

    float* ob = out + ((size_t)blockIdx.z * SEQ + q0) * DIM + blockIdx.y * HD;
#pragma unroll
    for (int i = 0; i < 32; i++) {
        int idx = tid + i * 256;
        int r = idx >> 6, c = idx & 63;
        ob[(size_t)r * DIM + c] = Ps[r * LDS + c] * rowinv[r];
    }
#endif
}

// ---------------------------------------------------------------------------
extern "C" void kernel_launch(void* const* d_in, const int* in_sizes, int n_in,
                              void* d_out, int out_size)
{
    const float* x  = (const float*)d_in[0];
    const float* Wq = (const float*)d_in[1];
    const float* bq = (const float*)d_in[2];
    const float* Wk = (const float*)d_in[3];
    const float* bk = (const float*)d_in[4];
    float* out = (float*)d_out;

    cudaFuncSetAttribute(proj_kernel, cudaFuncAttributeMaxDynamicSharedMemorySize, PJ_TOTAL);
    dim3 pg((BATCH * SEQ) / 128, DIM / 64, 2);
    proj_kernel<<<pg, 256, PJ_TOTAL>>>(x, Wq, bq, Wk, bk);

    cudaFuncSetAttribute(attn_kernel, cudaFuncAttributeMaxDynamicSharedMemorySize, ATTN_TOTAL);
    dim3 ag(SEQ / 128, NH, BATCH);
    attn_kernel<<<ag, 256, ATTN_TOTAL>>>(out);
}

// round 9
// speedup vs baseline: 4.7115x; 1.0993x over previous
#include <cuda_runtime.h>
#include <cuda_bf16.h>
#include <mma.h>
#include <cstdint>

using namespace nvcuda;

#define BATCH 2
#define SEQ   4096
#define DIM   512
#define NH    8
#define HD    64
#define LDS   68
#define LDSB  36

#if defined(__CUDA_ARCH__) && defined(__CUDA_ARCH_HAS_FEATURE__)
#if __CUDA_ARCH_HAS_FEATURE__(SM103_ALL)
#define TC_OK 1
#endif
#endif
#ifndef TC_OK
#define TC_OK 0
#endif

__device__ float g_q[(size_t)BATCH * NH * SEQ * HD];
__device__ float g_k[(size_t)BATCH * NH * SEQ * HD];

using FragA  = wmma::fragment<wmma::matrix_a, 16, 16, 8, wmma::precision::tf32, wmma::row_major>;
using FragBc = wmma::fragment<wmma::matrix_b, 16, 16, 8, wmma::precision::tf32, wmma::col_major>;
using FragBr = wmma::fragment<wmma::matrix_b, 16, 16, 8, wmma::precision::tf32, wmma::row_major>;
using FragC  = wmma::fragment<wmma::accumulator, 16, 16, 8, float>;

// ===========================================================================
// helpers
// ===========================================================================
__device__ __forceinline__ uint32_t smem_u32(const void* p) {
    uint32_t a;
    asm("{ .reg .u64 t; cvta.to.shared.u64 t, %1; cvt.u32.u64 %0, t; }" : "=r"(a) : "l"(p));
    return a;
}
__device__ __forceinline__ float cvt_tf32(float x) {
    float r; asm("cvt.rna.tf32.f32 %0, %1;" : "=f"(r) : "f"(x)); return r;
}
__device__ __forceinline__ float ex2f(float x) {
    float r; asm("ex2.approx.f32 %0, %1;" : "=f"(r) : "f"(x)); return r;
}

#if TC_OK
__device__ __forceinline__ uint32_t elect_one() {
    uint32_t p;
    asm volatile("{\n .reg .pred p;\n elect.sync _|p, 0xFFFFFFFF;\n selp.b32 %0, 1, 0, p;\n}" : "=r"(p));
    return p;
}
__device__ __forceinline__ void mbar_init(uint32_t mbar, uint32_t cnt) {
    asm volatile("mbarrier.init.shared.b64 [%0], %1;" :: "r"(mbar), "r"(cnt) : "memory");
}
__device__ __forceinline__ void mbar_inval(uint32_t mbar) {
    asm volatile("mbarrier.inval.shared.b64 [%0];" :: "r"(mbar) : "memory");
}
__device__ __forceinline__ void mbar_wait(uint32_t mbar, uint32_t parity) {
    asm volatile(
        "{\n .reg .pred P;\n"
        "W%=: mbarrier.try_wait.parity.acquire.cta.shared::cta.b64 P, [%0], %1, 0x989680;\n"
        " @P bra D%=;\n bra W%=;\n D%=:\n}"
        :: "r"(mbar), "r"(parity) : "memory");
}
__device__ __forceinline__ void tc_alloc(uint32_t smem_dst, uint32_t ncols) {
    asm volatile("tcgen05.alloc.cta_group::1.sync.aligned.shared::cta.b32 [%0], %1;"
                 :: "r"(smem_dst), "r"(ncols) : "memory");
}
__device__ __forceinline__ void tc_dealloc(uint32_t tmem, uint32_t ncols) {
    asm volatile("tcgen05.dealloc.cta_group::1.sync.aligned.b32 %0, %1;" :: "r"(tmem), "r"(ncols));
}
__device__ __forceinline__ void tc_commit(uint32_t mbar) {
    asm volatile("tcgen05.commit.cta_group::1.mbarrier::arrive::one.shared::cluster.b64 [%0];"
                 :: "r"(mbar) : "memory");
}
__device__ __forceinline__ void fence_before() { asm volatile("tcgen05.fence::before_thread_sync;" ::: "memory"); }
__device__ __forceinline__ void fence_after()  { asm volatile("tcgen05.fence::after_thread_sync;" ::: "memory"); }
__device__ __forceinline__ void fence_async()  { asm volatile("fence.proxy.async.shared::cta;" ::: "memory"); }
__device__ __forceinline__ void tc_wait_ld()   { asm volatile("tcgen05.wait::ld.sync.aligned;" ::: "memory"); }
__device__ __forceinline__ void tc_wait_st()   { asm volatile("tcgen05.wait::st.sync.aligned;" ::: "memory"); }

__device__ __forceinline__ void mma_tf32_ss(uint32_t d, uint64_t a, uint64_t b,
                                            uint32_t idesc, uint32_t en) {
    asm volatile(
        "{\n .reg .pred p;\n setp.ne.u32 p, %5, 0;\n"
        " tcgen05.mma.cta_group::1.kind::tf32 [%0], %1, %2, %3, {%4, %4, %4, %4}, p;\n}"
        :: "r"(d), "l"(a), "l"(b), "r"(idesc), "r"(0u), "r"(en) : "memory");
}
// TS form: A in TMEM
__device__ __forceinline__ void mma_tf32_ts(uint32_t d, uint32_t a, uint64_t b,
                                            uint32_t idesc, uint32_t en) {
    asm volatile(
        "{\n .reg .pred p;\n setp.ne.u32 p, %5, 0;\n"
        " tcgen05.mma.cta_group::1.kind::tf32 [%0], [%1], %2, %3, {%4, %4, %4, %4}, p;\n}"
        :: "r"(d), "r"(a), "l"(b), "r"(idesc), "r"(0u), "r"(en) : "memory");
}

__device__ __forceinline__ void ld32(uint32_t* r, uint32_t addr) {
    asm volatile(
        "tcgen05.ld.sync.aligned.32x32b.x32.b32 "
        "{%0,%1,%2,%3,%4,%5,%6,%7,%8,%9,%10,%11,%12,%13,%14,%15,"
        "%16,%17,%18,%19,%20,%21,%22,%23,%24,%25,%26,%27,%28,%29,%30,%31}, [%32];"
        : "=r"(r[0]),"=r"(r[1]),"=r"(r[2]),"=r"(r[3]),"=r"(r[4]),"=r"(r[5]),"=r"(r[6]),"=r"(r[7]),
          "=r"(r[8]),"=r"(r[9]),"=r"(r[10]),"=r"(r[11]),"=r"(r[12]),"=r"(r[13]),"=r"(r[14]),"=r"(r[15]),
          "=r"(r[16]),"=r"(r[17]),"=r"(r[18]),"=r"(r[19]),"=r"(r[20]),"=r"(r[21]),"=r"(r[22]),"=r"(r[23]),
          "=r"(r[24]),"=r"(r[25]),"=r"(r[26]),"=r"(r[27]),"=r"(r[28]),"=r"(r[29]),"=r"(r[30]),"=r"(r[31])
        : "r"(addr));
}
__device__ __forceinline__ void st32(uint32_t addr, const uint32_t* r) {
    asm volatile(
        "tcgen05.st.sync.aligned.32x32b.x32.b32 [%0], "
        "{%1,%2,%3,%4,%5,%6,%7,%8,%9,%10,%11,%12,%13,%14,%15,%16,"
        "%17,%18,%19,%20,%21,%22,%23,%24,%25,%26,%27,%28,%29,%30,%31,%32};"
        :: "r"(addr),
           "r"(r[0]),"r"(r[1]),"r"(r[2]),"r"(r[3]),"r"(r[4]),"r"(r[5]),"r"(r[6]),"r"(r[7]),
           "r"(r[8]),"r"(r[9]),"r"(r[10]),"r"(r[11]),"r"(r[12]),"r"(r[13]),"r"(r[14]),"r"(r[15]),
           "r"(r[16]),"r"(r[17]),"r"(r[18]),"r"(r[19]),"r"(r[20]),"r"(r[21]),"r"(r[22]),"r"(r[23]),
           "r"(r[24]),"r"(r[25]),"r"(r[26]),"r"(r[27]),"r"(r[28]),"r"(r[29]),"r"(r[30]),"r"(r[31])
        : "memory");
}

// K-major SW128 descriptor: SBO=64, LBO=1, version=1
__device__ __forceinline__ uint64_t make_desc(uint32_t addr) {
    const uint64_t base = (uint64_t(2) << 61) | (uint64_t(1) << 46) |
                          (uint64_t(64) << 32) | (uint64_t(1) << 16);
    return base | ((uint64_t)(addr >> 4) & 0x3FFF);
}
#endif  // TC_OK

#define IDESC_TF32 ((1u<<4) | (2u<<7) | (2u<<10) | (8u<<17) | (8u<<24))  // F32 acc, tf32 a/b, N=64, M=128

#define AOFF(s) ((s) < 4 ? (uint64_t)((s) * 2) : (uint64_t)(1024 + ((s) - 4) * 2))
#define BOFF(s) ((s) < 4 ? (uint64_t)((s) * 2) : (uint64_t)(512  + ((s) - 4) * 2))

// ===========================================================================
// Projection (unchanged from R6, ~48us total): grid (64, 8, 2), 256 thr.
// ===========================================================================
#define PJ_TMEMP   0
#define PJ_BAR(i)  (8 + (i) * 8)
#define PJ_X       1024
#define PJ_XSTR    16384
#define PJ_W       (1024 + 3 * 16384)
#define PJ_WSTR    8192
#define PJ_TOTAL   74880

__global__ void __launch_bounds__(256, 2)
proj_kernel(const float* __restrict__ x,
            const float* __restrict__ Wq, const float* __restrict__ bq,
            const float* __restrict__ Wk, const float* __restrict__ bk)
{
    const int which = blockIdx.z;
    const float* W    = which ? Wk : Wq;
    const float* bias = which ? bk : bq;

#if TC_OK
    extern __shared__ __align__(1024) char smem[];
    const uint32_t sb = smem_u32(smem);

    const int tid  = threadIdx.x;
    const int wid  = tid >> 5;
    const int lane = tid & 31;
    const int half = wid >> 2;
    const int row  = (wid & 3) * 32 + lane;
    const int m0   = blockIdx.x * 128;
    const int e0   = blockIdx.y * 64;

    if (wid == 0) tc_alloc(sb + PJ_TMEMP, 64);
    if (tid == 0) {
        mbar_init(sb + PJ_BAR(0), 1);
        mbar_init(sb + PJ_BAR(1), 1);
        mbar_init(sb + PJ_BAR(2), 1);
    }

    auto stageX = [&](int k0, int b) {
#pragma unroll
        for (int i = 0; i < 4; i++) {
            int idx4 = tid + i * 256;
            int r = idx4 >> 3, c4 = (idx4 & 7) * 4;
            float4 v = *(const float4*)(x + (size_t)(m0 + r) * DIM + k0 + c4);
            uint32_t off = ((uint32_t)(r >> 3) * 1024 + (r & 7) * 128 + c4 * 4)
                           ^ ((uint32_t)(r & 7) << 4);
            *(float4*)(smem + PJ_X + b * PJ_XSTR + off) = make_float4(
                cvt_tf32(v.x), cvt_tf32(v.y), cvt_tf32(v.z), cvt_tf32(v.w));
        }
    };
    auto stageW = [&](int k0, int b) {
#pragma unroll
        for (int i = 0; i < 2; i++) {
            int idx4 = tid + i * 256;
            int r = idx4 >> 3, c4 = (idx4 & 7) * 4;
            float4 v = *(const float4*)(W + (size_t)(e0 + r) * DIM + k0 + c4);
            uint32_t off = ((uint32_t)(r >> 3) * 1024 + (r & 7) * 128 + c4 * 4)
                           ^ ((uint32_t)(r & 7) << 4);
            *(float4*)(smem + PJ_W + b * PJ_WSTR + off) = make_float4(
                cvt_tf32(v.x), cvt_tf32(v.y), cvt_tf32(v.z), cvt_tf32(v.w));
        }
    };

    stageX(0, 0);  stageW(0, 0);
    stageX(32, 1); stageW(32, 1);
    fence_async();
    fence_before();
    __syncthreads();

    uint32_t tmem;
    asm volatile("ld.shared.b32 %0, [%1];" : "=r"(tmem) : "r"(sb + PJ_TMEMP));

    int ph0 = 0, ph1 = 0, ph2 = 0;
#pragma unroll
    for (int c = 0; c < 16; c++) {
        if (wid == 0) {
            fence_after();
            if (elect_one()) {
                uint64_t ad = make_desc(sb + PJ_X + (c % 3) * PJ_XSTR);
                uint64_t bd = make_desc(sb + PJ_W + (c % 3) * PJ_WSTR);
#pragma unroll
                for (int s = 0; s < 4; s++)
                    mma_tf32_ss(tmem, ad + s * 2, bd + s * 2, IDESC_TF32, (c > 0) || (s > 0));
                tc_commit(sb + PJ_BAR(c % 3));
            }
        }
        if (c + 2 < 16) {
            const int b2 = (c + 2) % 3;
            if (c + 2 >= 3) {
                if (b2 == 0)      { mbar_wait(sb + PJ_BAR(0), (uint32_t)ph0); ph0 ^= 1; }
                else if (b2 == 1) { mbar_wait(sb + PJ_BAR(1), (uint32_t)ph1); ph1 ^= 1; }
                else              { mbar_wait(sb + PJ_BAR(2), (uint32_t)ph2); ph2 ^= 1; }
            }
            stageX((c + 2) * 32, b2);
            stageW((c + 2) * 32, b2);
            fence_async();
            fence_before();
            __syncthreads();
        }
    }

    mbar_wait(sb + PJ_BAR(0), (uint32_t)ph0);
    fence_after();

    uint32_t orr[32];
    ld32(orr, tmem + (uint32_t)(half * 32));
    tc_wait_ld();

    const int m = m0 + row;
    const int b = m >> 12;
    const int nn = m & (SEQ - 1);
    float* dst = (which ? g_k : g_q)
               + (((size_t)b * NH + blockIdx.y) * SEQ + nn) * HD + half * 32;
    const float* bp = bias + e0 + half * 32;
#pragma unroll
    for (int j = 0; j < 32; j += 4)
        *(float4*)(dst + j) = make_float4(__uint_as_float(orr[j])     + bp[j],
                                          __uint_as_float(orr[j + 1]) + bp[j + 1],
                                          __uint_as_float(orr[j + 2]) + bp[j + 2],
                                          __uint_as_float(orr[j + 3]) + bp[j + 3]);

    fence_before();
    __syncthreads();
    if (tid == 0) { mbar_inval(sb + PJ_BAR(0)); mbar_inval(sb + PJ_BAR(1)); mbar_inval(sb + PJ_BAR(2)); }
    if (wid == 0) tc_dealloc(tmem, 64);

#else
    // -------- wmma fallback --------
    extern __shared__ float smf[];
    float* As = smf;
    float* Bs = smf + 128 * LDSB;

    const int tid  = threadIdx.x;
    const int warp = tid >> 5;
    const int m0   = blockIdx.x * 128;
    const int e0   = blockIdx.y * 64;

    FragC acc[4];
#pragma unroll
    for (int n = 0; n < 4; n++) wmma::fill_fragment(acc[n], 0.0f);

    float xr[16], wr[8];
#pragma unroll
    for (int i = 0; i < 16; i++) {
        int idx = tid + i * 256, r = idx >> 5, c = idx & 31;
        xr[i] = x[(size_t)(m0 + r) * DIM + c];
    }
#pragma unroll
    for (int i = 0; i < 8; i++) {
        int idx = tid + i * 256, r = idx >> 5, c = idx & 31;
        wr[i] = W[(size_t)(e0 + r) * DIM + c];
    }

    for (int kt = 0; kt < 16; kt++) {
#pragma unroll
        for (int i = 0; i < 16; i++) {
            int idx = tid + i * 256, r = idx >> 5, c = idx & 31;
            As[r * LDSB + c] = wmma::__float_to_tf32(xr[i]);
        }
#pragma unroll
        for (int i = 0; i < 8; i++) {
            int idx = tid + i * 256, r = idx >> 5, c = idx & 31;
            Bs[r * LDSB + c] = wmma::__float_to_tf32(wr[i]);
        }
        __syncthreads();

        if (kt < 15) {
            const int k0 = (kt + 1) * 32;
#pragma unroll
            for (int i = 0; i < 16; i++) {
                int idx = tid + i * 256, r = idx >> 5, c = idx & 31;
                xr[i] = x[(size_t)(m0 + r) * DIM + k0 + c];
            }
#pragma unroll
            for (int i = 0; i < 8; i++) {
                int idx = tid + i * 256, r = idx >> 5, c = idx & 31;
                wr[i] = W[(size_t)(e0 + r) * DIM + k0 + c];
            }
        }

#pragma unroll
        for (int kk = 0; kk < 4; kk++) {
            FragA a;
            wmma::load_matrix_sync(a, As + warp * 16 * LDSB + kk * 8, LDSB);
#pragma unroll
            for (int n = 0; n < 4; n++) {
                FragBc b;
                wmma::load_matrix_sync(b, Bs + n * 16 * LDSB + kk * 8, LDSB);
                wmma::mma_sync(acc[n], a, b, acc[n]);
            }
        }
        __syncthreads();
    }

#pragma unroll
    for (int n = 0; n < 4; n++)
        wmma::store_matrix_sync(smf + warp * 16 * LDS + n * 16, acc[n], LDS, wmma::mem_row_major);
    __syncthreads();

    float* dst = which ? g_k : g_q;
    const int h = blockIdx.y;
#pragma unroll
    for (int i = 0; i < 32; i++) {
        int idx = tid + i * 256;
        int r = idx >> 6, c = idx & 63;
        int m = m0 + r;
        int b = m >> 12;
        int nn = m & (SEQ - 1);
        dst[(((size_t)b * NH + h) * SEQ + nn) * HD + c] = smf[r * LDS + c] + bias[e0 + c];
    }
#endif
}

// ===========================================================================
// Attention. Grid (32, 8, 2), 256 threads, 2 CTAs/SM. TC path:
//   TMEM (256 cols): S0 @0, S1 @64, O @128, P @192 (single-buffered).
//   SMEM: Q 32KB, K 2x16KB (ring of 2), VT 2x16KB. ~97KB -> occ 25%.
//   P stored to TMEM via tcgen05.st; O-mma is TS-form (A in TMEM).
//   exp via raw ex2 (log2e folded into Q scale).
// ===========================================================================
#define AT_TMEMP  0
#define AT_SBAR   8
#define AT_OBAR   16
#define AT_RSA    32
#define AT_RSB    544
#define AT_Q      1024
#define AT_K      33792                    /* 2 x 16384 */
#define AT_VT     66560                    /* 2 x 16384 */
#define ATTN_TOTAL 99328

__global__ void __launch_bounds__(256, 2)
attn_kernel(float* __restrict__ out)
{
#if TC_OK
    extern __shared__ __align__(1024) char smem[];
    const uint32_t sb = smem_u32(smem);

    const int tid  = threadIdx.x;
    const int wid  = tid >> 5;
    const int lane = tid & 31;
    const int half = wid >> 2;
    const int row  = (wid & 3) * 32 + lane;

    const int bh = blockIdx.z * NH + blockIdx.y;
    const int q0 = blockIdx.x * 128;
    const float* qb = g_q + (size_t)bh * SEQ * HD + (size_t)q0 * HD;
    const float* kb = g_k + (size_t)bh * SEQ * HD;
    // 512^-0.5 * log2(e): exp(s) == ex2(s * log2e); fold into Q scale.
    const float scale = 0.063758746f;

    if (wid == 0) tc_alloc(sb + AT_TMEMP, 256);

    // Stage Q (128x64, scale folded, tf32, blocked SW128; 16 atoms/col-block)
    {
        const float4* q4 = (const float4*)qb;
#pragma unroll
        for (int i = 0; i < 8; i++) {
            int idx4 = tid + i * 256;
            int eb = idx4 * 4;
            int r = eb >> 6, c = eb & 63;
            float4 v = q4[idx4];
            uint32_t atom = (uint32_t)((r >> 3) + ((c >> 5) << 4));
            uint32_t off = (atom * 1024 + (r & 7) * 128 + (c & 31) * 4)
                           ^ ((uint32_t)(r & 7) << 4);
            *(float4*)(smem + AT_Q + off) = make_float4(
                cvt_tf32(v.x * scale), cvt_tf32(v.y * scale),
                cvt_tf32(v.z * scale), cvt_tf32(v.w * scale));
        }
    }

    auto stageK = [&](const float4* kr, int b) {
        char* Kb = smem + AT_K + b * 16384;
#pragma unroll
        for (int i = 0; i < 4; i++) {
            int idx4 = tid + i * 256;
            int eb = idx4 * 4;
            int key = eb >> 6, h0 = eb & 63;
            float4 v = kr[i];
            uint32_t offk = ((uint32_t)((key >> 3) + ((h0 >> 5) << 3)) * 1024
                             + (key & 7) * 128 + (h0 & 31) * 4) ^ ((uint32_t)(key & 7) << 4);
            *(float4*)(Kb + offk) = make_float4(
                cvt_tf32(v.x), cvt_tf32(v.y), cvt_tf32(v.z), cvt_tf32(v.w));
        }
    };

    // conflict-free smem transpose K -> VT
    auto stageVT = [&](int kbuf, int vbuf) {
        char* Kb = smem + AT_K  + kbuf * 16384;
        char* Vb = smem + AT_VT + vbuf * 16384;
#pragma unroll
        for (int j = 0; j < 4; j++) {
            int idx = tid + j * 256;
            int hd = idx & 63, kq = idx >> 6;
            float v[4];
#pragma unroll
            for (int r = 0; r < 4; r++) {
                int key = kq * 4 + r;
                uint32_t offr = ((uint32_t)((key >> 3) + ((hd >> 5) << 3)) * 1024
                                 + (key & 7) * 128 + (hd & 31) * 4)
                                ^ ((uint32_t)(key & 7) << 4);
                v[r] = *(const float*)(Kb + offr);
            }
            uint32_t offw = ((uint32_t)((hd >> 3) + ((kq >> 3) << 3)) * 1024
                             + (hd & 7) * 128 + ((kq * 4) & 31) * 4)
                            ^ ((uint32_t)(hd & 7) << 4);
            *(float4*)(Vb + offw) = make_float4(v[0], v[1], v[2], v[3]);
        }
    };

    // Prologue: stage K tiles 0 and 1 (ring of 2)
    {
        float4 kr[4];
#pragma unroll
        for (int i = 0; i < 4; i++) kr[i] = ((const float4*)kb)[tid + i * 256];
        stageK(kr, 0);
#pragma unroll
        for (int i = 0; i < 4; i++) kr[i] = ((const float4*)(kb + (size_t)64 * HD))[tid + i * 256];
        stageK(kr, 1);
    }

    if (tid == 0) { mbar_init(sb + AT_SBAR, 1); mbar_init(sb + AT_OBAR, 1); }
    fence_async();
    fence_before();
    __syncthreads();

    uint32_t tmem;
    asm volatile("ld.shared.b32 %0, [%1];" : "=r"(tmem) : "r"(sb + AT_TMEMP));
    const uint32_t O_T  = tmem + 128;
    const uint32_t P_T  = tmem + 192;
    const uint32_t sbar = sb + AT_SBAR;
    const uint32_t obar = sb + AT_OBAR;
    const uint64_t qd   = make_desc(sb + AT_Q);
    const uint32_t wsub = (uint32_t)(wid & 3) << 21;   // TMEM subpartition field

    // issue S(0) -> S-buf 0
    if (wid == 0) {
        fence_after();
        if (elect_one()) {
            uint64_t kd = make_desc(sb + AT_K);
#pragma unroll
            for (int s = 0; s < 8; s++)
                mma_tf32_ss(tmem, qd + AOFF(s), kd + BOFF(s), IDESC_TF32, s > 0);
            tc_commit(sbar);
        }
    }

    // VT(0) from K buf 0
    stageVT(0, 0);

    float rsum = 0.0f;

    for (int kt = 0; kt < SEQ / 64; kt++) {
        // 0. early LDG of K(kt+2)
        float4 kr[4];
        const bool do_stage = (kt + 2 < SEQ / 64);
        if (do_stage) {
            const float4* k4 = (const float4*)(kb + (size_t)(kt + 2) * 64 * HD);
#pragma unroll
            for (int i = 0; i < 4; i++) kr[i] = k4[tid + i * 256];
        }

        // 1. wait S(kt)   (flip kt+1, parity kt&1)
        mbar_wait(sbar, (uint32_t)(kt & 1));
        fence_after();

        // 2. issue S(kt+1) immediately (reads K buf (kt+1)&1, other S buf)
        if (kt < SEQ / 64 - 1 && wid == 0) {
            if (elect_one()) {
                uint64_t kd = make_desc(sb + AT_K + ((kt + 1) & 1) * 16384);
                uint32_t dstS = tmem + (uint32_t)(((kt + 1) & 1) * 64);
#pragma unroll
                for (int s = 0; s < 8; s++)
                    mma_tf32_ss(dstS, qd + AOFF(s), kd + BOFF(s), IDESC_TF32, s > 0);
                tc_commit(sbar);
            }
        }

        // 3. LDTM S(kt) -> ex2 -> tf32 (registers)
        uint32_t v[32];
        ld32(v, tmem + (uint32_t)((kt & 1) * 64 + half * 32));
        tc_wait_ld();
#pragma unroll
        for (int c = 0; c < 32; c++) {
            float e = ex2f(__uint_as_float(v[c]));
            rsum += e;
            v[c] = __float_as_uint(cvt_tf32(e));
        }

        // 4. wait O(kt-1) (flip kt, parity (kt+1)&1) — frees P (TMEM) and
        //    VT buf (kt-1)&1
        if (kt >= 1) mbar_wait(obar, (uint32_t)((kt + 1) & 1));

        // 4b. STTM P (single TMEM buffer, now free)
        st32(P_T + (uint32_t)(half * 32) + wsub, v);
        tc_wait_st();

        // 5a. stage K(kt+2) into buf kt&1 (K(kt) fully consumed: S(kt) waited,
        //     VT(kt) was staged last iteration)
        if (do_stage) stageK(kr, kt & 1);
        // 5b. stage VT(kt+1) from K buf (kt+1)&1 into VT buf (kt+1)&1
        if (kt + 1 < SEQ / 64) stageVT((kt + 1) & 1, (kt + 1) & 1);

        fence_async();
        fence_before();
        __syncthreads();

        // 6. issue O(kt): TS-form, A = P (TMEM), B = VT buf kt&1
        if (wid == 0) {
            fence_after();
            if (elect_one()) {
                uint64_t vd = make_desc(sb + AT_VT + (kt & 1) * 16384);
#pragma unroll
                for (int s = 0; s < 8; s++)
                    mma_tf32_ts(O_T, P_T + (uint32_t)(s * 8), vd + BOFF(s),
                                IDESC_TF32, (kt > 0) || (s > 0));
                tc_commit(obar);
            }
        }
    }

    // final: O(63) = flip 64, parity 1
    mbar_wait(obar, 1u);
    fence_after();

    *(float*)(smem + (half ? AT_RSB : AT_RSA) + row * 4) = rsum;

    uint32_t orr[32];
    ld32(orr, O_T + (uint32_t)(half * 32));
    tc_wait_ld();
    __syncthreads();

    float inv = 1.0f / (*(float*)(smem + AT_RSA + row * 4) +
                        *(float*)(smem + AT_RSB + row * 4));

    float* ob = out + ((size_t)blockIdx.z * SEQ + q0 + row) * DIM
                    + blockIdx.y * HD + half * 32;
#pragma unroll
    for (int j = 0; j < 32; j += 4)
        *(float4*)(ob + j) = make_float4(__uint_as_float(orr[j]) * inv,
                                         __uint_as_float(orr[j + 1]) * inv,
                                         __uint_as_float(orr[j + 2]) * inv,
                                         __uint_as_float(orr[j + 3]) * inv);

    fence_before();
    __syncthreads();
    if (tid == 0) { mbar_inval(sbar); mbar_inval(obar); }
    if (wid == 0) tc_dealloc(tmem, 256);

#else
    // -------- wmma fallback (R3 body) --------
    extern __shared__ float smf[];
    float* Ks0    = smf;
    float* Ks1    = smf + 64 * LDS;
    float* Ps     = smf + 128 * LDS;
    float* rowinv = smf + 256 * LDS;

    const int tid  = threadIdx.x;
    const int warp = tid >> 5;
    const int lane = tid & 31;
    const int bh   = blockIdx.z * NH + blockIdx.y;
    const int q0   = blockIdx.x * 128;

    const float* qb = g_q + (size_t)bh * SEQ * HD + (size_t)q0 * HD;
    const float* kb = g_k + (size_t)bh * SEQ * HD;
    const float scale = 0.04419417382415922f;

#pragma unroll
    for (int i = 0; i < 32; i++) {
        int idx = tid + i * 256;
        int r = idx >> 6, c = idx & 63;
        Ps[r * LDS + c] = wmma::__float_to_tf32(qb[idx] * scale);
    }
    __syncthreads();

    FragA qa[8];
#pragma unroll
    for (int kk = 0; kk < 8; kk++)
        wmma::load_matrix_sync(qa[kk], Ps + warp * 16 * LDS + kk * 8, LDS);

#pragma unroll
    for (int i = 0; i < 16; i++) {
        int idx = tid + i * 256;
        int r = idx >> 6, c = idx & 63;
        Ks0[r * LDS + c] = wmma::__float_to_tf32(kb[idx]);
    }
    __syncthreads();

    FragC oacc[4];
#pragma unroll
    for (int n = 0; n < 4; n++) wmma::fill_fragment(oacc[n], 0.0f);

    float rsum = 0.0f;
    float* Pw = Ps + warp * 16 * LDS;

    for (int kt = 0; kt < SEQ / 64; kt++) {
        float* cur = (kt & 1) ? Ks1 : Ks0;
        float* nxt = (kt & 1) ? Ks0 : Ks1;

        if (kt < SEQ / 64 - 1) {
            const float* kp = kb + (size_t)(kt + 1) * 64 * HD;
#pragma unroll
            for (int i = 0; i < 16; i++) {
                int idx = tid + i * 256;
                int r = idx >> 6, c = idx & 63;
                nxt[r * LDS + c] = wmma::__float_to_tf32(kp[idx]);
            }
        }

        FragC sacc[4];
#pragma unroll
        for (int n = 0; n < 4; n++) wmma::fill_fragment(sacc[n], 0.0f);
#pragma unroll
        for (int kk = 0; kk < 8; kk++) {
#pragma unroll
            for (int n = 0; n < 4; n++) {
                FragBc b;
                wmma::load_matrix_sync(b, cur + n * 16 * LDS + kk * 8, LDS);
                wmma::mma_sync(sacc[n], qa[kk], b, sacc[n]);
            }
        }

#pragma unroll
        for (int n = 0; n < 4; n++) {
#pragma unroll
            for (int e = 0; e < sacc[n].num_elements; e++)
                sacc[n].x[e] = wmma::__float_to_tf32(__expf(sacc[n].x[e]));
            wmma::store_matrix_sync(Pw + n * 16, sacc[n], LDS, wmma::mem_row_major);
        }
        __syncwarp();

        {
            const float* pp = Pw + (lane >> 1) * LDS + (lane & 1) * 32;
            float part = 0.0f;
#pragma unroll
            for (int c = 0; c < 32; c++) part += pp[c];
            rsum += part;
        }

#pragma unroll
        for (int kk = 0; kk < 8; kk++) {
            FragA a;
            wmma::load_matrix_sync(a, Pw + kk * 8, LDS);
#pragma unroll
            for (int n = 0; n < 4; n++) {
                FragBr b;
                wmma::load_matrix_sync(b, cur + kk * 8 * LDS + n * 16, LDS);
                wmma::mma_sync(oacc[n], a, b, oacc[n]);
            }
        }

        __syncthreads();
    }

    rsum += __shfl_xor_sync(0xffffffffu, rsum, 1);
    if ((lane & 1) == 0) rowinv[warp * 16 + (lane >> 1)] = 1.0f / rsum;

#pragma unroll
    for (int n = 0; n < 4; n++)
        wmma::store_matrix_sync(Pw + n * 16, oacc[n], LDS, wmma::mem_row_major);
    __syncthreads();

    float* ob = out + ((size_t)blockIdx.z * SEQ + q0) * DIM + blockIdx.y * HD;
#pragma unroll
    for (int i = 0; i < 32; i++) {
        int idx = tid + i * 256;
        int r = idx >> 6, c = idx & 63;
        ob[(size_t)r * DIM + c] = Ps[r * LDS + c] * rowinv[r];
    }
#endif
}

// ---------------------------------------------------------------------------
extern "C" void kernel_launch(void* const* d_in, const int* in_sizes, int n_in,
                              void* d_out, int out_size)
{
    const float* x  = (const float*)d_in[0];
    const float* Wq = (const float*)d_in[1];
    const float* bq = (const float*)d_in[2];
    const float* Wk = (const float*)d_in[3];
    const float* bk = (const float*)d_in[4];
    float* out = (float*)d_out;

    cudaFuncSetAttribute(proj_kernel, cudaFuncAttributeMaxDynamicSharedMemorySize, PJ_TOTAL);
    dim3 pg((BATCH * SEQ) / 128, DIM / 64, 2);
    proj_kernel<<<pg, 256, PJ_TOTAL>>>(x, Wq, bq, Wk, bk);

    cudaFuncSetAttribute(attn_kernel, cudaFuncAttributeMaxDynamicSharedMemorySize, ATTN_TOTAL);
    dim3 ag(SEQ / 128, NH, BATCH);
    attn_kernel<<<ag, 256, ATTN_TOTAL>>>(out);
}

// round 12
// speedup vs baseline: 4.7493x; 1.0080x over previous
#include <cuda_runtime.h>
#include <cuda_bf16.h>
#include <mma.h>
#include <cstdint>

using namespace nvcuda;

#define BATCH 2
#define SEQ   4096
#define DIM   512
#define NH    8
#define HD    64
#define LDS   68
#define LDSB  36

#if defined(__CUDA_ARCH__) && defined(__CUDA_ARCH_HAS_FEATURE__)
#if __CUDA_ARCH_HAS_FEATURE__(SM103_ALL)
#define TC_OK 1
#endif
#endif
#ifndef TC_OK
#define TC_OK 0
#endif

__device__ float g_q[(size_t)BATCH * NH * SEQ * HD];
__device__ float g_k[(size_t)BATCH * NH * SEQ * HD];

using FragA  = wmma::fragment<wmma::matrix_a, 16, 16, 8, wmma::precision::tf32, wmma::row_major>;
using FragBc = wmma::fragment<wmma::matrix_b, 16, 16, 8, wmma::precision::tf32, wmma::col_major>;
using FragBr = wmma::fragment<wmma::matrix_b, 16, 16, 8, wmma::precision::tf32, wmma::row_major>;
using FragC  = wmma::fragment<wmma::accumulator, 16, 16, 8, float>;

// ===========================================================================
// helpers
// ===========================================================================
__device__ __forceinline__ uint32_t smem_u32(const void* p) {
    uint32_t a;
    asm("{ .reg .u64 t; cvta.to.shared.u64 t, %1; cvt.u32.u64 %0, t; }" : "=r"(a) : "l"(p));
    return a;
}
__device__ __forceinline__ float cvt_tf32(float x) {
    float r; asm("cvt.rna.tf32.f32 %0, %1;" : "=f"(r) : "f"(x)); return r;
}
__device__ __forceinline__ float ex2f(float x) {
    float r; asm("ex2.approx.f32 %0, %1;" : "=f"(r) : "f"(x)); return r;
}

#if TC_OK
__device__ __forceinline__ uint32_t elect_one() {
    uint32_t p;
    asm volatile("{\n .reg .pred p;\n elect.sync _|p, 0xFFFFFFFF;\n selp.b32 %0, 1, 0, p;\n}" : "=r"(p));
    return p;
}
__device__ __forceinline__ void mbar_init(uint32_t mbar, uint32_t cnt) {
    asm volatile("mbarrier.init.shared.b64 [%0], %1;" :: "r"(mbar), "r"(cnt) : "memory");
}
__device__ __forceinline__ void mbar_inval(uint32_t mbar) {
    asm volatile("mbarrier.inval.shared.b64 [%0];" :: "r"(mbar) : "memory");
}
__device__ __forceinline__ void mbar_wait(uint32_t mbar, uint32_t parity) {
    asm volatile(
        "{\n .reg .pred P;\n"
        "W%=: mbarrier.try_wait.parity.acquire.cta.shared::cta.b64 P, [%0], %1, 0x989680;\n"
        " @P bra D%=;\n bra W%=;\n D%=:\n}"
        :: "r"(mbar), "r"(parity) : "memory");
}
__device__ __forceinline__ void tc_alloc(uint32_t smem_dst, uint32_t ncols) {
    asm volatile("tcgen05.alloc.cta_group::1.sync.aligned.shared::cta.b32 [%0], %1;"
                 :: "r"(smem_dst), "r"(ncols) : "memory");
}
__device__ __forceinline__ void tc_dealloc(uint32_t tmem, uint32_t ncols) {
    asm volatile("tcgen05.dealloc.cta_group::1.sync.aligned.b32 %0, %1;" :: "r"(tmem), "r"(ncols));
}
__device__ __forceinline__ void tc_commit(uint32_t mbar) {
    asm volatile("tcgen05.commit.cta_group::1.mbarrier::arrive::one.shared::cluster.b64 [%0];"
                 :: "r"(mbar) : "memory");
}
__device__ __forceinline__ void fence_before() { asm volatile("tcgen05.fence::before_thread_sync;" ::: "memory"); }
__device__ __forceinline__ void fence_after()  { asm volatile("tcgen05.fence::after_thread_sync;" ::: "memory"); }
__device__ __forceinline__ void fence_async()  { asm volatile("fence.proxy.async.shared::cta;" ::: "memory"); }
__device__ __forceinline__ void tc_wait_ld()   { asm volatile("tcgen05.wait::ld.sync.aligned;" ::: "memory"); }
__device__ __forceinline__ void tc_wait_st()   { asm volatile("tcgen05.wait::st.sync.aligned;" ::: "memory"); }

__device__ __forceinline__ void mma_tf32_ss(uint32_t d, uint64_t a, uint64_t b,
                                            uint32_t idesc, uint32_t en) {
    asm volatile(
        "{\n .reg .pred p;\n setp.ne.u32 p, %5, 0;\n"
        " tcgen05.mma.cta_group::1.kind::tf32 [%0], %1, %2, %3, {%4, %4, %4, %4}, p;\n}"
        :: "r"(d), "l"(a), "l"(b), "r"(idesc), "r"(0u), "r"(en) : "memory");
}
__device__ __forceinline__ void mma_tf32_ts(uint32_t d, uint32_t a, uint64_t b,
                                            uint32_t idesc, uint32_t en) {
    asm volatile(
        "{\n .reg .pred p;\n setp.ne.u32 p, %5, 0;\n"
        " tcgen05.mma.cta_group::1.kind::tf32 [%0], [%1], %2, %3, {%4, %4, %4, %4}, p;\n}"
        :: "r"(d), "r"(a), "l"(b), "r"(idesc), "r"(0u), "r"(en) : "memory");
}

__device__ __forceinline__ void ld32(uint32_t* r, uint32_t addr) {
    asm volatile(
        "tcgen05.ld.sync.aligned.32x32b.x32.b32 "
        "{%0,%1,%2,%3,%4,%5,%6,%7,%8,%9,%10,%11,%12,%13,%14,%15,"
        "%16,%17,%18,%19,%20,%21,%22,%23,%24,%25,%26,%27,%28,%29,%30,%31}, [%32];"
        : "=r"(r[0]),"=r"(r[1]),"=r"(r[2]),"=r"(r[3]),"=r"(r[4]),"=r"(r[5]),"=r"(r[6]),"=r"(r[7]),
          "=r"(r[8]),"=r"(r[9]),"=r"(r[10]),"=r"(r[11]),"=r"(r[12]),"=r"(r[13]),"=r"(r[14]),"=r"(r[15]),
          "=r"(r[16]),"=r"(r[17]),"=r"(r[18]),"=r"(r[19]),"=r"(r[20]),"=r"(r[21]),"=r"(r[22]),"=r"(r[23]),
          "=r"(r[24]),"=r"(r[25]),"=r"(r[26]),"=r"(r[27]),"=r"(r[28]),"=r"(r[29]),"=r"(r[30]),"=r"(r[31])
        : "r"(addr));
}
__device__ __forceinline__ void st32(uint32_t addr, const uint32_t* r) {
    asm volatile(
        "tcgen05.st.sync.aligned.32x32b.x32.b32 [%0], "
        "{%1,%2,%3,%4,%5,%6,%7,%8,%9,%10,%11,%12,%13,%14,%15,%16,"
        "%17,%18,%19,%20,%21,%22,%23,%24,%25,%26,%27,%28,%29,%30,%31,%32};"
        :: "r"(addr),
           "r"(r[0]),"r"(r[1]),"r"(r[2]),"r"(r[3]),"r"(r[4]),"r"(r[5]),"r"(r[6]),"r"(r[7]),
           "r"(r[8]),"r"(r[9]),"r"(r[10]),"r"(r[11]),"r"(r[12]),"r"(r[13]),"r"(r[14]),"r"(r[15]),
           "r"(r[16]),"r"(r[17]),"r"(r[18]),"r"(r[19]),"r"(r[20]),"r"(r[21]),"r"(r[22]),"r"(r[23]),
           "r"(r[24]),"r"(r[25]),"r"(r[26]),"r"(r[27]),"r"(r[28]),"r"(r[29]),"r"(r[30]),"r"(r[31])
        : "memory");
}

// K-major SW128 descriptor: SBO=64, LBO=1, version=1
__device__ __forceinline__ uint64_t make_desc(uint32_t addr) {
    const uint64_t base = (uint64_t(2) << 61) | (uint64_t(1) << 46) |
                          (uint64_t(64) << 32) | (uint64_t(1) << 16);
    return base | ((uint64_t)(addr >> 4) & 0x3FFF);
}
#endif  // TC_OK

#define IDESC_TF32 ((1u<<4) | (2u<<7) | (2u<<10) | (8u<<17) | (8u<<24))  // F32 acc, tf32 a/b, N=64, M=128

#define AOFF(s) ((s) < 4 ? (uint64_t)((s) * 2) : (uint64_t)(1024 + ((s) - 4) * 2))
#define BOFF(s) ((s) < 4 ? (uint64_t)((s) * 2) : (uint64_t)(512  + ((s) - 4) * 2))

// ===========================================================================
// Projection (unchanged from R6): grid (64, 8, 2), 256 thr.
// ===========================================================================
#define PJ_TMEMP   0
#define PJ_BAR(i)  (8 + (i) * 8)
#define PJ_X       1024
#define PJ_XSTR    16384
#define PJ_W       (1024 + 3 * 16384)
#define PJ_WSTR    8192
#define PJ_TOTAL   74880

__global__ void __launch_bounds__(256, 2)
proj_kernel(const float* __restrict__ x,
            const float* __restrict__ Wq, const float* __restrict__ bq,
            const float* __restrict__ Wk, const float* __restrict__ bk)
{
    const int which = blockIdx.z;
    const float* W    = which ? Wk : Wq;
    const float* bias = which ? bk : bq;

#if TC_OK
    extern __shared__ __align__(1024) char smem[];
    const uint32_t sb = smem_u32(smem);

    const int tid  = threadIdx.x;
    const int wid  = tid >> 5;
    const int lane = tid & 31;
    const int half = wid >> 2;
    const int row  = (wid & 3) * 32 + lane;
    const int m0   = blockIdx.x * 128;
    const int e0   = blockIdx.y * 64;

    if (wid == 0) tc_alloc(sb + PJ_TMEMP, 64);
    if (tid == 0) {
        mbar_init(sb + PJ_BAR(0), 1);
        mbar_init(sb + PJ_BAR(1), 1);
        mbar_init(sb + PJ_BAR(2), 1);
    }

    auto stageX = [&](int k0, int b) {
#pragma unroll
        for (int i = 0; i < 4; i++) {
            int idx4 = tid + i * 256;
            int r = idx4 >> 3, c4 = (idx4 & 7) * 4;
            float4 v = *(const float4*)(x + (size_t)(m0 + r) * DIM + k0 + c4);
            uint32_t off = ((uint32_t)(r >> 3) * 1024 + (r & 7) * 128 + c4 * 4)
                           ^ ((uint32_t)(r & 7) << 4);
            *(float4*)(smem + PJ_X + b * PJ_XSTR + off) = make_float4(
                cvt_tf32(v.x), cvt_tf32(v.y), cvt_tf32(v.z), cvt_tf32(v.w));
        }
    };
    auto stageW = [&](int k0, int b) {
#pragma unroll
        for (int i = 0; i < 2; i++) {
            int idx4 = tid + i * 256;
            int r = idx4 >> 3, c4 = (idx4 & 7) * 4;
            float4 v = *(const float4*)(W + (size_t)(e0 + r) * DIM + k0 + c4);
            uint32_t off = ((uint32_t)(r >> 3) * 1024 + (r & 7) * 128 + c4 * 4)
                           ^ ((uint32_t)(r & 7) << 4);
            *(float4*)(smem + PJ_W + b * PJ_WSTR + off) = make_float4(
                cvt_tf32(v.x), cvt_tf32(v.y), cvt_tf32(v.z), cvt_tf32(v.w));
        }
    };

    stageX(0, 0);  stageW(0, 0);
    stageX(32, 1); stageW(32, 1);
    fence_async();
    fence_before();
    __syncthreads();

    uint32_t tmem;
    asm volatile("ld.shared.b32 %0, [%1];" : "=r"(tmem) : "r"(sb + PJ_TMEMP));

    int ph0 = 0, ph1 = 0, ph2 = 0;
#pragma unroll
    for (int c = 0; c < 16; c++) {
        if (wid == 0) {
            fence_after();
            if (elect_one()) {
                uint64_t ad = make_desc(sb + PJ_X + (c % 3) * PJ_XSTR);
                uint64_t bd = make_desc(sb + PJ_W + (c % 3) * PJ_WSTR);
#pragma unroll
                for (int s = 0; s < 4; s++)
                    mma_tf32_ss(tmem, ad + s * 2, bd + s * 2, IDESC_TF32, (c > 0) || (s > 0));
                tc_commit(sb + PJ_BAR(c % 3));
            }
        }
        if (c + 2 < 16) {
            const int b2 = (c + 2) % 3;
            if (c + 2 >= 3) {
                if (b2 == 0)      { mbar_wait(sb + PJ_BAR(0), (uint32_t)ph0); ph0 ^= 1; }
                else if (b2 == 1) { mbar_wait(sb + PJ_BAR(1), (uint32_t)ph1); ph1 ^= 1; }
                else              { mbar_wait(sb + PJ_BAR(2), (uint32_t)ph2); ph2 ^= 1; }
            }
            stageX((c + 2) * 32, b2);
            stageW((c + 2) * 32, b2);
            fence_async();
            fence_before();
            __syncthreads();
        }
    }

    mbar_wait(sb + PJ_BAR(0), (uint32_t)ph0);
    fence_after();

    uint32_t orr[32];
    ld32(orr, tmem + (uint32_t)(half * 32));
    tc_wait_ld();

    const int m = m0 + row;
    const int b = m >> 12;
    const int nn = m & (SEQ - 1);
    float* dst = (which ? g_k : g_q)
               + (((size_t)b * NH + blockIdx.y) * SEQ + nn) * HD + half * 32;
    const float* bp = bias + e0 + half * 32;
#pragma unroll
    for (int j = 0; j < 32; j += 4)
        *(float4*)(dst + j) = make_float4(__uint_as_float(orr[j])     + bp[j],
                                          __uint_as_float(orr[j + 1]) + bp[j + 1],
                                          __uint_as_float(orr[j + 2]) + bp[j + 2],
                                          __uint_as_float(orr[j + 3]) + bp[j + 3]);

    fence_before();
    __syncthreads();
    if (tid == 0) { mbar_inval(sb + PJ_BAR(0)); mbar_inval(sb + PJ_BAR(1)); mbar_inval(sb + PJ_BAR(2)); }
    if (wid == 0) tc_dealloc(tmem, 64);

#else
    // -------- wmma fallback --------
    extern __shared__ float smf[];
    float* As = smf;
    float* Bs = smf + 128 * LDSB;

    const int tid  = threadIdx.x;
    const int warp = tid >> 5;
    const int m0   = blockIdx.x * 128;
    const int e0   = blockIdx.y * 64;

    FragC acc[4];
#pragma unroll
    for (int n = 0; n < 4; n++) wmma::fill_fragment(acc[n], 0.0f);

    float xr[16], wr[8];
#pragma unroll
    for (int i = 0; i < 16; i++) {
        int idx = tid + i * 256, r = idx >> 5, c = idx & 31;
        xr[i] = x[(size_t)(m0 + r) * DIM + c];
    }
#pragma unroll
    for (int i = 0; i < 8; i++) {
        int idx = tid + i * 256, r = idx >> 5, c = idx & 31;
        wr[i] = W[(size_t)(e0 + r) * DIM + c];
    }

    for (int kt = 0; kt < 16; kt++) {
#pragma unroll
        for (int i = 0; i < 16; i++) {
            int idx = tid + i * 256, r = idx >> 5, c = idx & 31;
            As[r * LDSB + c] = wmma::__float_to_tf32(xr[i]);
        }
#pragma unroll
        for (int i = 0; i < 8; i++) {
            int idx = tid + i * 256, r = idx >> 5, c = idx & 31;
            Bs[r * LDSB + c] = wmma::__float_to_tf32(wr[i]);
        }
        __syncthreads();

        if (kt < 15) {
            const int k0 = (kt + 1) * 32;
#pragma unroll
            for (int i = 0; i < 16; i++) {
                int idx = tid + i * 256, r = idx >> 5, c = idx & 31;
                xr[i] = x[(size_t)(m0 + r) * DIM + k0 + c];
            }
#pragma unroll
            for (int i = 0; i < 8; i++) {
                int idx = tid + i * 256, r = idx >> 5, c = idx & 31;
                wr[i] = W[(size_t)(e0 + r) * DIM + k0 + c];
            }
        }

#pragma unroll
        for (int kk = 0; kk < 4; kk++) {
            FragA a;
            wmma::load_matrix_sync(a, As + warp * 16 * LDSB + kk * 8, LDSB);
#pragma unroll
            for (int n = 0; n < 4; n++) {
                FragBc b;
                wmma::load_matrix_sync(b, Bs + n * 16 * LDSB + kk * 8, LDSB);
                wmma::mma_sync(acc[n], a, b, acc[n]);
            }
        }
        __syncthreads();
    }

#pragma unroll
    for (int n = 0; n < 4; n++)
        wmma::store_matrix_sync(smf + warp * 16 * LDS + n * 16, acc[n], LDS, wmma::mem_row_major);
    __syncthreads();

    float* dst = which ? g_k : g_q;
    const int h = blockIdx.y;
#pragma unroll
    for (int i = 0; i < 32; i++) {
        int idx = tid + i * 256;
        int r = idx >> 6, c = idx & 63;
        int m = m0 + r;
        int b = m >> 12;
        int nn = m & (SEQ - 1);
        dst[(((size_t)b * NH + h) * SEQ + nn) * HD + c] = smf[r * LDS + c] + bias[e0 + c];
    }
#endif
}

// ===========================================================================
// Attention. Grid (32, 8, 2), 256 threads. R9 skeleton (uniform control flow)
// with P DOUBLE-BUFFERED in TMEM:
//   TMEM (alloc 512): S0 @0, S1 @64, O @128, P0 @192, P1 @256.
//   STTM P(kt&1) issues right after ex2 (prev reader O(kt-2) long retired);
//   obar(kt-1) wait moved after stageK, overlapping staging work.
//   SMEM: Q 32KB, K 2x16KB, VT 2x16KB.
// ===========================================================================
#define AT_TMEMP  0
#define AT_SBAR   8
#define AT_OBAR   16
#define AT_RSA    32
#define AT_RSB    544
#define AT_Q      1024
#define AT_K      33792                    /* 2 x 16384 */
#define AT_VT     66560                    /* 2 x 16384 */
#define ATTN_TOTAL 99328

__global__ void __launch_bounds__(256, 1)
attn_kernel(float* __restrict__ out)
{
#if TC_OK
    extern __shared__ __align__(1024) char smem[];
    const uint32_t sb = smem_u32(smem);

    const int tid  = threadIdx.x;
    const int wid  = tid >> 5;
    const int lane = tid & 31;
    const int half = wid >> 2;
    const int row  = (wid & 3) * 32 + lane;

    const int bh = blockIdx.z * NH + blockIdx.y;
    const int q0 = blockIdx.x * 128;
    const float* qb = g_q + (size_t)bh * SEQ * HD + (size_t)q0 * HD;
    const float* kb = g_k + (size_t)bh * SEQ * HD;
    // 512^-0.5 * log2(e) folded into Q scale (exp -> raw ex2)
    const float scale = 0.063758746f;

    if (wid == 0) tc_alloc(sb + AT_TMEMP, 512);

    // Stage Q (128x64, scale folded, tf32, blocked SW128; 16 atoms/col-block)
    {
        const float4* q4 = (const float4*)qb;
#pragma unroll
        for (int i = 0; i < 8; i++) {
            int idx4 = tid + i * 256;
            int eb = idx4 * 4;
            int r = eb >> 6, c = eb & 63;
            float4 v = q4[idx4];
            uint32_t atom = (uint32_t)((r >> 3) + ((c >> 5) << 4));
            uint32_t off = (atom * 1024 + (r & 7) * 128 + (c & 31) * 4)
                           ^ ((uint32_t)(r & 7) << 4);
            *(float4*)(smem + AT_Q + off) = make_float4(
                cvt_tf32(v.x * scale), cvt_tf32(v.y * scale),
                cvt_tf32(v.z * scale), cvt_tf32(v.w * scale));
        }
    }

    auto stageK = [&](const float4* kr, int b) {
        char* Kb = smem + AT_K + b * 16384;
#pragma unroll
        for (int i = 0; i < 4; i++) {
            int idx4 = tid + i * 256;
            int eb = idx4 * 4;
            int key = eb >> 6, h0 = eb & 63;
            float4 v = kr[i];
            uint32_t offk = ((uint32_t)((key >> 3) + ((h0 >> 5) << 3)) * 1024
                             + (key & 7) * 128 + (h0 & 31) * 4) ^ ((uint32_t)(key & 7) << 4);
            *(float4*)(Kb + offk) = make_float4(
                cvt_tf32(v.x), cvt_tf32(v.y), cvt_tf32(v.z), cvt_tf32(v.w));
        }
    };

    // conflict-free smem transpose K -> VT
    auto stageVT = [&](int kbuf, int vbuf) {
        char* Kb = smem + AT_K  + kbuf * 16384;
        char* Vb = smem + AT_VT + vbuf * 16384;
#pragma unroll
        for (int j = 0; j < 4; j++) {
            int idx = tid + j * 256;
            int hd = idx & 63, kq = idx >> 6;
            float v[4];
#pragma unroll
            for (int r = 0; r < 4; r++) {
                int key = kq * 4 + r;
                uint32_t offr = ((uint32_t)((key >> 3) + ((hd >> 5) << 3)) * 1024
                                 + (key & 7) * 128 + (hd & 31) * 4)
                                ^ ((uint32_t)(key & 7) << 4);
                v[r] = *(const float*)(Kb + offr);
            }
            uint32_t offw = ((uint32_t)((hd >> 3) + ((kq >> 3) << 3)) * 1024
                             + (hd & 7) * 128 + ((kq * 4) & 31) * 4)
                            ^ ((uint32_t)(hd & 7) << 4);
            *(float4*)(Vb + offw) = make_float4(v[0], v[1], v[2], v[3]);
        }
    };

    // Prologue: stage K tiles 0 and 1 (ring of 2)
    {
        float4 kr[4];
#pragma unroll
        for (int i = 0; i < 4; i++) kr[i] = ((const float4*)kb)[tid + i * 256];
        stageK(kr, 0);
#pragma unroll
        for (int i = 0; i < 4; i++) kr[i] = ((const float4*)(kb + (size_t)64 * HD))[tid + i * 256];
        stageK(kr, 1);
    }

    if (tid == 0) { mbar_init(sb + AT_SBAR, 1); mbar_init(sb + AT_OBAR, 1); }
    fence_async();
    fence_before();
    __syncthreads();

    uint32_t tmem;
    asm volatile("ld.shared.b32 %0, [%1];" : "=r"(tmem) : "r"(sb + AT_TMEMP));
    const uint32_t O_T  = tmem + 128;
    const uint32_t P_T0 = tmem + 192;
    const uint32_t P_T1 = tmem + 256;
    const uint32_t sbar = sb + AT_SBAR;
    const uint32_t obar = sb + AT_OBAR;
    const uint64_t qd   = make_desc(sb + AT_Q);
    const uint32_t wsub = (uint32_t)(wid & 3) << 21;   // TMEM subpartition field

    // issue S(0) -> S-buf 0
    if (wid == 0) {
        fence_after();
        if (elect_one()) {
            uint64_t kd = make_desc(sb + AT_K);
#pragma unroll
            for (int s = 0; s < 8; s++)
                mma_tf32_ss(tmem, qd + AOFF(s), kd + BOFF(s), IDESC_TF32, s > 0);
            tc_commit(sbar);
        }
    }

    // VT(0) from K buf 0
    stageVT(0, 0);

    float rsum = 0.0f;

    for (int kt = 0; kt < SEQ / 64; kt++) {
        // 0. early LDG of K(kt+2)
        float4 kr[4];
        const bool do_stage = (kt + 2 < SEQ / 64);
        if (do_stage) {
            const float4* k4 = (const float4*)(kb + (size_t)(kt + 2) * 64 * HD);
#pragma unroll
            for (int i = 0; i < 4; i++) kr[i] = k4[tid + i * 256];
        }

        // 1. wait S(kt)   (flip kt+1, parity kt&1)
        mbar_wait(sbar, (uint32_t)(kt & 1));
        fence_after();

        // 2. issue S(kt+1) immediately (reads K buf (kt+1)&1, other S buf)
        if (kt < SEQ / 64 - 1 && wid == 0) {
            if (elect_one()) {
                uint64_t kd = make_desc(sb + AT_K + ((kt + 1) & 1) * 16384);
                uint32_t dstS = tmem + (uint32_t)(((kt + 1) & 1) * 64);
#pragma unroll
                for (int s = 0; s < 8; s++)
                    mma_tf32_ss(dstS, qd + AOFF(s), kd + BOFF(s), IDESC_TF32, s > 0);
                tc_commit(sbar);
            }
        }

        // 3. LDTM S(kt) -> ex2 -> tf32 -> STTM P(kt&1) (double-buffered:
        //    previous reader O(kt-2) retired at iter kt-1's obar wait)
        uint32_t v[32];
        ld32(v, tmem + (uint32_t)((kt & 1) * 64 + half * 32));
        tc_wait_ld();
#pragma unroll
        for (int c = 0; c < 32; c++) {
            float e = ex2f(__uint_as_float(v[c]));
            rsum += e;
            v[c] = __float_as_uint(cvt_tf32(e));
        }
        st32(((kt & 1) ? P_T1 : P_T0) + (uint32_t)(half * 32) + wsub, v);
        tc_wait_st();

        // 4. stage K(kt+2) into buf kt&1 (K(kt) fully consumed: S(kt) waited,
        //    VT(kt) staged last iteration)
        if (do_stage) stageK(kr, kt & 1);

        // 5. wait O(kt-1) (flip kt, parity (kt+1)&1) — frees VT buf (kt-1)&1
        if (kt >= 1) mbar_wait(obar, (uint32_t)((kt + 1) & 1));

        // 6. stage VT(kt+1) from K buf (kt+1)&1 into VT buf (kt+1)&1
        if (kt + 1 < SEQ / 64) stageVT((kt + 1) & 1, (kt + 1) & 1);

        fence_async();
        fence_before();
        __syncthreads();

        // 7. issue O(kt): TS-form, A = P(kt&1) (TMEM), B = VT buf kt&1
        if (wid == 0) {
            fence_after();
            if (elect_one()) {
                uint64_t vd = make_desc(sb + AT_VT + (kt & 1) * 16384);
                uint32_t pT = (kt & 1) ? P_T1 : P_T0;
#pragma unroll
                for (int s = 0; s < 8; s++)
                    mma_tf32_ts(O_T, pT + (uint32_t)(s * 8), vd + BOFF(s),
                                IDESC_TF32, (kt > 0) || (s > 0));
                tc_commit(obar);
            }
        }
    }

    // final: O(63) = flip 64, parity 1
    mbar_wait(obar, 1u);
    fence_after();

    *(float*)(smem + (half ? AT_RSB : AT_RSA) + row * 4) = rsum;

    uint32_t orr[32];
    ld32(orr, O_T + (uint32_t)(half * 32));
    tc_wait_ld();
    __syncthreads();

    float inv = 1.0f / (*(float*)(smem + AT_RSA + row * 4) +
                        *(float*)(smem + AT_RSB + row * 4));

    float* ob = out + ((size_t)blockIdx.z * SEQ + q0 + row) * DIM
                    + blockIdx.y * HD + half * 32;
#pragma unroll
    for (int j = 0; j < 32; j += 4)
        *(float4*)(ob + j) = make_float4(__uint_as_float(orr[j]) * inv,
                                         __uint_as_float(orr[j + 1]) * inv,
                                         __uint_as_float(orr[j + 2]) * inv,
                                         __uint_as_float(orr[j + 3]) * inv);

    fence_before();
    __syncthreads();
    if (tid == 0) { mbar_inval(sbar); mbar_inval(obar); }
    if (wid == 0) tc_dealloc(tmem, 512);

#else
    // -------- wmma fallback (R3 body) --------
    extern __shared__ float smf[];
    float* Ks0    = smf;
    float* Ks1    = smf + 64 * LDS;
    float* Ps     = smf + 128 * LDS;
    float* rowinv = smf + 256 * LDS;

    const int tid  = threadIdx.x;
    const int warp = tid >> 5;
    const int lane = tid & 31;
    const int bh   = blockIdx.z * NH + blockIdx.y;
    const int q0   = blockIdx.x * 128;

    const float* qb = g_q + (size_t)bh * SEQ * HD + (size_t)q0 * HD;
    const float* kb = g_k + (size_t)bh * SEQ * HD;
    const float scale = 0.04419417382415922f;

#pragma unroll
    for (int i = 0; i < 32; i++) {
        int idx = tid + i * 256;
        int r = idx >> 6, c = idx & 63;
        Ps[r * LDS + c] = wmma::__float_to_tf32(qb[idx] * scale);
    }
    __syncthreads();

    FragA qa[8];
#pragma unroll
    for (int kk = 0; kk < 8; kk++)
        wmma::load_matrix_sync(qa[kk], Ps + warp * 16 * LDS + kk * 8, LDS);

#pragma unroll
    for (int i = 0; i < 16; i++) {
        int idx = tid + i * 256;
        int r = idx >> 6, c = idx & 63;
        Ks0[r * LDS + c] = wmma::__float_to_tf32(kb[idx]);
    }
    __syncthreads();

    FragC oacc[4];
#pragma unroll
    for (int n = 0; n < 4; n++) wmma::fill_fragment(oacc[n], 0.0f);

    float rsum = 0.0f;
    float* Pw = Ps + warp * 16 * LDS;

    for (int kt = 0; kt < SEQ / 64; kt++) {
        float* cur = (kt & 1) ? Ks1 : Ks0;
        float* nxt = (kt & 1) ? Ks0 : Ks1;

        if (kt < SEQ / 64 - 1) {
            const float* kp = kb + (size_t)(kt + 1) * 64 * HD;
#pragma unroll
            for (int i = 0; i < 16; i++) {
                int idx = tid + i * 256;
                int r = idx >> 6, c = idx & 63;
                nxt[r * LDS + c] = wmma::__float_to_tf32(kp[idx]);
            }
        }

        FragC sacc[4];
#pragma unroll
        for (int n = 0; n < 4; n++) wmma::fill_fragment(sacc[n], 0.0f);
#pragma unroll
        for (int kk = 0; kk < 8; kk++) {
#pragma unroll
            for (int n = 0; n < 4; n++) {
                FragBc b;
                wmma::load_matrix_sync(b, cur + n * 16 * LDS + kk * 8, LDS);
                wmma::mma_sync(sacc[n], qa[kk], b, sacc[n]);
            }
        }

#pragma unroll
        for (int n = 0; n < 4; n++) {
#pragma unroll
            for (int e = 0; e < sacc[n].num_elements; e++)
                sacc[n].x[e] = wmma::__float_to_tf32(__expf(sacc[n].x[e]));
            wmma::store_matrix_sync(Pw + n * 16, sacc[n], LDS, wmma::mem_row_major);
        }
        __syncwarp();

        {
            const float* pp = Pw + (lane >> 1) * LDS + (lane & 1) * 32;
            float part = 0.0f;
#pragma unroll
            for (int c = 0; c < 32; c++) part += pp[c];
            rsum += part;
        }

#pragma unroll
        for (int kk = 0; kk < 8; kk++) {
            FragA a;
            wmma::load_matrix_sync(a, Pw + kk * 8, LDS);
#pragma unroll
            for (int n = 0; n < 4; n++) {
                FragBr b;
                wmma::load_matrix_sync(b, cur + kk * 8 * LDS + n * 16, LDS);
                wmma::mma_sync(oacc[n], a, b, oacc[n]);
            }
        }

        __syncthreads();
    }

    rsum += __shfl_xor_sync(0xffffffffu, rsum, 1);
    if ((lane & 1) == 0) rowinv[warp * 16 + (lane >> 1)] = 1.0f / rsum;

#pragma unroll
    for (int n = 0; n < 4; n++)
        wmma::store_matrix_sync(Pw + n * 16, oacc[n], LDS, wmma::mem_row_major);
    __syncthreads();

    float* ob = out + ((size_t)blockIdx.z * SEQ + q0) * DIM + blockIdx.y * HD;
#pragma unroll
    for (int i = 0; i < 32; i++) {
        int idx = tid + i * 256;
        int r = idx >> 6, c = idx & 63;
        ob[(size_t)r * DIM + c] = Ps[r * LDS + c] * rowinv[r];
    }
#endif
}

// ---------------------------------------------------------------------------
extern "C" void kernel_launch(void* const* d_in, const int* in_sizes, int n_in,
                              void* d_out, int out_size)
{
    const float* x  = (const float*)d_in[0];
    const float* Wq = (const float*)d_in[1];
    const float* bq = (const float*)d_in[2];
    const float* Wk = (const float*)d_in[3];
    const float* bk = (const float*)d_in[4];
    float* out = (float*)d_out;

    cudaFuncSetAttribute(proj_kernel, cudaFuncAttributeMaxDynamicSharedMemorySize, PJ_TOTAL);
    dim3 pg((BATCH * SEQ) / 128, DIM / 64, 2);
    proj_kernel<<<pg, 256, PJ_TOTAL>>>(x, Wq, bq, Wk, bk);

    cudaFuncSetAttribute(attn_kernel, cudaFuncAttributeMaxDynamicSharedMemorySize, ATTN_TOTAL);
    dim3 ag(SEQ / 128, NH, BATCH);
    attn_kernel<<<ag, 256, ATTN_TOTAL>>>(out);
}

// round 13
// speedup vs baseline: 5.8010x; 1.2215x over previous
#include <cuda_runtime.h>
#include <cuda_bf16.h>
#include <mma.h>
#include <cstdint>

using namespace nvcuda;

#define BATCH 2
#define SEQ   4096
#define DIM   512
#define NH    8
#define HD    64
#define LDS   68
#define LDSB  36

#if defined(__CUDA_ARCH__) && defined(__CUDA_ARCH_HAS_FEATURE__)
#if __CUDA_ARCH_HAS_FEATURE__(SM103_ALL)
#define TC_OK 1
#endif
#endif
#ifndef TC_OK
#define TC_OK 0
#endif

__device__ float g_q[(size_t)BATCH * NH * SEQ * HD];
__device__ float g_k[(size_t)BATCH * NH * SEQ * HD];

using FragA  = wmma::fragment<wmma::matrix_a, 16, 16, 8, wmma::precision::tf32, wmma::row_major>;
using FragBc = wmma::fragment<wmma::matrix_b, 16, 16, 8, wmma::precision::tf32, wmma::col_major>;
using FragBr = wmma::fragment<wmma::matrix_b, 16, 16, 8, wmma::precision::tf32, wmma::row_major>;
using FragC  = wmma::fragment<wmma::accumulator, 16, 16, 8, float>;

// ===========================================================================
// helpers
// ===========================================================================
__device__ __forceinline__ uint32_t smem_u32(const void* p) {
    uint32_t a;
    asm("{ .reg .u64 t; cvta.to.shared.u64 t, %1; cvt.u32.u64 %0, t; }" : "=r"(a) : "l"(p));
    return a;
}
__device__ __forceinline__ float cvt_tf32(float x) {
    float r; asm("cvt.rna.tf32.f32 %0, %1;" : "=f"(r) : "f"(x)); return r;
}
__device__ __forceinline__ float ex2f(float x) {
    float r; asm("ex2.approx.f32 %0, %1;" : "=f"(r) : "f"(x)); return r;
}

#if TC_OK
__device__ __forceinline__ uint32_t elect_one() {
    uint32_t p;
    asm volatile("{\n .reg .pred p;\n elect.sync _|p, 0xFFFFFFFF;\n selp.b32 %0, 1, 0, p;\n}" : "=r"(p));
    return p;
}
__device__ __forceinline__ void mbar_init(uint32_t mbar, uint32_t cnt) {
    asm volatile("mbarrier.init.shared.b64 [%0], %1;" :: "r"(mbar), "r"(cnt) : "memory");
}
__device__ __forceinline__ void mbar_inval(uint32_t mbar) {
    asm volatile("mbarrier.inval.shared.b64 [%0];" :: "r"(mbar) : "memory");
}
__device__ __forceinline__ void mbar_wait(uint32_t mbar, uint32_t parity) {
    asm volatile(
        "{\n .reg .pred P;\n"
        "W%=: mbarrier.try_wait.parity.acquire.cta.shared::cta.b64 P, [%0], %1, 0x989680;\n"
        " @P bra D%=;\n bra W%=;\n D%=:\n}"
        :: "r"(mbar), "r"(parity) : "memory");
}
__device__ __forceinline__ void tc_alloc(uint32_t smem_dst, uint32_t ncols) {
    asm volatile("tcgen05.alloc.cta_group::1.sync.aligned.shared::cta.b32 [%0], %1;"
                 :: "r"(smem_dst), "r"(ncols) : "memory");
}
__device__ __forceinline__ void tc_dealloc(uint32_t tmem, uint32_t ncols) {
    asm volatile("tcgen05.dealloc.cta_group::1.sync.aligned.b32 %0, %1;" :: "r"(tmem), "r"(ncols));
}
__device__ __forceinline__ void tc_commit(uint32_t mbar) {
    asm volatile("tcgen05.commit.cta_group::1.mbarrier::arrive::one.shared::cluster.b64 [%0];"
                 :: "r"(mbar) : "memory");
}
__device__ __forceinline__ void fence_before() { asm volatile("tcgen05.fence::before_thread_sync;" ::: "memory"); }
__device__ __forceinline__ void fence_after()  { asm volatile("tcgen05.fence::after_thread_sync;" ::: "memory"); }
__device__ __forceinline__ void fence_async()  { asm volatile("fence.proxy.async.shared::cta;" ::: "memory"); }
__device__ __forceinline__ void tc_wait_ld()   { asm volatile("tcgen05.wait::ld.sync.aligned;" ::: "memory"); }
__device__ __forceinline__ void tc_wait_st()   { asm volatile("tcgen05.wait::st.sync.aligned;" ::: "memory"); }

__device__ __forceinline__ void mma_tf32_ss(uint32_t d, uint64_t a, uint64_t b,
                                            uint32_t idesc, uint32_t en) {
    asm volatile(
        "{\n .reg .pred p;\n setp.ne.u32 p, %5, 0;\n"
        " tcgen05.mma.cta_group::1.kind::tf32 [%0], %1, %2, %3, {%4, %4, %4, %4}, p;\n}"
        :: "r"(d), "l"(a), "l"(b), "r"(idesc), "r"(0u), "r"(en) : "memory");
}
__device__ __forceinline__ void mma_tf32_ts(uint32_t d, uint32_t a, uint64_t b,
                                            uint32_t idesc, uint32_t en) {
    asm volatile(
        "{\n .reg .pred p;\n setp.ne.u32 p, %5, 0;\n"
        " tcgen05.mma.cta_group::1.kind::tf32 [%0], [%1], %2, %3, {%4, %4, %4, %4}, p;\n}"
        :: "r"(d), "r"(a), "l"(b), "r"(idesc), "r"(0u), "r"(en) : "memory");
}

__device__ __forceinline__ void ld32(uint32_t* r, uint32_t addr) {
    asm volatile(
        "tcgen05.ld.sync.aligned.32x32b.x32.b32 "
        "{%0,%1,%2,%3,%4,%5,%6,%7,%8,%9,%10,%11,%12,%13,%14,%15,"
        "%16,%17,%18,%19,%20,%21,%22,%23,%24,%25,%26,%27,%28,%29,%30,%31}, [%32];"
        : "=r"(r[0]),"=r"(r[1]),"=r"(r[2]),"=r"(r[3]),"=r"(r[4]),"=r"(r[5]),"=r"(r[6]),"=r"(r[7]),
          "=r"(r[8]),"=r"(r[9]),"=r"(r[10]),"=r"(r[11]),"=r"(r[12]),"=r"(r[13]),"=r"(r[14]),"=r"(r[15]),
          "=r"(r[16]),"=r"(r[17]),"=r"(r[18]),"=r"(r[19]),"=r"(r[20]),"=r"(r[21]),"=r"(r[22]),"=r"(r[23]),
          "=r"(r[24]),"=r"(r[25]),"=r"(r[26]),"=r"(r[27]),"=r"(r[28]),"=r"(r[29]),"=r"(r[30]),"=r"(r[31])
        : "r"(addr));
}
__device__ __forceinline__ void st32(uint32_t addr, const uint32_t* r) {
    asm volatile(
        "tcgen05.st.sync.aligned.32x32b.x32.b32 [%0], "
        "{%1,%2,%3,%4,%5,%6,%7,%8,%9,%10,%11,%12,%13,%14,%15,%16,"
        "%17,%18,%19,%20,%21,%22,%23,%24,%25,%26,%27,%28,%29,%30,%31,%32};"
        :: "r"(addr),
           "r"(r[0]),"r"(r[1]),"r"(r[2]),"r"(r[3]),"r"(r[4]),"r"(r[5]),"r"(r[6]),"r"(r[7]),
           "r"(r[8]),"r"(r[9]),"r"(r[10]),"r"(r[11]),"r"(r[12]),"r"(r[13]),"r"(r[14]),"r"(r[15]),
           "r"(r[16]),"r"(r[17]),"r"(r[18]),"r"(r[19]),"r"(r[20]),"r"(r[21]),"r"(r[22]),"r"(r[23]),
           "r"(r[24]),"r"(r[25]),"r"(r[26]),"r"(r[27]),"r"(r[28]),"r"(r[29]),"r"(r[30]),"r"(r[31])
        : "memory");
}

// K-major SW128 descriptor: SBO=64, LBO=1, version=1
__device__ __forceinline__ uint64_t make_desc(uint32_t addr) {
    const uint64_t base = (uint64_t(2) << 61) | (uint64_t(1) << 46) |
                          (uint64_t(64) << 32) | (uint64_t(1) << 16);
    return base | ((uint64_t)(addr >> 4) & 0x3FFF);
}
#endif  // TC_OK

#define IDESC_TF32 ((1u<<4) | (2u<<7) | (2u<<10) | (8u<<17) | (8u<<24))  // F32 acc, tf32 a/b, N=64, M=128

#define AOFF(s) ((s) < 4 ? (uint64_t)((s) * 2) : (uint64_t)(1024 + ((s) - 4) * 2))
#define BOFF(s) ((s) < 4 ? (uint64_t)((s) * 2) : (uint64_t)(512  + ((s) - 4) * 2))

// ===========================================================================
// Projection (unchanged from R6): grid (64, 8, 2), 256 thr.
// ===========================================================================
#define PJ_TMEMP   0
#define PJ_BAR(i)  (8 + (i) * 8)
#define PJ_X       1024
#define PJ_XSTR    16384
#define PJ_W       (1024 + 3 * 16384)
#define PJ_WSTR    8192
#define PJ_TOTAL   74880

__global__ void __launch_bounds__(256, 2)
proj_kernel(const float* __restrict__ x,
            const float* __restrict__ Wq, const float* __restrict__ bq,
            const float* __restrict__ Wk, const float* __restrict__ bk)
{
    const int which = blockIdx.z;
    const float* W    = which ? Wk : Wq;
    const float* bias = which ? bk : bq;

#if TC_OK
    extern __shared__ __align__(1024) char smem[];
    const uint32_t sb = smem_u32(smem);

    const int tid  = threadIdx.x;
    const int wid  = tid >> 5;
    const int lane = tid & 31;
    const int half = wid >> 2;
    const int row  = (wid & 3) * 32 + lane;
    const int m0   = blockIdx.x * 128;
    const int e0   = blockIdx.y * 64;

    if (wid == 0) tc_alloc(sb + PJ_TMEMP, 64);
    if (tid == 0) {
        mbar_init(sb + PJ_BAR(0), 1);
        mbar_init(sb + PJ_BAR(1), 1);
        mbar_init(sb + PJ_BAR(2), 1);
    }

    auto stageX = [&](int k0, int b) {
#pragma unroll
        for (int i = 0; i < 4; i++) {
            int idx4 = tid + i * 256;
            int r = idx4 >> 3, c4 = (idx4 & 7) * 4;
            float4 v = *(const float4*)(x + (size_t)(m0 + r) * DIM + k0 + c4);
            uint32_t off = ((uint32_t)(r >> 3) * 1024 + (r & 7) * 128 + c4 * 4)
                           ^ ((uint32_t)(r & 7) << 4);
            *(float4*)(smem + PJ_X + b * PJ_XSTR + off) = make_float4(
                cvt_tf32(v.x), cvt_tf32(v.y), cvt_tf32(v.z), cvt_tf32(v.w));
        }
    };
    auto stageW = [&](int k0, int b) {
#pragma unroll
        for (int i = 0; i < 2; i++) {
            int idx4 = tid + i * 256;
            int r = idx4 >> 3, c4 = (idx4 & 7) * 4;
            float4 v = *(const float4*)(W + (size_t)(e0 + r) * DIM + k0 + c4);
            uint32_t off = ((uint32_t)(r >> 3) * 1024 + (r & 7) * 128 + c4 * 4)
                           ^ ((uint32_t)(r & 7) << 4);
            *(float4*)(smem + PJ_W + b * PJ_WSTR + off) = make_float4(
                cvt_tf32(v.x), cvt_tf32(v.y), cvt_tf32(v.z), cvt_tf32(v.w));
        }
    };

    stageX(0, 0);  stageW(0, 0);
    stageX(32, 1); stageW(32, 1);
    fence_async();
    fence_before();
    __syncthreads();

    uint32_t tmem;
    asm volatile("ld.shared.b32 %0, [%1];" : "=r"(tmem) : "r"(sb + PJ_TMEMP));

    int ph0 = 0, ph1 = 0, ph2 = 0;
#pragma unroll
    for (int c = 0; c < 16; c++) {
        if (wid == 0) {
            fence_after();
            if (elect_one()) {
                uint64_t ad = make_desc(sb + PJ_X + (c % 3) * PJ_XSTR);
                uint64_t bd = make_desc(sb + PJ_W + (c % 3) * PJ_WSTR);
#pragma unroll
                for (int s = 0; s < 4; s++)
                    mma_tf32_ss(tmem, ad + s * 2, bd + s * 2, IDESC_TF32, (c > 0) || (s > 0));
                tc_commit(sb + PJ_BAR(c % 3));
            }
        }
        if (c + 2 < 16) {
            const int b2 = (c + 2) % 3;
            if (c + 2 >= 3) {
                if (b2 == 0)      { mbar_wait(sb + PJ_BAR(0), (uint32_t)ph0); ph0 ^= 1; }
                else if (b2 == 1) { mbar_wait(sb + PJ_BAR(1), (uint32_t)ph1); ph1 ^= 1; }
                else              { mbar_wait(sb + PJ_BAR(2), (uint32_t)ph2); ph2 ^= 1; }
            }
            stageX((c + 2) * 32, b2);
            stageW((c + 2) * 32, b2);
            fence_async();
            fence_before();
            __syncthreads();
        }
    }

    mbar_wait(sb + PJ_BAR(0), (uint32_t)ph0);
    fence_after();

    uint32_t orr[32];
    ld32(orr, tmem + (uint32_t)(half * 32));
    tc_wait_ld();

    const int m = m0 + row;
    const int b = m >> 12;
    const int nn = m & (SEQ - 1);
    float* dst = (which ? g_k : g_q)
               + (((size_t)b * NH + blockIdx.y) * SEQ + nn) * HD + half * 32;
    const float* bp = bias + e0 + half * 32;
#pragma unroll
    for (int j = 0; j < 32; j += 4)
        *(float4*)(dst + j) = make_float4(__uint_as_float(orr[j])     + bp[j],
                                          __uint_as_float(orr[j + 1]) + bp[j + 1],
                                          __uint_as_float(orr[j + 2]) + bp[j + 2],
                                          __uint_as_float(orr[j + 3]) + bp[j + 3]);

    fence_before();
    __syncthreads();
    if (tid == 0) { mbar_inval(sb + PJ_BAR(0)); mbar_inval(sb + PJ_BAR(1)); mbar_inval(sb + PJ_BAR(2)); }
    if (wid == 0) tc_dealloc(tmem, 64);

#else
    // -------- wmma fallback --------
    extern __shared__ float smf[];
    float* As = smf;
    float* Bs = smf + 128 * LDSB;

    const int tid  = threadIdx.x;
    const int warp = tid >> 5;
    const int m0   = blockIdx.x * 128;
    const int e0   = blockIdx.y * 64;

    FragC acc[4];
#pragma unroll
    for (int n = 0; n < 4; n++) wmma::fill_fragment(acc[n], 0.0f);

    float xr[16], wr[8];
#pragma unroll
    for (int i = 0; i < 16; i++) {
        int idx = tid + i * 256, r = idx >> 5, c = idx & 31;
        xr[i] = x[(size_t)(m0 + r) * DIM + c];
    }
#pragma unroll
    for (int i = 0; i < 8; i++) {
        int idx = tid + i * 256, r = idx >> 5, c = idx & 31;
        wr[i] = W[(size_t)(e0 + r) * DIM + c];
    }

    for (int kt = 0; kt < 16; kt++) {
#pragma unroll
        for (int i = 0; i < 16; i++) {
            int idx = tid + i * 256, r = idx >> 5, c = idx & 31;
            As[r * LDSB + c] = wmma::__float_to_tf32(xr[i]);
        }
#pragma unroll
        for (int i = 0; i < 8; i++) {
            int idx = tid + i * 256, r = idx >> 5, c = idx & 31;
            Bs[r * LDSB + c] = wmma::__float_to_tf32(wr[i]);
        }
        __syncthreads();

        if (kt < 15) {
            const int k0 = (kt + 1) * 32;
#pragma unroll
            for (int i = 0; i < 16; i++) {
                int idx = tid + i * 256, r = idx >> 5, c = idx & 31;
                xr[i] = x[(size_t)(m0 + r) * DIM + k0 + c];
            }
#pragma unroll
            for (int i = 0; i < 8; i++) {
                int idx = tid + i * 256, r = idx >> 5, c = idx & 31;
                wr[i] = W[(size_t)(e0 + r) * DIM + k0 + c];
            }
        }

#pragma unroll
        for (int kk = 0; kk < 4; kk++) {
            FragA a;
            wmma::load_matrix_sync(a, As + warp * 16 * LDSB + kk * 8, LDSB);
#pragma unroll
            for (int n = 0; n < 4; n++) {
                FragBc b;
                wmma::load_matrix_sync(b, Bs + n * 16 * LDSB + kk * 8, LDSB);
                wmma::mma_sync(acc[n], a, b, acc[n]);
            }
        }
        __syncthreads();
    }

#pragma unroll
    for (int n = 0; n < 4; n++)
        wmma::store_matrix_sync(smf + warp * 16 * LDS + n * 16, acc[n], LDS, wmma::mem_row_major);
    __syncthreads();

    float* dst = which ? g_k : g_q;
    const int h = blockIdx.y;
#pragma unroll
    for (int i = 0; i < 32; i++) {
        int idx = tid + i * 256;
        int r = idx >> 6, c = idx & 63;
        int m = m0 + r;
        int b = m >> 12;
        int nn = m & (SEQ - 1);
        dst[(((size_t)b * NH + h) * SEQ + nn) * HD + c] = smf[r * LDS + c] + bias[e0 + c];
    }
#endif
}

// ===========================================================================
// Attention: TWO q-tiles (A: rows q0..q0+127, B: q0+128..q0+255) per CTA,
// same (b,h) -> K/VT staged ONCE per 2 tiles; mma queue stays fed while
// softmax runs. Grid (SEQ/256=16, NH, BATCH), 256 threads.
//   TMEM (512): SA0@0 SA1@64 OA@128 PA@192 | SB0@256 SB1@320 OB@384 PB@448.
//   SMEM: QA/QB 2x32KB, K 2x16KB, VT 2x16KB.
//   One sbar commit covers SA+SB; one obar covers OA+OB (commit tracks all
//   prior uncommitted mmas). Parity scheme identical to R12.
// ===========================================================================
#define AT_TMEMP  0
#define AT_SBAR   8
#define AT_OBAR   16
#define AT_RS(i)  (32 + (i) * 512)         /* 4 arrays of 128 floats */
#define AT_Q      3072                     /* 2 x 32768 */
#define AT_K      68608                    /* 2 x 16384 */
#define AT_VT     101376                   /* 2 x 16384 */
#define ATTN_TOTAL 134144

__global__ void __launch_bounds__(256, 1)
attn_kernel(float* __restrict__ out)
{
#if TC_OK
    extern __shared__ __align__(1024) char smem[];
    const uint32_t sb = smem_u32(smem);

    const int tid  = threadIdx.x;
    const int wid  = tid >> 5;
    const int lane = tid & 31;
    const int half = wid >> 2;
    const int row  = (wid & 3) * 32 + lane;

    const int bh = blockIdx.z * NH + blockIdx.y;
    const int q0 = blockIdx.x * 256;
    const float* qb = g_q + (size_t)bh * SEQ * HD + (size_t)q0 * HD;
    const float* kb = g_k + (size_t)bh * SEQ * HD;
    // 512^-0.5 * log2(e) folded into Q scale (exp -> raw ex2)
    const float scale = 0.063758746f;

    if (wid == 0) tc_alloc(sb + AT_TMEMP, 512);

    // Stage Q tiles A and B (each 128x64, scale folded, tf32, blocked SW128)
#pragma unroll
    for (int t = 0; t < 2; t++) {
        const float4* q4 = (const float4*)(qb + (size_t)t * 128 * HD);
        char* Qb = smem + AT_Q + t * 32768;
#pragma unroll
        for (int i = 0; i < 8; i++) {
            int idx4 = tid + i * 256;
            int eb = idx4 * 4;
            int r = eb >> 6, c = eb & 63;
            float4 v = q4[idx4];
            uint32_t atom = (uint32_t)((r >> 3) + ((c >> 5) << 4));
            uint32_t off = (atom * 1024 + (r & 7) * 128 + (c & 31) * 4)
                           ^ ((uint32_t)(r & 7) << 4);
            *(float4*)(Qb + off) = make_float4(
                cvt_tf32(v.x * scale), cvt_tf32(v.y * scale),
                cvt_tf32(v.z * scale), cvt_tf32(v.w * scale));
        }
    }

    auto stageK = [&](const float4* kr, int b) {
        char* Kb = smem + AT_K + b * 16384;
#pragma unroll
        for (int i = 0; i < 4; i++) {
            int idx4 = tid + i * 256;
            int eb = idx4 * 4;
            int key = eb >> 6, h0 = eb & 63;
            float4 v = kr[i];
            uint32_t offk = ((uint32_t)((key >> 3) + ((h0 >> 5) << 3)) * 1024
                             + (key & 7) * 128 + (h0 & 31) * 4) ^ ((uint32_t)(key & 7) << 4);
            *(float4*)(Kb + offk) = make_float4(
                cvt_tf32(v.x), cvt_tf32(v.y), cvt_tf32(v.z), cvt_tf32(v.w));
        }
    };

    // conflict-free smem transpose K -> VT
    auto stageVT = [&](int kbuf, int vbuf) {
        char* Kb = smem + AT_K  + kbuf * 16384;
        char* Vb = smem + AT_VT + vbuf * 16384;
#pragma unroll
        for (int j = 0; j < 4; j++) {
            int idx = tid + j * 256;
            int hd = idx & 63, kq = idx >> 6;
            float v[4];
#pragma unroll
            for (int r = 0; r < 4; r++) {
                int key = kq * 4 + r;
                uint32_t offr = ((uint32_t)((key >> 3) + ((hd >> 5) << 3)) * 1024
                                 + (key & 7) * 128 + (hd & 31) * 4)
                                ^ ((uint32_t)(key & 7) << 4);
                v[r] = *(const float*)(Kb + offr);
            }
            uint32_t offw = ((uint32_t)((hd >> 3) + ((kq >> 3) << 3)) * 1024
                             + (hd & 7) * 128 + ((kq * 4) & 31) * 4)
                            ^ ((uint32_t)(hd & 7) << 4);
            *(float4*)(Vb + offw) = make_float4(v[0], v[1], v[2], v[3]);
        }
    };

    // Prologue: stage K tiles 0 and 1
    {
        float4 kr[4];
#pragma unroll
        for (int i = 0; i < 4; i++) kr[i] = ((const float4*)kb)[tid + i * 256];
        stageK(kr, 0);
#pragma unroll
        for (int i = 0; i < 4; i++) kr[i] = ((const float4*)(kb + (size_t)64 * HD))[tid + i * 256];
        stageK(kr, 1);
    }

    if (tid == 0) { mbar_init(sb + AT_SBAR, 1); mbar_init(sb + AT_OBAR, 1); }
    fence_async();
    fence_before();
    __syncthreads();

    uint32_t tmem;
    asm volatile("ld.shared.b32 %0, [%1];" : "=r"(tmem) : "r"(sb + AT_TMEMP));
    const uint32_t SA_T = tmem;          // +0/64
    const uint32_t OA_T = tmem + 128;
    const uint32_t PA_T = tmem + 192;
    const uint32_t SB_T = tmem + 256;    // +0/64
    const uint32_t OB_T = tmem + 384;
    const uint32_t PB_T = tmem + 448;
    const uint32_t sbar = sb + AT_SBAR;
    const uint32_t obar = sb + AT_OBAR;
    const uint64_t qdA  = make_desc(sb + AT_Q);
    const uint64_t qdB  = make_desc(sb + AT_Q + 32768);
    const uint32_t wsub = (uint32_t)(wid & 3) << 21;

    // issue SA(0), SB(0) -> S-buf 0 of each tile; single commit
    if (wid == 0) {
        fence_after();
        if (elect_one()) {
            uint64_t kd = make_desc(sb + AT_K);
#pragma unroll
            for (int s = 0; s < 8; s++)
                mma_tf32_ss(SA_T, qdA + AOFF(s), kd + BOFF(s), IDESC_TF32, s > 0);
#pragma unroll
            for (int s = 0; s < 8; s++)
                mma_tf32_ss(SB_T, qdB + AOFF(s), kd + BOFF(s), IDESC_TF32, s > 0);
            tc_commit(sbar);
        }
    }

    // VT(0) from K buf 0 (writes fenced before O(0) issue at iter-0 sync)
    stageVT(0, 0);

    float rsumA = 0.0f, rsumB = 0.0f;

    for (int kt = 0; kt < SEQ / 64; kt++) {
        // 0. early LDG of K(kt+2)
        float4 kr[4];
        const bool do_stage = (kt + 2 < SEQ / 64);
        if (do_stage) {
            const float4* k4 = (const float4*)(kb + (size_t)(kt + 2) * 64 * HD);
#pragma unroll
            for (int i = 0; i < 4; i++) kr[i] = k4[tid + i * 256];
        }

        // 1. wait S(kt) for both tiles (flip kt+1, parity kt&1)
        mbar_wait(sbar, (uint32_t)(kt & 1));
        fence_after();

        // 2. issue SA(kt+1), SB(kt+1) immediately (other S bufs, K buf (kt+1)&1)
        if (kt < SEQ / 64 - 1 && wid == 0) {
            if (elect_one()) {
                uint64_t kd = make_desc(sb + AT_K + ((kt + 1) & 1) * 16384);
                uint32_t off = (uint32_t)(((kt + 1) & 1) * 64);
#pragma unroll
                for (int s = 0; s < 8; s++)
                    mma_tf32_ss(SA_T + off, qdA + AOFF(s), kd + BOFF(s), IDESC_TF32, s > 0);
#pragma unroll
                for (int s = 0; s < 8; s++)
                    mma_tf32_ss(SB_T + off, qdB + AOFF(s), kd + BOFF(s), IDESC_TF32, s > 0);
                tc_commit(sbar);
            }
        }

        // 3. wait O(kt-1) (frees PA/PB and VT buf (kt-1)&1)
        if (kt >= 1) mbar_wait(obar, (uint32_t)((kt + 1) & 1));

        // 4. softmax tile A: LDTM SA(kt) -> ex2 -> tf32 -> STTM PA
        {
            uint32_t v[32];
            ld32(v, SA_T + (uint32_t)((kt & 1) * 64 + half * 32));
            tc_wait_ld();
#pragma unroll
            for (int c = 0; c < 32; c++) {
                float e = ex2f(__uint_as_float(v[c]));
                rsumA += e;
                v[c] = __float_as_uint(cvt_tf32(e));
            }
            st32(PA_T + (uint32_t)(half * 32) + wsub, v);
        }
        // 5. softmax tile B
        {
            uint32_t v[32];
            ld32(v, SB_T + (uint32_t)((kt & 1) * 64 + half * 32));
            tc_wait_ld();
#pragma unroll
            for (int c = 0; c < 32; c++) {
                float e = ex2f(__uint_as_float(v[c]));
                rsumB += e;
                v[c] = __float_as_uint(cvt_tf32(e));
            }
            st32(PB_T + (uint32_t)(half * 32) + wsub, v);
        }
        tc_wait_st();

        // 6. stage K(kt+2) into buf kt&1 (K(kt) consumed: S(kt) waited,
        //    VT(kt) staged last iteration)
        if (do_stage) stageK(kr, kt & 1);
        // 7. stage VT(kt+1) from K buf (kt+1)&1 into VT buf (kt+1)&1
        if (kt + 1 < SEQ / 64) stageVT((kt + 1) & 1, (kt + 1) & 1);

        fence_async();
        fence_before();
        __syncthreads();

        // 8. issue OA(kt), OB(kt): TS-form, A = P (TMEM), B = VT buf kt&1
        if (wid == 0) {
            fence_after();
            if (elect_one()) {
                uint64_t vd = make_desc(sb + AT_VT + (kt & 1) * 16384);
                uint32_t en0 = (kt > 0);
#pragma unroll
                for (int s = 0; s < 8; s++)
                    mma_tf32_ts(OA_T, PA_T + (uint32_t)(s * 8), vd + BOFF(s),
                                IDESC_TF32, en0 || (s > 0));
#pragma unroll
                for (int s = 0; s < 8; s++)
                    mma_tf32_ts(OB_T, PB_T + (uint32_t)(s * 8), vd + BOFF(s),
                                IDESC_TF32, en0 || (s > 0));
                tc_commit(obar);
            }
        }
    }

    // final: O(63) = flip 64, parity 1
    mbar_wait(obar, 1u);
    fence_after();

    *(float*)(smem + AT_RS(half)     + row * 4) = rsumA;
    *(float*)(smem + AT_RS(2 + half) + row * 4) = rsumB;
    __syncthreads();

    const float invA = 1.0f / (*(float*)(smem + AT_RS(0) + row * 4) +
                               *(float*)(smem + AT_RS(1) + row * 4));
    const float invB = 1.0f / (*(float*)(smem + AT_RS(2) + row * 4) +
                               *(float*)(smem + AT_RS(3) + row * 4));

    {
        uint32_t orr[32];
        ld32(orr, OA_T + (uint32_t)(half * 32));
        tc_wait_ld();
        float* ob = out + ((size_t)blockIdx.z * SEQ + q0 + row) * DIM
                        + blockIdx.y * HD + half * 32;
#pragma unroll
        for (int j = 0; j < 32; j += 4)
            *(float4*)(ob + j) = make_float4(__uint_as_float(orr[j]) * invA,
                                             __uint_as_float(orr[j + 1]) * invA,
                                             __uint_as_float(orr[j + 2]) * invA,
                                             __uint_as_float(orr[j + 3]) * invA);
    }
    {
        uint32_t orr[32];
        ld32(orr, OB_T + (uint32_t)(half * 32));
        tc_wait_ld();
        float* ob = out + ((size_t)blockIdx.z * SEQ + q0 + 128 + row) * DIM
                        + blockIdx.y * HD + half * 32;
#pragma unroll
        for (int j = 0; j < 32; j += 4)
            *(float4*)(ob + j) = make_float4(__uint_as_float(orr[j]) * invB,
                                             __uint_as_float(orr[j + 1]) * invB,
                                             __uint_as_float(orr[j + 2]) * invB,
                                             __uint_as_float(orr[j + 3]) * invB);
    }

    fence_before();
    __syncthreads();
    if (tid == 0) { mbar_inval(sbar); mbar_inval(obar); }
    if (wid == 0) tc_dealloc(tmem, 512);

#else
    // -------- wmma fallback (R3 body, looped over 2 q-sub-tiles) --------
    extern __shared__ float smf[];
    float* Ks0    = smf;
    float* Ks1    = smf + 64 * LDS;
    float* Ps     = smf + 128 * LDS;
    float* rowinv = smf + 256 * LDS;

    const int tid  = threadIdx.x;
    const int warp = tid >> 5;
    const int lane = tid & 31;
    const int bh   = blockIdx.z * NH + blockIdx.y;

    for (int t = 0; t < 2; t++) {
        const int q0 = blockIdx.x * 256 + t * 128;
        const float* qb = g_q + (size_t)bh * SEQ * HD + (size_t)q0 * HD;
        const float* kb = g_k + (size_t)bh * SEQ * HD;
        const float scale = 0.04419417382415922f;

#pragma unroll
        for (int i = 0; i < 32; i++) {
            int idx = tid + i * 256;
            int r = idx >> 6, c = idx & 63;
            Ps[r * LDS + c] = wmma::__float_to_tf32(qb[idx] * scale);
        }
        __syncthreads();

        FragA qa[8];
#pragma unroll
        for (int kk = 0; kk < 8; kk++)
            wmma::load_matrix_sync(qa[kk], Ps + warp * 16 * LDS + kk * 8, LDS);

#pragma unroll
        for (int i = 0; i < 16; i++) {
            int idx = tid + i * 256;
            int r = idx >> 6, c = idx & 63;
            Ks0[r * LDS + c] = wmma::__float_to_tf32(kb[idx]);
        }
        __syncthreads();

        FragC oacc[4];
#pragma unroll
        for (int n = 0; n < 4; n++) wmma::fill_fragment(oacc[n], 0.0f);

        float rsum = 0.0f;
        float* Pw = Ps + warp * 16 * LDS;

        for (int kt = 0; kt < SEQ / 64; kt++) {
            float* cur = (kt & 1) ? Ks1 : Ks0;
            float* nxt = (kt & 1) ? Ks0 : Ks1;

            if (kt < SEQ / 64 - 1) {
                const float* kp = kb + (size_t)(kt + 1) * 64 * HD;
#pragma unroll
                for (int i = 0; i < 16; i++) {
                    int idx = tid + i * 256;
                    int r = idx >> 6, c = idx & 63;
                    nxt[r * LDS + c] = wmma::__float_to_tf32(kp[idx]);
                }
            }

            FragC sacc[4];
#pragma unroll
            for (int n = 0; n < 4; n++) wmma::fill_fragment(sacc[n], 0.0f);
#pragma unroll
            for (int kk = 0; kk < 8; kk++) {
#pragma unroll
                for (int n = 0; n < 4; n++) {
                    FragBc b;
                    wmma::load_matrix_sync(b, cur + n * 16 * LDS + kk * 8, LDS);
                    wmma::mma_sync(sacc[n], qa[kk], b, sacc[n]);
                }
            }

#pragma unroll
            for (int n = 0; n < 4; n++) {
#pragma unroll
                for (int e = 0; e < sacc[n].num_elements; e++)
                    sacc[n].x[e] = wmma::__float_to_tf32(__expf(sacc[n].x[e]));
                wmma::store_matrix_sync(Pw + n * 16, sacc[n], LDS, wmma::mem_row_major);
            }
            __syncwarp();

            {
                const float* pp = Pw + (lane >> 1) * LDS + (lane & 1) * 32;
                float part = 0.0f;
#pragma unroll
                for (int c = 0; c < 32; c++) part += pp[c];
                rsum += part;
            }

#pragma unroll
            for (int kk = 0; kk < 8; kk++) {
                FragA a;
                wmma::load_matrix_sync(a, Pw + kk * 8, LDS);
#pragma unroll
                for (int n = 0; n < 4; n++) {
                    FragBr b;
                    wmma::load_matrix_sync(b, cur + kk * 8 * LDS + n * 16, LDS);
                    wmma::mma_sync(oacc[n], a, b, oacc[n]);
                }
            }

            __syncthreads();
        }

        rsum += __shfl_xor_sync(0xffffffffu, rsum, 1);
        if ((lane & 1) == 0) rowinv[warp * 16 + (lane >> 1)] = 1.0f / rsum;

#pragma unroll
        for (int n = 0; n < 4; n++)
            wmma::store_matrix_sync(Pw + n * 16, oacc[n], LDS, wmma::mem_row_major);
        __syncthreads();

        float* ob = out + ((size_t)blockIdx.z * SEQ + q0) * DIM + blockIdx.y * HD;
#pragma unroll
        for (int i = 0; i < 32; i++) {
            int idx = tid + i * 256;
            int r = idx >> 6, c = idx & 63;
            ob[(size_t)r * DIM + c] = Ps[r * LDS + c] * rowinv[r];
        }
        __syncthreads();
    }
#endif
}

// ---------------------------------------------------------------------------
extern "C" void kernel_launch(void* const* d_in, const int* in_sizes, int n_in,
                              void* d_out, int out_size)
{
    const float* x  = (const float*)d_in[0];
    const float* Wq = (const float*)d_in[1];
    const float* bq = (const float*)d_in[2];
    const float* Wk = (const float*)d_in[3];
    const float* bk = (const float*)d_in[4];
    float* out = (float*)d_out;

    cudaFuncSetAttribute(proj_kernel, cudaFuncAttributeMaxDynamicSharedMemorySize, PJ_TOTAL);
    dim3 pg((BATCH * SEQ) / 128, DIM / 64, 2);
    proj_kernel<<<pg, 256, PJ_TOTAL>>>(x, Wq, bq, Wk, bk);

    cudaFuncSetAttribute(attn_kernel, cudaFuncAttributeMaxDynamicSharedMemorySize, ATTN_TOTAL);
    dim3 ag(SEQ / 256, NH, BATCH);
    attn_kernel<<<ag, 256, ATTN_TOTAL>>>(out);
}

// round 14
// speedup vs baseline: 5.9030x; 1.0176x over previous
#include <cuda_runtime.h>
#include <cuda_bf16.h>
#include <mma.h>
#include <cstdint>

using namespace nvcuda;

#define BATCH 2
#define SEQ   4096
#define DIM   512
#define NH    8
#define HD    64
#define LDS   68
#define LDSB  36

#if defined(__CUDA_ARCH__) && defined(__CUDA_ARCH_HAS_FEATURE__)
#if __CUDA_ARCH_HAS_FEATURE__(SM103_ALL)
#define TC_OK 1
#endif
#endif
#ifndef TC_OK
#define TC_OK 0
#endif

__device__ float g_q[(size_t)BATCH * NH * SEQ * HD];
__device__ float g_k[(size_t)BATCH * NH * SEQ * HD];

using FragA  = wmma::fragment<wmma::matrix_a, 16, 16, 8, wmma::precision::tf32, wmma::row_major>;
using FragBc = wmma::fragment<wmma::matrix_b, 16, 16, 8, wmma::precision::tf32, wmma::col_major>;
using FragBr = wmma::fragment<wmma::matrix_b, 16, 16, 8, wmma::precision::tf32, wmma::row_major>;
using FragC  = wmma::fragment<wmma::accumulator, 16, 16, 8, float>;

// ===========================================================================
// helpers
// ===========================================================================
__device__ __forceinline__ uint32_t smem_u32(const void* p) {
    uint32_t a;
    asm("{ .reg .u64 t; cvta.to.shared.u64 t, %1; cvt.u32.u64 %0, t; }" : "=r"(a) : "l"(p));
    return a;
}
__device__ __forceinline__ float cvt_tf32(float x) {
    float r; asm("cvt.rna.tf32.f32 %0, %1;" : "=f"(r) : "f"(x)); return r;
}
__device__ __forceinline__ float ex2f(float x) {
    float r; asm("ex2.approx.f32 %0, %1;" : "=f"(r) : "f"(x)); return r;
}

#if TC_OK
__device__ __forceinline__ uint32_t elect_one() {
    uint32_t p;
    asm volatile("{\n .reg .pred p;\n elect.sync _|p, 0xFFFFFFFF;\n selp.b32 %0, 1, 0, p;\n}" : "=r"(p));
    return p;
}
__device__ __forceinline__ void mbar_init(uint32_t mbar, uint32_t cnt) {
    asm volatile("mbarrier.init.shared.b64 [%0], %1;" :: "r"(mbar), "r"(cnt) : "memory");
}
__device__ __forceinline__ void mbar_inval(uint32_t mbar) {
    asm volatile("mbarrier.inval.shared.b64 [%0];" :: "r"(mbar) : "memory");
}
__device__ __forceinline__ void mbar_wait(uint32_t mbar, uint32_t parity) {
    asm volatile(
        "{\n .reg .pred P;\n"
        "W%=: mbarrier.try_wait.parity.acquire.cta.shared::cta.b64 P, [%0], %1, 0x989680;\n"
        " @P bra D%=;\n bra W%=;\n D%=:\n}"
        :: "r"(mbar), "r"(parity) : "memory");
}
__device__ __forceinline__ void tc_alloc(uint32_t smem_dst, uint32_t ncols) {
    asm volatile("tcgen05.alloc.cta_group::1.sync.aligned.shared::cta.b32 [%0], %1;"
                 :: "r"(smem_dst), "r"(ncols) : "memory");
}
__device__ __forceinline__ void tc_dealloc(uint32_t tmem, uint32_t ncols) {
    asm volatile("tcgen05.dealloc.cta_group::1.sync.aligned.b32 %0, %1;" :: "r"(tmem), "r"(ncols));
}
__device__ __forceinline__ void tc_commit(uint32_t mbar) {
    asm volatile("tcgen05.commit.cta_group::1.mbarrier::arrive::one.shared::cluster.b64 [%0];"
                 :: "r"(mbar) : "memory");
}
__device__ __forceinline__ void fence_before() { asm volatile("tcgen05.fence::before_thread_sync;" ::: "memory"); }
__device__ __forceinline__ void fence_after()  { asm volatile("tcgen05.fence::after_thread_sync;" ::: "memory"); }
__device__ __forceinline__ void fence_async()  { asm volatile("fence.proxy.async.shared::cta;" ::: "memory"); }
__device__ __forceinline__ void tc_wait_ld()   { asm volatile("tcgen05.wait::ld.sync.aligned;" ::: "memory"); }
__device__ __forceinline__ void tc_wait_st()   { asm volatile("tcgen05.wait::st.sync.aligned;" ::: "memory"); }

__device__ __forceinline__ void mma_tf32_ss(uint32_t d, uint64_t a, uint64_t b,
                                            uint32_t idesc, uint32_t en) {
    asm volatile(
        "{\n .reg .pred p;\n setp.ne.u32 p, %5, 0;\n"
        " tcgen05.mma.cta_group::1.kind::tf32 [%0], %1, %2, %3, {%4, %4, %4, %4}, p;\n}"
        :: "r"(d), "l"(a), "l"(b), "r"(idesc), "r"(0u), "r"(en) : "memory");
}
__device__ __forceinline__ void mma_tf32_ts(uint32_t d, uint32_t a, uint64_t b,
                                            uint32_t idesc, uint32_t en) {
    asm volatile(
        "{\n .reg .pred p;\n setp.ne.u32 p, %5, 0;\n"
        " tcgen05.mma.cta_group::1.kind::tf32 [%0], [%1], %2, %3, {%4, %4, %4, %4}, p;\n}"
        :: "r"(d), "r"(a), "l"(b), "r"(idesc), "r"(0u), "r"(en) : "memory");
}

__device__ __forceinline__ void ld32(uint32_t* r, uint32_t addr) {
    asm volatile(
        "tcgen05.ld.sync.aligned.32x32b.x32.b32 "
        "{%0,%1,%2,%3,%4,%5,%6,%7,%8,%9,%10,%11,%12,%13,%14,%15,"
        "%16,%17,%18,%19,%20,%21,%22,%23,%24,%25,%26,%27,%28,%29,%30,%31}, [%32];"
        : "=r"(r[0]),"=r"(r[1]),"=r"(r[2]),"=r"(r[3]),"=r"(r[4]),"=r"(r[5]),"=r"(r[6]),"=r"(r[7]),
          "=r"(r[8]),"=r"(r[9]),"=r"(r[10]),"=r"(r[11]),"=r"(r[12]),"=r"(r[13]),"=r"(r[14]),"=r"(r[15]),
          "=r"(r[16]),"=r"(r[17]),"=r"(r[18]),"=r"(r[19]),"=r"(r[20]),"=r"(r[21]),"=r"(r[22]),"=r"(r[23]),
          "=r"(r[24]),"=r"(r[25]),"=r"(r[26]),"=r"(r[27]),"=r"(r[28]),"=r"(r[29]),"=r"(r[30]),"=r"(r[31])
        : "r"(addr));
}
__device__ __forceinline__ void st32(uint32_t addr, const uint32_t* r) {
    asm volatile(
        "tcgen05.st.sync.aligned.32x32b.x32.b32 [%0], "
        "{%1,%2,%3,%4,%5,%6,%7,%8,%9,%10,%11,%12,%13,%14,%15,%16,"
        "%17,%18,%19,%20,%21,%22,%23,%24,%25,%26,%27,%28,%29,%30,%31,%32};"
        :: "r"(addr),
           "r"(r[0]),"r"(r[1]),"r"(r[2]),"r"(r[3]),"r"(r[4]),"r"(r[5]),"r"(r[6]),"r"(r[7]),
           "r"(r[8]),"r"(r[9]),"r"(r[10]),"r"(r[11]),"r"(r[12]),"r"(r[13]),"r"(r[14]),"r"(r[15]),
           "r"(r[16]),"r"(r[17]),"r"(r[18]),"r"(r[19]),"r"(r[20]),"r"(r[21]),"r"(r[22]),"r"(r[23]),
           "r"(r[24]),"r"(r[25]),"r"(r[26]),"r"(r[27]),"r"(r[28]),"r"(r[29]),"r"(r[30]),"r"(r[31])
        : "memory");
}

// K-major SW128 descriptor: SBO=64, LBO=1, version=1
__device__ __forceinline__ uint64_t make_desc(uint32_t addr) {
    const uint64_t base = (uint64_t(2) << 61) | (uint64_t(1) << 46) |
                          (uint64_t(64) << 32) | (uint64_t(1) << 16);
    return base | ((uint64_t)(addr >> 4) & 0x3FFF);
}
#endif  // TC_OK

#define IDESC_TF32 ((1u<<4) | (2u<<7) | (2u<<10) | (8u<<17) | (8u<<24))  // F32 acc, tf32 a/b, N=64, M=128

#define AOFF(s) ((s) < 4 ? (uint64_t)((s) * 2) : (uint64_t)(1024 + ((s) - 4) * 2))
#define BOFF(s) ((s) < 4 ? (uint64_t)((s) * 2) : (uint64_t)(512  + ((s) - 4) * 2))

// ===========================================================================
// Projection (unchanged from R6): grid (64, 8, 2), 256 thr.
// ===========================================================================
#define PJ_TMEMP   0
#define PJ_BAR(i)  (8 + (i) * 8)
#define PJ_X       1024
#define PJ_XSTR    16384
#define PJ_W       (1024 + 3 * 16384)
#define PJ_WSTR    8192
#define PJ_TOTAL   74880

__global__ void __launch_bounds__(256, 2)
proj_kernel(const float* __restrict__ x,
            const float* __restrict__ Wq, const float* __restrict__ bq,
            const float* __restrict__ Wk, const float* __restrict__ bk)
{
    const int which = blockIdx.z;
    const float* W    = which ? Wk : Wq;
    const float* bias = which ? bk : bq;

#if TC_OK
    extern __shared__ __align__(1024) char smem[];
    const uint32_t sb = smem_u32(smem);

    const int tid  = threadIdx.x;
    const int wid  = tid >> 5;
    const int lane = tid & 31;
    const int half = wid >> 2;
    const int row  = (wid & 3) * 32 + lane;
    const int m0   = blockIdx.x * 128;
    const int e0   = blockIdx.y * 64;

    if (wid == 0) tc_alloc(sb + PJ_TMEMP, 64);
    if (tid == 0) {
        mbar_init(sb + PJ_BAR(0), 1);
        mbar_init(sb + PJ_BAR(1), 1);
        mbar_init(sb + PJ_BAR(2), 1);
    }

    auto stageX = [&](int k0, int b) {
#pragma unroll
        for (int i = 0; i < 4; i++) {
            int idx4 = tid + i * 256;
            int r = idx4 >> 3, c4 = (idx4 & 7) * 4;
            float4 v = *(const float4*)(x + (size_t)(m0 + r) * DIM + k0 + c4);
            uint32_t off = ((uint32_t)(r >> 3) * 1024 + (r & 7) * 128 + c4 * 4)
                           ^ ((uint32_t)(r & 7) << 4);
            *(float4*)(smem + PJ_X + b * PJ_XSTR + off) = make_float4(
                cvt_tf32(v.x), cvt_tf32(v.y), cvt_tf32(v.z), cvt_tf32(v.w));
        }
    };
    auto stageW = [&](int k0, int b) {
#pragma unroll
        for (int i = 0; i < 2; i++) {
            int idx4 = tid + i * 256;
            int r = idx4 >> 3, c4 = (idx4 & 7) * 4;
            float4 v = *(const float4*)(W + (size_t)(e0 + r) * DIM + k0 + c4);
            uint32_t off = ((uint32_t)(r >> 3) * 1024 + (r & 7) * 128 + c4 * 4)
                           ^ ((uint32_t)(r & 7) << 4);
            *(float4*)(smem + PJ_W + b * PJ_WSTR + off) = make_float4(
                cvt_tf32(v.x), cvt_tf32(v.y), cvt_tf32(v.z), cvt_tf32(v.w));
        }
    };

    stageX(0, 0);  stageW(0, 0);
    stageX(32, 1); stageW(32, 1);
    fence_async();
    fence_before();
    __syncthreads();

    uint32_t tmem;
    asm volatile("ld.shared.b32 %0, [%1];" : "=r"(tmem) : "r"(sb + PJ_TMEMP));

    int ph0 = 0, ph1 = 0, ph2 = 0;
#pragma unroll
    for (int c = 0; c < 16; c++) {
        if (wid == 0) {
            fence_after();
            if (elect_one()) {
                uint64_t ad = make_desc(sb + PJ_X + (c % 3) * PJ_XSTR);
                uint64_t bd = make_desc(sb + PJ_W + (c % 3) * PJ_WSTR);
#pragma unroll
                for (int s = 0; s < 4; s++)
                    mma_tf32_ss(tmem, ad + s * 2, bd + s * 2, IDESC_TF32, (c > 0) || (s > 0));
                tc_commit(sb + PJ_BAR(c % 3));
            }
        }
        if (c + 2 < 16) {
            const int b2 = (c + 2) % 3;
            if (c + 2 >= 3) {
                if (b2 == 0)      { mbar_wait(sb + PJ_BAR(0), (uint32_t)ph0); ph0 ^= 1; }
                else if (b2 == 1) { mbar_wait(sb + PJ_BAR(1), (uint32_t)ph1); ph1 ^= 1; }
                else              { mbar_wait(sb + PJ_BAR(2), (uint32_t)ph2); ph2 ^= 1; }
            }
            stageX((c + 2) * 32, b2);
            stageW((c + 2) * 32, b2);
            fence_async();
            fence_before();
            __syncthreads();
        }
    }

    mbar_wait(sb + PJ_BAR(0), (uint32_t)ph0);
    fence_after();

    uint32_t orr[32];
    ld32(orr, tmem + (uint32_t)(half * 32));
    tc_wait_ld();

    const int m = m0 + row;
    const int b = m >> 12;
    const int nn = m & (SEQ - 1);
    float* dst = (which ? g_k : g_q)
               + (((size_t)b * NH + blockIdx.y) * SEQ + nn) * HD + half * 32;
    const float* bp = bias + e0 + half * 32;
#pragma unroll
    for (int j = 0; j < 32; j += 4)
        *(float4*)(dst + j) = make_float4(__uint_as_float(orr[j])     + bp[j],
                                          __uint_as_float(orr[j + 1]) + bp[j + 1],
                                          __uint_as_float(orr[j + 2]) + bp[j + 2],
                                          __uint_as_float(orr[j + 3]) + bp[j + 3]);

    fence_before();
    __syncthreads();
    if (tid == 0) { mbar_inval(sb + PJ_BAR(0)); mbar_inval(sb + PJ_BAR(1)); mbar_inval(sb + PJ_BAR(2)); }
    if (wid == 0) tc_dealloc(tmem, 64);

#else
    // -------- wmma fallback --------
    extern __shared__ float smf[];
    float* As = smf;
    float* Bs = smf + 128 * LDSB;

    const int tid  = threadIdx.x;
    const int warp = tid >> 5;
    const int m0   = blockIdx.x * 128;
    const int e0   = blockIdx.y * 64;

    FragC acc[4];
#pragma unroll
    for (int n = 0; n < 4; n++) wmma::fill_fragment(acc[n], 0.0f);

    float xr[16], wr[8];
#pragma unroll
    for (int i = 0; i < 16; i++) {
        int idx = tid + i * 256, r = idx >> 5, c = idx & 31;
        xr[i] = x[(size_t)(m0 + r) * DIM + c];
    }
#pragma unroll
    for (int i = 0; i < 8; i++) {
        int idx = tid + i * 256, r = idx >> 5, c = idx & 31;
        wr[i] = W[(size_t)(e0 + r) * DIM + c];
    }

    for (int kt = 0; kt < 16; kt++) {
#pragma unroll
        for (int i = 0; i < 16; i++) {
            int idx = tid + i * 256, r = idx >> 5, c = idx & 31;
            As[r * LDSB + c] = wmma::__float_to_tf32(xr[i]);
        }
#pragma unroll
        for (int i = 0; i < 8; i++) {
            int idx = tid + i * 256, r = idx >> 5, c = idx & 31;
            Bs[r * LDSB + c] = wmma::__float_to_tf32(wr[i]);
        }
        __syncthreads();

        if (kt < 15) {
            const int k0 = (kt + 1) * 32;
#pragma unroll
            for (int i = 0; i < 16; i++) {
                int idx = tid + i * 256, r = idx >> 5, c = idx & 31;
                xr[i] = x[(size_t)(m0 + r) * DIM + k0 + c];
            }
#pragma unroll
            for (int i = 0; i < 8; i++) {
                int idx = tid + i * 256, r = idx >> 5, c = idx & 31;
                wr[i] = W[(size_t)(e0 + r) * DIM + k0 + c];
            }
        }

#pragma unroll
        for (int kk = 0; kk < 4; kk++) {
            FragA a;
            wmma::load_matrix_sync(a, As + warp * 16 * LDSB + kk * 8, LDSB);
#pragma unroll
            for (int n = 0; n < 4; n++) {
                FragBc b;
                wmma::load_matrix_sync(b, Bs + n * 16 * LDSB + kk * 8, LDSB);
                wmma::mma_sync(acc[n], a, b, acc[n]);
            }
        }
        __syncthreads();
    }

#pragma unroll
    for (int n = 0; n < 4; n++)
        wmma::store_matrix_sync(smf + warp * 16 * LDS + n * 16, acc[n], LDS, wmma::mem_row_major);
    __syncthreads();

    float* dst = which ? g_k : g_q;
    const int h = blockIdx.y;
#pragma unroll
    for (int i = 0; i < 32; i++) {
        int idx = tid + i * 256;
        int r = idx >> 6, c = idx & 63;
        int m = m0 + r;
        int b = m >> 12;
        int nn = m & (SEQ - 1);
        dst[(((size_t)b * NH + h) * SEQ + nn) * HD + c] = smf[r * LDS + c] + bias[e0 + c];
    }
#endif
}

// ===========================================================================
// Attention: TWO q-tiles per CTA (R13 structure), with the softmax pipelined
// across the tiles: LDTM(B) issued before ex2(A) so the TMEM-read port
// overlaps the MUFU work. Grid (SEQ/256=16, NH, BATCH), 256 threads.
//   TMEM (512): SA0@0 SA1@64 OA@128 PA@192 | SB0@256 SB1@320 OB@384 PB@448.
// ===========================================================================
#define AT_TMEMP  0
#define AT_SBAR   8
#define AT_OBAR   16
#define AT_RS(i)  (32 + (i) * 512)
#define AT_Q      3072
#define AT_K      68608                    /* 2 x 16384 */
#define AT_VT     101376                   /* 2 x 16384 */
#define ATTN_TOTAL 134144

__global__ void __launch_bounds__(256, 1)
attn_kernel(float* __restrict__ out)
{
#if TC_OK
    extern __shared__ __align__(1024) char smem[];
    const uint32_t sb = smem_u32(smem);

    const int tid  = threadIdx.x;
    const int wid  = tid >> 5;
    const int lane = tid & 31;
    const int half = wid >> 2;
    const int row  = (wid & 3) * 32 + lane;

    const int bh = blockIdx.z * NH + blockIdx.y;
    const int q0 = blockIdx.x * 256;
    const float* qb = g_q + (size_t)bh * SEQ * HD + (size_t)q0 * HD;
    const float* kb = g_k + (size_t)bh * SEQ * HD;
    const float scale = 0.063758746f;   // 512^-0.5 * log2(e)

    if (wid == 0) tc_alloc(sb + AT_TMEMP, 512);

    // Stage Q tiles A and B
#pragma unroll
    for (int t = 0; t < 2; t++) {
        const float4* q4 = (const float4*)(qb + (size_t)t * 128 * HD);
        char* Qb = smem + AT_Q + t * 32768;
#pragma unroll
        for (int i = 0; i < 8; i++) {
            int idx4 = tid + i * 256;
            int eb = idx4 * 4;
            int r = eb >> 6, c = eb & 63;
            float4 v = q4[idx4];
            uint32_t atom = (uint32_t)((r >> 3) + ((c >> 5) << 4));
            uint32_t off = (atom * 1024 + (r & 7) * 128 + (c & 31) * 4)
                           ^ ((uint32_t)(r & 7) << 4);
            *(float4*)(Qb + off) = make_float4(
                cvt_tf32(v.x * scale), cvt_tf32(v.y * scale),
                cvt_tf32(v.z * scale), cvt_tf32(v.w * scale));
        }
    }

    // Precompute loop-invariant staging offsets (pure functions of tid)
    uint32_t kOff[4];
#pragma unroll
    for (int i = 0; i < 4; i++) {
        int idx4 = tid + i * 256;
        int eb = idx4 * 4;
        int key = eb >> 6, h0 = eb & 63;
        kOff[i] = (((uint32_t)((key >> 3) + ((h0 >> 5) << 3)) * 1024
                    + (key & 7) * 128 + (h0 & 31) * 4) ^ ((uint32_t)(key & 7) << 4));
    }
    uint32_t vtW[4];
#pragma unroll
    for (int j = 0; j < 4; j++) {
        int idx = tid + j * 256;
        int hd = idx & 63, kq = idx >> 6;
        vtW[j] = (((uint32_t)((hd >> 3) + ((kq >> 3) << 3)) * 1024
                   + (hd & 7) * 128 + ((kq * 4) & 31) * 4) ^ ((uint32_t)(hd & 7) << 4));
    }

    auto stageK = [&](const float4* kr, int b) {
        char* Kb = smem + AT_K + b * 16384;
#pragma unroll
        for (int i = 0; i < 4; i++) {
            float4 v = kr[i];
            *(float4*)(Kb + kOff[i]) = make_float4(
                cvt_tf32(v.x), cvt_tf32(v.y), cvt_tf32(v.z), cvt_tf32(v.w));
        }
    };

    auto stageVT = [&](int kbuf, int vbuf) {
        char* Kb = smem + AT_K  + kbuf * 16384;
        char* Vb = smem + AT_VT + vbuf * 16384;
#pragma unroll
        for (int j = 0; j < 4; j++) {
            int idx = tid + j * 256;
            int hd = idx & 63, kq = idx >> 6;
            float v[4];
#pragma unroll
            for (int r = 0; r < 4; r++) {
                int key = kq * 4 + r;
                uint32_t offr = ((uint32_t)((key >> 3) + ((hd >> 5) << 3)) * 1024
                                 + (key & 7) * 128 + (hd & 31) * 4)
                                ^ ((uint32_t)(key & 7) << 4);
                v[r] = *(const float*)(Kb + offr);
            }
            *(float4*)(Vb + vtW[j]) = make_float4(v[0], v[1], v[2], v[3]);
        }
    };

    // Prologue: stage K tiles 0 and 1
    {
        float4 kr[4];
#pragma unroll
        for (int i = 0; i < 4; i++) kr[i] = ((const float4*)kb)[tid + i * 256];
        stageK(kr, 0);
#pragma unroll
        for (int i = 0; i < 4; i++) kr[i] = ((const float4*)(kb + (size_t)64 * HD))[tid + i * 256];
        stageK(kr, 1);
    }

    if (tid == 0) { mbar_init(sb + AT_SBAR, 1); mbar_init(sb + AT_OBAR, 1); }
    fence_async();
    fence_before();
    __syncthreads();

    uint32_t tmem;
    asm volatile("ld.shared.b32 %0, [%1];" : "=r"(tmem) : "r"(sb + AT_TMEMP));
    const uint32_t SA_T = tmem;
    const uint32_t OA_T = tmem + 128;
    const uint32_t PA_T = tmem + 192;
    const uint32_t SB_T = tmem + 256;
    const uint32_t OB_T = tmem + 384;
    const uint32_t PB_T = tmem + 448;
    const uint32_t sbar = sb + AT_SBAR;
    const uint32_t obar = sb + AT_OBAR;
    const uint64_t qdA  = make_desc(sb + AT_Q);
    const uint64_t qdB  = make_desc(sb + AT_Q + 32768);
    const uint32_t wsub = (uint32_t)(wid & 3) << 21;

    // issue SA(0), SB(0); single commit
    if (wid == 0) {
        fence_after();
        if (elect_one()) {
            uint64_t kd = make_desc(sb + AT_K);
#pragma unroll
            for (int s = 0; s < 8; s++)
                mma_tf32_ss(SA_T, qdA + AOFF(s), kd + BOFF(s), IDESC_TF32, s > 0);
#pragma unroll
            for (int s = 0; s < 8; s++)
                mma_tf32_ss(SB_T, qdB + AOFF(s), kd + BOFF(s), IDESC_TF32, s > 0);
            tc_commit(sbar);
        }
    }

    stageVT(0, 0);

    float rsumA = 0.0f, rsumB = 0.0f;

    for (int kt = 0; kt < SEQ / 64; kt++) {
        // 0. early LDG of K(kt+2)
        float4 kr[4];
        const bool do_stage = (kt + 2 < SEQ / 64);
        if (do_stage) {
            const float4* k4 = (const float4*)(kb + (size_t)(kt + 2) * 64 * HD);
#pragma unroll
            for (int i = 0; i < 4; i++) kr[i] = k4[tid + i * 256];
        }

        // 1. wait S(kt) for both tiles
        mbar_wait(sbar, (uint32_t)(kt & 1));
        fence_after();

        // 2. issue SA(kt+1), SB(kt+1) immediately
        if (kt < SEQ / 64 - 1 && wid == 0) {
            if (elect_one()) {
                uint64_t kd = make_desc(sb + AT_K + ((kt + 1) & 1) * 16384);
                uint32_t off = (uint32_t)(((kt + 1) & 1) * 64);
#pragma unroll
                for (int s = 0; s < 8; s++)
                    mma_tf32_ss(SA_T + off, qdA + AOFF(s), kd + BOFF(s), IDESC_TF32, s > 0);
#pragma unroll
                for (int s = 0; s < 8; s++)
                    mma_tf32_ss(SB_T + off, qdB + AOFF(s), kd + BOFF(s), IDESC_TF32, s > 0);
                tc_commit(sbar);
            }
        }

        // 3. wait O(kt-1) (frees PA/PB and VT buf (kt-1)&1)
        if (kt >= 1) mbar_wait(obar, (uint32_t)((kt + 1) & 1));

        // 4. PIPELINED softmax: LDTM(B) issued before ex2(A) so the TMEM
        //    read port transfer of B overlaps the MUFU work on A.
        {
            uint32_t va[32], vb[32];
            ld32(va, SA_T + (uint32_t)((kt & 1) * 64 + half * 32));
            tc_wait_ld();                       // only A outstanding
            ld32(vb, SB_T + (uint32_t)((kt & 1) * 64 + half * 32));  // async

            // ex2(A) overlaps B's port transfer
#pragma unroll
            for (int c = 0; c < 32; c++) {
                float e = ex2f(__uint_as_float(va[c]));
                rsumA += e;
                va[c] = __float_as_uint(cvt_tf32(e));
            }
            st32(PA_T + (uint32_t)(half * 32) + wsub, va);

            tc_wait_ld();                       // B done
#pragma unroll
            for (int c = 0; c < 32; c++) {
                float e = ex2f(__uint_as_float(vb[c]));
                rsumB += e;
                vb[c] = __float_as_uint(cvt_tf32(e));
            }
            st32(PB_T + (uint32_t)(half * 32) + wsub, vb);
            tc_wait_st();
        }

        // 5. stage K(kt+2) into buf kt&1
        if (do_stage) stageK(kr, kt & 1);
        // 6. stage VT(kt+1) from K buf (kt+1)&1 into VT buf (kt+1)&1
        if (kt + 1 < SEQ / 64) stageVT((kt + 1) & 1, (kt + 1) & 1);

        fence_async();
        fence_before();
        __syncthreads();

        // 7. issue OA(kt), OB(kt)
        if (wid == 0) {
            fence_after();
            if (elect_one()) {
                uint64_t vd = make_desc(sb + AT_VT + (kt & 1) * 16384);
                uint32_t en0 = (kt > 0);
#pragma unroll
                for (int s = 0; s < 8; s++)
                    mma_tf32_ts(OA_T, PA_T + (uint32_t)(s * 8), vd + BOFF(s),
                                IDESC_TF32, en0 || (s > 0));
#pragma unroll
                for (int s = 0; s < 8; s++)
                    mma_tf32_ts(OB_T, PB_T + (uint32_t)(s * 8), vd + BOFF(s),
                                IDESC_TF32, en0 || (s > 0));
                tc_commit(obar);
            }
        }
    }

    // final: O(63) = flip 64, parity 1
    mbar_wait(obar, 1u);
    fence_after();

    *(float*)(smem + AT_RS(half)     + row * 4) = rsumA;
    *(float*)(smem + AT_RS(2 + half) + row * 4) = rsumB;
    __syncthreads();

    const float invA = 1.0f / (*(float*)(smem + AT_RS(0) + row * 4) +
                               *(float*)(smem + AT_RS(1) + row * 4));
    const float invB = 1.0f / (*(float*)(smem + AT_RS(2) + row * 4) +
                               *(float*)(smem + AT_RS(3) + row * 4));

    {
        uint32_t orr[32];
        ld32(orr, OA_T + (uint32_t)(half * 32));
        tc_wait_ld();
        float* ob = out + ((size_t)blockIdx.z * SEQ + q0 + row) * DIM
                        + blockIdx.y * HD + half * 32;
#pragma unroll
        for (int j = 0; j < 32; j += 4)
            *(float4*)(ob + j) = make_float4(__uint_as_float(orr[j]) * invA,
                                             __uint_as_float(orr[j + 1]) * invA,
                                             __uint_as_float(orr[j + 2]) * invA,
                                             __uint_as_float(orr[j + 3]) * invA);
    }
    {
        uint32_t orr[32];
        ld32(orr, OB_T + (uint32_t)(half * 32));
        tc_wait_ld();
        float* ob = out + ((size_t)blockIdx.z * SEQ + q0 + 128 + row) * DIM
                        + blockIdx.y * HD + half * 32;
#pragma unroll
        for (int j = 0; j < 32; j += 4)
            *(float4*)(ob + j) = make_float4(__uint_as_float(orr[j]) * invB,
                                             __uint_as_float(orr[j + 1]) * invB,
                                             __uint_as_float(orr[j + 2]) * invB,
                                             __uint_as_float(orr[j + 3]) * invB);
    }

    fence_before();
    __syncthreads();
    if (tid == 0) { mbar_inval(sbar); mbar_inval(obar); }
    if (wid == 0) tc_dealloc(tmem, 512);

#else
    // -------- wmma fallback (R3 body, looped over 2 q-sub-tiles) --------
    extern __shared__ float smf[];
    float* Ks0    = smf;
    float* Ks1    = smf + 64 * LDS;
    float* Ps     = smf + 128 * LDS;
    float* rowinv = smf + 256 * LDS;

    const int tid  = threadIdx.x;
    const int warp = tid >> 5;
    const int lane = tid & 31;
    const int bh   = blockIdx.z * NH + blockIdx.y;

    for (int t = 0; t < 2; t++) {
        const int q0 = blockIdx.x * 256 + t * 128;
        const float* qb = g_q + (size_t)bh * SEQ * HD + (size_t)q0 * HD;
        const float* kb = g_k + (size_t)bh * SEQ * HD;
        const float scale = 0.04419417382415922f;

#pragma unroll
        for (int i = 0; i < 32; i++) {
            int idx = tid + i * 256;
            int r = idx >> 6, c = idx & 63;
            Ps[r * LDS + c] = wmma::__float_to_tf32(qb[idx] * scale);
        }
        __syncthreads();

        FragA qa[8];
#pragma unroll
        for (int kk = 0; kk < 8; kk++)
            wmma::load_matrix_sync(qa[kk], Ps + warp * 16 * LDS + kk * 8, LDS);

#pragma unroll
        for (int i = 0; i < 16; i++) {
            int idx = tid + i * 256;
            int r = idx >> 6, c = idx & 63;
            Ks0[r * LDS + c] = wmma::__float_to_tf32(kb[idx]);
        }
        __syncthreads();

        FragC oacc[4];
#pragma unroll
        for (int n = 0; n < 4; n++) wmma::fill_fragment(oacc[n], 0.0f);

        float rsum = 0.0f;
        float* Pw = Ps + warp * 16 * LDS;

        for (int kt = 0; kt < SEQ / 64; kt++) {
            float* cur = (kt & 1) ? Ks1 : Ks0;
            float* nxt = (kt & 1) ? Ks0 : Ks1;

            if (kt < SEQ / 64 - 1) {
                const float* kp = kb + (size_t)(kt + 1) * 64 * HD;
#pragma unroll
                for (int i = 0; i < 16; i++) {
                    int idx = tid + i * 256;
                    int r = idx >> 6, c = idx & 63;
                    nxt[r * LDS + c] = wmma::__float_to_tf32(kp[idx]);
                }
            }

            FragC sacc[4];
#pragma unroll
            for (int n = 0; n < 4; n++) wmma::fill_fragment(sacc[n], 0.0f);
#pragma unroll
            for (int kk = 0; kk < 8; kk++) {
#pragma unroll
                for (int n = 0; n < 4; n++) {
                    FragBc b;
                    wmma::load_matrix_sync(b, cur + n * 16 * LDS + kk * 8, LDS);
                    wmma::mma_sync(sacc[n], qa[kk], b, sacc[n]);
                }
            }

#pragma unroll
            for (int n = 0; n < 4; n++) {
#pragma unroll
                for (int e = 0; e < sacc[n].num_elements; e++)
                    sacc[n].x[e] = wmma::__float_to_tf32(__expf(sacc[n].x[e]));
                wmma::store_matrix_sync(Pw + n * 16, sacc[n], LDS, wmma::mem_row_major);
            }
            __syncwarp();

            {
                const float* pp = Pw + (lane >> 1) * LDS + (lane & 1) * 32;
                float part = 0.0f;
#pragma unroll
                for (int c = 0; c < 32; c++) part += pp[c];
                rsum += part;
            }

#pragma unroll
            for (int kk = 0; kk < 8; kk++) {
                FragA a;
                wmma::load_matrix_sync(a, Pw + kk * 8, LDS);
#pragma unroll
                for (int n = 0; n < 4; n++) {
                    FragBr b;
                    wmma::load_matrix_sync(b, cur + kk * 8 * LDS + n * 16, LDS);
                    wmma::mma_sync(oacc[n], a, b, oacc[n]);
                }
            }

            __syncthreads();
        }

        rsum += __shfl_xor_sync(0xffffffffu, rsum, 1);
        if ((lane & 1) == 0) rowinv[warp * 16 + (lane >> 1)] = 1.0f / rsum;

#pragma unroll
        for (int n = 0; n < 4; n++)
            wmma::store_matrix_sync(Pw + n * 16, oacc[n], LDS, wmma::mem_row_major);
        __syncthreads();

        float* ob = out + ((size_t)blockIdx.z * SEQ + q0) * DIM + blockIdx.y * HD;
#pragma unroll
        for (int i = 0; i < 32; i++) {
            int idx = tid + i * 256;
            int r = idx >> 6, c = idx & 63;
            ob[(size_t)r * DIM + c] = Ps[r * LDS + c] * rowinv[r];
        }
        __syncthreads();
    }
#endif
}

// ---------------------------------------------------------------------------
extern "C" void kernel_launch(void* const* d_in, const int* in_sizes, int n_in,
                              void* d_out, int out_size)
{
    const float* x  = (const float*)d_in[0];
    const float* Wq = (const float*)d_in[1];
    const float* bq = (const float*)d_in[2];
    const float* Wk = (const float*)d_in[3];
    const float* bk = (const float*)d_in[4];
    float* out = (float*)d_out;

    cudaFuncSetAttribute(proj_kernel, cudaFuncAttributeMaxDynamicSharedMemorySize, PJ_TOTAL);
    dim3 pg((BATCH * SEQ) / 128, DIM / 64, 2);
    proj_kernel<<<pg, 256, PJ_TOTAL>>>(x, Wq, bq, Wk, bk);

    cudaFuncSetAttribute(attn_kernel, cudaFuncAttributeMaxDynamicSharedMemorySize, ATTN_TOTAL);
    dim3 ag(SEQ / 256, NH, BATCH);
    attn_kernel<<<ag, 256, ATTN_TOTAL>>>(out);
}

// round 15
// speedup vs baseline: 6.3546x; 1.0765x over previous
#include <cuda_runtime.h>
#include <cuda_bf16.h>
#include <mma.h>
#include <cstdint>

using namespace nvcuda;

#define BATCH 2
#define SEQ   4096
#define DIM   512
#define NH    8
#define HD    64
#define LDS   68
#define LDSB  36

#if defined(__CUDA_ARCH__) && defined(__CUDA_ARCH_HAS_FEATURE__)
#if __CUDA_ARCH_HAS_FEATURE__(SM103_ALL)
#define TC_OK 1
#endif
#endif
#ifndef TC_OK
#define TC_OK 0
#endif

__device__ float g_q[(size_t)BATCH * NH * SEQ * HD];
__device__ float g_k[(size_t)BATCH * NH * SEQ * HD];

using FragA  = wmma::fragment<wmma::matrix_a, 16, 16, 8, wmma::precision::tf32, wmma::row_major>;
using FragBc = wmma::fragment<wmma::matrix_b, 16, 16, 8, wmma::precision::tf32, wmma::col_major>;
using FragBr = wmma::fragment<wmma::matrix_b, 16, 16, 8, wmma::precision::tf32, wmma::row_major>;
using FragC  = wmma::fragment<wmma::accumulator, 16, 16, 8, float>;

// ===========================================================================
// helpers
// ===========================================================================
__device__ __forceinline__ uint32_t smem_u32(const void* p) {
    uint32_t a;
    asm("{ .reg .u64 t; cvta.to.shared.u64 t, %1; cvt.u32.u64 %0, t; }" : "=r"(a) : "l"(p));
    return a;
}
__device__ __forceinline__ float cvt_tf32(float x) {
    float r; asm("cvt.rna.tf32.f32 %0, %1;" : "=f"(r) : "f"(x)); return r;
}
__device__ __forceinline__ float ex2f(float x) {
    float r; asm("ex2.approx.f32 %0, %1;" : "=f"(r) : "f"(x)); return r;
}

#if TC_OK
__device__ __forceinline__ uint32_t elect_one() {
    uint32_t p;
    asm volatile("{\n .reg .pred p;\n elect.sync _|p, 0xFFFFFFFF;\n selp.b32 %0, 1, 0, p;\n}" : "=r"(p));
    return p;
}
__device__ __forceinline__ void mbar_init(uint32_t mbar, uint32_t cnt) {
    asm volatile("mbarrier.init.shared.b64 [%0], %1;" :: "r"(mbar), "r"(cnt) : "memory");
}
__device__ __forceinline__ void mbar_inval(uint32_t mbar) {
    asm volatile("mbarrier.inval.shared.b64 [%0];" :: "r"(mbar) : "memory");
}
__device__ __forceinline__ void mbar_wait(uint32_t mbar, uint32_t parity) {
    asm volatile(
        "{\n .reg .pred P;\n"
        "W%=: mbarrier.try_wait.parity.acquire.cta.shared::cta.b64 P, [%0], %1, 0x989680;\n"
        " @P bra D%=;\n bra W%=;\n D%=:\n}"
        :: "r"(mbar), "r"(parity) : "memory");
}
__device__ __forceinline__ void tc_alloc(uint32_t smem_dst, uint32_t ncols) {
    asm volatile("tcgen05.alloc.cta_group::1.sync.aligned.shared::cta.b32 [%0], %1;"
                 :: "r"(smem_dst), "r"(ncols) : "memory");
}
__device__ __forceinline__ void tc_dealloc(uint32_t tmem, uint32_t ncols) {
    asm volatile("tcgen05.dealloc.cta_group::1.sync.aligned.b32 %0, %1;" :: "r"(tmem), "r"(ncols));
}
__device__ __forceinline__ void tc_commit(uint32_t mbar) {
    asm volatile("tcgen05.commit.cta_group::1.mbarrier::arrive::one.shared::cluster.b64 [%0];"
                 :: "r"(mbar) : "memory");
}
__device__ __forceinline__ void fence_before() { asm volatile("tcgen05.fence::before_thread_sync;" ::: "memory"); }
__device__ __forceinline__ void fence_after()  { asm volatile("tcgen05.fence::after_thread_sync;" ::: "memory"); }
__device__ __forceinline__ void fence_async()  { asm volatile("fence.proxy.async.shared::cta;" ::: "memory"); }
__device__ __forceinline__ void tc_wait_ld()   { asm volatile("tcgen05.wait::ld.sync.aligned;" ::: "memory"); }
__device__ __forceinline__ void tc_wait_st()   { asm volatile("tcgen05.wait::st.sync.aligned;" ::: "memory"); }

__device__ __forceinline__ void mma_tf32_ss(uint32_t d, uint64_t a, uint64_t b,
                                            uint32_t idesc, uint32_t en) {
    asm volatile(
        "{\n .reg .pred p;\n setp.ne.u32 p, %5, 0;\n"
        " tcgen05.mma.cta_group::1.kind::tf32 [%0], %1, %2, %3, {%4, %4, %4, %4}, p;\n}"
        :: "r"(d), "l"(a), "l"(b), "r"(idesc), "r"(0u), "r"(en) : "memory");
}
__device__ __forceinline__ void mma_tf32_ts(uint32_t d, uint32_t a, uint64_t b,
                                            uint32_t idesc, uint32_t en) {
    asm volatile(
        "{\n .reg .pred p;\n setp.ne.u32 p, %5, 0;\n"
        " tcgen05.mma.cta_group::1.kind::tf32 [%0], [%1], %2, %3, {%4, %4, %4, %4}, p;\n}"
        :: "r"(d), "r"(a), "l"(b), "r"(idesc), "r"(0u), "r"(en) : "memory");
}

__device__ __forceinline__ void ld32(uint32_t* r, uint32_t addr) {
    asm volatile(
        "tcgen05.ld.sync.aligned.32x32b.x32.b32 "
        "{%0,%1,%2,%3,%4,%5,%6,%7,%8,%9,%10,%11,%12,%13,%14,%15,"
        "%16,%17,%18,%19,%20,%21,%22,%23,%24,%25,%26,%27,%28,%29,%30,%31}, [%32];"
        : "=r"(r[0]),"=r"(r[1]),"=r"(r[2]),"=r"(r[3]),"=r"(r[4]),"=r"(r[5]),"=r"(r[6]),"=r"(r[7]),
          "=r"(r[8]),"=r"(r[9]),"=r"(r[10]),"=r"(r[11]),"=r"(r[12]),"=r"(r[13]),"=r"(r[14]),"=r"(r[15]),
          "=r"(r[16]),"=r"(r[17]),"=r"(r[18]),"=r"(r[19]),"=r"(r[20]),"=r"(r[21]),"=r"(r[22]),"=r"(r[23]),
          "=r"(r[24]),"=r"(r[25]),"=r"(r[26]),"=r"(r[27]),"=r"(r[28]),"=r"(r[29]),"=r"(r[30]),"=r"(r[31])
        : "r"(addr));
}
__device__ __forceinline__ void st32(uint32_t addr, const uint32_t* r) {
    asm volatile(
        "tcgen05.st.sync.aligned.32x32b.x32.b32 [%0], "
        "{%1,%2,%3,%4,%5,%6,%7,%8,%9,%10,%11,%12,%13,%14,%15,%16,"
        "%17,%18,%19,%20,%21,%22,%23,%24,%25,%26,%27,%28,%29,%30,%31,%32};"
        :: "r"(addr),
           "r"(r[0]),"r"(r[1]),"r"(r[2]),"r"(r[3]),"r"(r[4]),"r"(r[5]),"r"(r[6]),"r"(r[7]),
           "r"(r[8]),"r"(r[9]),"r"(r[10]),"r"(r[11]),"r"(r[12]),"r"(r[13]),"r"(r[14]),"r"(r[15]),
           "r"(r[16]),"r"(r[17]),"r"(r[18]),"r"(r[19]),"r"(r[20]),"r"(r[21]),"r"(r[22]),"r"(r[23]),
           "r"(r[24]),"r"(r[25]),"r"(r[26]),"r"(r[27]),"r"(r[28]),"r"(r[29]),"r"(r[30]),"r"(r[31])
        : "memory");
}

// K-major SW128 descriptor: SBO=64, LBO=1, version=1
__device__ __forceinline__ uint64_t make_desc(uint32_t addr) {
    const uint64_t base = (uint64_t(2) << 61) | (uint64_t(1) << 46) |
                          (uint64_t(64) << 32) | (uint64_t(1) << 16);
    return base | ((uint64_t)(addr >> 4) & 0x3FFF);
}
#endif  // TC_OK

#define IDESC_TF32 ((1u<<4) | (2u<<7) | (2u<<10) | (8u<<17) | (8u<<24))  // F32 acc, tf32 a/b, N=64, M=128

#define AOFF(s) ((s) < 4 ? (uint64_t)((s) * 2) : (uint64_t)(1024 + ((s) - 4) * 2))
#define BOFF(s) ((s) < 4 ? (uint64_t)((s) * 2) : (uint64_t)(512  + ((s) - 4) * 2))

// ===========================================================================
// Projection (unchanged from R6): grid (64, 8, 2), 256 thr.
// ===========================================================================
#define PJ_TMEMP   0
#define PJ_BAR(i)  (8 + (i) * 8)
#define PJ_X       1024
#define PJ_XSTR    16384
#define PJ_W       (1024 + 3 * 16384)
#define PJ_WSTR    8192
#define PJ_TOTAL   74880

__global__ void __launch_bounds__(256, 2)
proj_kernel(const float* __restrict__ x,
            const float* __restrict__ Wq, const float* __restrict__ bq,
            const float* __restrict__ Wk, const float* __restrict__ bk)
{
    const int which = blockIdx.z;
    const float* W    = which ? Wk : Wq;
    const float* bias = which ? bk : bq;

#if TC_OK
    extern __shared__ __align__(1024) char smem[];
    const uint32_t sb = smem_u32(smem);

    const int tid  = threadIdx.x;
    const int wid  = tid >> 5;
    const int lane = tid & 31;
    const int half = wid >> 2;
    const int row  = (wid & 3) * 32 + lane;
    const int m0   = blockIdx.x * 128;
    const int e0   = blockIdx.y * 64;

    if (wid == 0) tc_alloc(sb + PJ_TMEMP, 64);
    if (tid == 0) {
        mbar_init(sb + PJ_BAR(0), 1);
        mbar_init(sb + PJ_BAR(1), 1);
        mbar_init(sb + PJ_BAR(2), 1);
    }

    auto stageX = [&](int k0, int b) {
#pragma unroll
        for (int i = 0; i < 4; i++) {
            int idx4 = tid + i * 256;
            int r = idx4 >> 3, c4 = (idx4 & 7) * 4;
            float4 v = *(const float4*)(x + (size_t)(m0 + r) * DIM + k0 + c4);
            uint32_t off = ((uint32_t)(r >> 3) * 1024 + (r & 7) * 128 + c4 * 4)
                           ^ ((uint32_t)(r & 7) << 4);
            *(float4*)(smem + PJ_X + b * PJ_XSTR + off) = make_float4(
                cvt_tf32(v.x), cvt_tf32(v.y), cvt_tf32(v.z), cvt_tf32(v.w));
        }
    };
    auto stageW = [&](int k0, int b) {
#pragma unroll
        for (int i = 0; i < 2; i++) {
            int idx4 = tid + i * 256;
            int r = idx4 >> 3, c4 = (idx4 & 7) * 4;
            float4 v = *(const float4*)(W + (size_t)(e0 + r) * DIM + k0 + c4);
            uint32_t off = ((uint32_t)(r >> 3) * 1024 + (r & 7) * 128 + c4 * 4)
                           ^ ((uint32_t)(r & 7) << 4);
            *(float4*)(smem + PJ_W + b * PJ_WSTR + off) = make_float4(
                cvt_tf32(v.x), cvt_tf32(v.y), cvt_tf32(v.z), cvt_tf32(v.w));
        }
    };

    stageX(0, 0);  stageW(0, 0);
    stageX(32, 1); stageW(32, 1);
    fence_async();
    fence_before();
    __syncthreads();

    uint32_t tmem;
    asm volatile("ld.shared.b32 %0, [%1];" : "=r"(tmem) : "r"(sb + PJ_TMEMP));

    int ph0 = 0, ph1 = 0, ph2 = 0;
#pragma unroll
    for (int c = 0; c < 16; c++) {
        if (wid == 0) {
            fence_after();
            if (elect_one()) {
                uint64_t ad = make_desc(sb + PJ_X + (c % 3) * PJ_XSTR);
                uint64_t bd = make_desc(sb + PJ_W + (c % 3) * PJ_WSTR);
#pragma unroll
                for (int s = 0; s < 4; s++)
                    mma_tf32_ss(tmem, ad + s * 2, bd + s * 2, IDESC_TF32, (c > 0) || (s > 0));
                tc_commit(sb + PJ_BAR(c % 3));
            }
        }
        if (c + 2 < 16) {
            const int b2 = (c + 2) % 3;
            if (c + 2 >= 3) {
                if (b2 == 0)      { mbar_wait(sb + PJ_BAR(0), (uint32_t)ph0); ph0 ^= 1; }
                else if (b2 == 1) { mbar_wait(sb + PJ_BAR(1), (uint32_t)ph1); ph1 ^= 1; }
                else              { mbar_wait(sb + PJ_BAR(2), (uint32_t)ph2); ph2 ^= 1; }
            }
            stageX((c + 2) * 32, b2);
            stageW((c + 2) * 32, b2);
            fence_async();
            fence_before();
            __syncthreads();
        }
    }

    mbar_wait(sb + PJ_BAR(0), (uint32_t)ph0);
    fence_after();

    uint32_t orr[32];
    ld32(orr, tmem + (uint32_t)(half * 32));
    tc_wait_ld();

    const int m = m0 + row;
    const int b = m >> 12;
    const int nn = m & (SEQ - 1);
    float* dst = (which ? g_k : g_q)
               + (((size_t)b * NH + blockIdx.y) * SEQ + nn) * HD + half * 32;
    const float* bp = bias + e0 + half * 32;
#pragma unroll
    for (int j = 0; j < 32; j += 4)
        *(float4*)(dst + j) = make_float4(__uint_as_float(orr[j])     + bp[j],
                                          __uint_as_float(orr[j + 1]) + bp[j + 1],
                                          __uint_as_float(orr[j + 2]) + bp[j + 2],
                                          __uint_as_float(orr[j + 3]) + bp[j + 3]);

    fence_before();
    __syncthreads();
    if (tid == 0) { mbar_inval(sb + PJ_BAR(0)); mbar_inval(sb + PJ_BAR(1)); mbar_inval(sb + PJ_BAR(2)); }
    if (wid == 0) tc_dealloc(tmem, 64);

#else
    // -------- wmma fallback --------
    extern __shared__ float smf[];
    float* As = smf;
    float* Bs = smf + 128 * LDSB;

    const int tid  = threadIdx.x;
    const int warp = tid >> 5;
    const int m0   = blockIdx.x * 128;
    const int e0   = blockIdx.y * 64;

    FragC acc[4];
#pragma unroll
    for (int n = 0; n < 4; n++) wmma::fill_fragment(acc[n], 0.0f);

    float xr[16], wr[8];
#pragma unroll
    for (int i = 0; i < 16; i++) {
        int idx = tid + i * 256, r = idx >> 5, c = idx & 31;
        xr[i] = x[(size_t)(m0 + r) * DIM + c];
    }
#pragma unroll
    for (int i = 0; i < 8; i++) {
        int idx = tid + i * 256, r = idx >> 5, c = idx & 31;
        wr[i] = W[(size_t)(e0 + r) * DIM + c];
    }

    for (int kt = 0; kt < 16; kt++) {
#pragma unroll
        for (int i = 0; i < 16; i++) {
            int idx = tid + i * 256, r = idx >> 5, c = idx & 31;
            As[r * LDSB + c] = wmma::__float_to_tf32(xr[i]);
        }
#pragma unroll
        for (int i = 0; i < 8; i++) {
            int idx = tid + i * 256, r = idx >> 5, c = idx & 31;
            Bs[r * LDSB + c] = wmma::__float_to_tf32(wr[i]);
        }
        __syncthreads();

        if (kt < 15) {
            const int k0 = (kt + 1) * 32;
#pragma unroll
            for (int i = 0; i < 16; i++) {
                int idx = tid + i * 256, r = idx >> 5, c = idx & 31;
                xr[i] = x[(size_t)(m0 + r) * DIM + k0 + c];
            }
#pragma unroll
            for (int i = 0; i < 8; i++) {
                int idx = tid + i * 256, r = idx >> 5, c = idx & 31;
                wr[i] = W[(size_t)(e0 + r) * DIM + k0 + c];
            }
        }

#pragma unroll
        for (int kk = 0; kk < 4; kk++) {
            FragA a;
            wmma::load_matrix_sync(a, As + warp * 16 * LDSB + kk * 8, LDSB);
#pragma unroll
            for (int n = 0; n < 4; n++) {
                FragBc b;
                wmma::load_matrix_sync(b, Bs + n * 16 * LDSB + kk * 8, LDSB);
                wmma::mma_sync(acc[n], a, b, acc[n]);
            }
        }
        __syncthreads();
    }

#pragma unroll
    for (int n = 0; n < 4; n++)
        wmma::store_matrix_sync(smf + warp * 16 * LDS + n * 16, acc[n], LDS, wmma::mem_row_major);
    __syncthreads();

    float* dst = which ? g_k : g_q;
    const int h = blockIdx.y;
#pragma unroll
    for (int i = 0; i < 32; i++) {
        int idx = tid + i * 256;
        int r = idx >> 6, c = idx & 63;
        int m = m0 + r;
        int b = m >> 12;
        int nn = m & (SEQ - 1);
        dst[(((size_t)b * NH + h) * SEQ + nn) * HD + c] = smf[r * LDS + c] + bias[e0 + c];
    }
#endif
}

// ===========================================================================
// Attention: TWO q-tiles per CTA, 512 THREADS (16 warps): warps 0-7 run
// tile A's softmax, warps 8-15 tile B's, CONCURRENTLY — TMEM-port, MUFU,
// FMA and LSU work from different warps overlaps. Grid (16, 8, 2).
//   TMEM (512): SA0@0 SA1@64 OA@128 PA@192 | SB0@256 SB1@320 OB@384 PB@448.
//   SMEM: QA/QB 2x32KB, K 2x16KB, VT 2x16KB.
// ===========================================================================
#define AT_TMEMP  0
#define AT_SBAR   8
#define AT_OBAR   16
#define AT_RS(i)  (32 + (i) * 512)         /* 4 arrays of 128 floats */
#define AT_Q      3072
#define AT_K      68608                    /* 2 x 16384 */
#define AT_VT     101376                   /* 2 x 16384 */
#define ATTN_TOTAL 134144

__global__ void __launch_bounds__(512, 1)
attn_kernel(float* __restrict__ out)
{
#if TC_OK
    extern __shared__ __align__(1024) char smem[];
    const uint32_t sb = smem_u32(smem);

    const int tid  = threadIdx.x;
    const int wid  = tid >> 5;
    const int lane = tid & 31;
    const int tile = wid >> 3;          // 0: tile A warps, 1: tile B warps
    const int wg   = wid & 7;           // warp within tile group
    const int half = wg >> 2;           // column half
    const int row  = (wg & 3) * 32 + lane;

    const int bh = blockIdx.z * NH + blockIdx.y;
    const int q0 = blockIdx.x * 256;
    const float* qb = g_q + (size_t)bh * SEQ * HD + (size_t)q0 * HD;
    const float* kb = g_k + (size_t)bh * SEQ * HD;
    const float scale = 0.063758746f;   // 512^-0.5 * log2(e)

    if (wid == 0) tc_alloc(sb + AT_TMEMP, 512);

    // Stage Q tiles A and B (512 threads: 4 float4 per thread per tile)
#pragma unroll
    for (int t = 0; t < 2; t++) {
        const float4* q4 = (const float4*)(qb + (size_t)t * 128 * HD);
        char* Qb = smem + AT_Q + t * 32768;
#pragma unroll
        for (int i = 0; i < 4; i++) {
            int idx4 = tid + i * 512;
            int eb = idx4 * 4;
            int r = eb >> 6, c = eb & 63;
            float4 v = q4[idx4];
            uint32_t atom = (uint32_t)((r >> 3) + ((c >> 5) << 4));
            uint32_t off = (atom * 1024 + (r & 7) * 128 + (c & 31) * 4)
                           ^ ((uint32_t)(r & 7) << 4);
            *(float4*)(Qb + off) = make_float4(
                cvt_tf32(v.x * scale), cvt_tf32(v.y * scale),
                cvt_tf32(v.z * scale), cvt_tf32(v.w * scale));
        }
    }

    // Loop-invariant staging offsets (512-thread layout)
    uint32_t kOff[2];
#pragma unroll
    for (int i = 0; i < 2; i++) {
        int idx4 = tid + i * 512;
        int eb = idx4 * 4;
        int key = eb >> 6, h0 = eb & 63;
        kOff[i] = (((uint32_t)((key >> 3) + ((h0 >> 5) << 3)) * 1024
                    + (key & 7) * 128 + (h0 & 31) * 4) ^ ((uint32_t)(key & 7) << 4));
    }
    uint32_t vtW[2];
#pragma unroll
    for (int j = 0; j < 2; j++) {
        int idx = tid + j * 512;
        int hd = idx & 63, kq = idx >> 6;
        vtW[j] = (((uint32_t)((hd >> 3) + ((kq >> 3) << 3)) * 1024
                   + (hd & 7) * 128 + ((kq * 4) & 31) * 4) ^ ((uint32_t)(hd & 7) << 4));
    }

    auto stageK = [&](const float4* kr, int b) {
        char* Kb = smem + AT_K + b * 16384;
#pragma unroll
        for (int i = 0; i < 2; i++) {
            float4 v = kr[i];
            *(float4*)(Kb + kOff[i]) = make_float4(
                cvt_tf32(v.x), cvt_tf32(v.y), cvt_tf32(v.z), cvt_tf32(v.w));
        }
    };

    auto stageVT = [&](int kbuf, int vbuf) {
        char* Kb = smem + AT_K  + kbuf * 16384;
        char* Vb = smem + AT_VT + vbuf * 16384;
#pragma unroll
        for (int j = 0; j < 2; j++) {
            int idx = tid + j * 512;
            int hd = idx & 63, kq = idx >> 6;
            float v[4];
#pragma unroll
            for (int r = 0; r < 4; r++) {
                int key = kq * 4 + r;
                uint32_t offr = ((uint32_t)((key >> 3) + ((hd >> 5) << 3)) * 1024
                                 + (key & 7) * 128 + (hd & 31) * 4)
                                ^ ((uint32_t)(key & 7) << 4);
                v[r] = *(const float*)(Kb + offr);
            }
            *(float4*)(Vb + vtW[j]) = make_float4(v[0], v[1], v[2], v[3]);
        }
    };

    // Prologue: stage K tiles 0 and 1
    {
        float4 kr[2];
#pragma unroll
        for (int i = 0; i < 2; i++) kr[i] = ((const float4*)kb)[tid + i * 512];
        stageK(kr, 0);
#pragma unroll
        for (int i = 0; i < 2; i++) kr[i] = ((const float4*)(kb + (size_t)64 * HD))[tid + i * 512];
        stageK(kr, 1);
    }

    if (tid == 0) { mbar_init(sb + AT_SBAR, 1); mbar_init(sb + AT_OBAR, 1); }
    fence_async();
    fence_before();
    __syncthreads();

    uint32_t tmem;
    asm volatile("ld.shared.b32 %0, [%1];" : "=r"(tmem) : "r"(sb + AT_TMEMP));
    const uint32_t S_T  = tmem + (uint32_t)(tile * 256);          // this warp's S
    const uint32_t P_T  = tmem + 192 + (uint32_t)(tile * 256);    // this warp's P
    const uint32_t SA_T = tmem;
    const uint32_t OA_T = tmem + 128;
    const uint32_t PA_T = tmem + 192;
    const uint32_t SB_T = tmem + 256;
    const uint32_t OB_T = tmem + 384;
    const uint32_t PB_T = tmem + 448;
    const uint32_t sbar = sb + AT_SBAR;
    const uint32_t obar = sb + AT_OBAR;
    const uint64_t qdA  = make_desc(sb + AT_Q);
    const uint64_t qdB  = make_desc(sb + AT_Q + 32768);
    const uint32_t wsub = (uint32_t)(wid & 3) << 21;

    // issue SA(0), SB(0); single commit
    if (wid == 0) {
        fence_after();
        if (elect_one()) {
            uint64_t kd = make_desc(sb + AT_K);
#pragma unroll
            for (int s = 0; s < 8; s++)
                mma_tf32_ss(SA_T, qdA + AOFF(s), kd + BOFF(s), IDESC_TF32, s > 0);
#pragma unroll
            for (int s = 0; s < 8; s++)
                mma_tf32_ss(SB_T, qdB + AOFF(s), kd + BOFF(s), IDESC_TF32, s > 0);
            tc_commit(sbar);
        }
    }

    stageVT(0, 0);

    float rsum = 0.0f;    // this warp's (tile, half, row) partial

    for (int kt = 0; kt < SEQ / 64; kt++) {
        // 0. early LDG of K(kt+2)
        float4 kr[2];
        const bool do_stage = (kt + 2 < SEQ / 64);
        if (do_stage) {
            const float4* k4 = (const float4*)(kb + (size_t)(kt + 2) * 64 * HD);
#pragma unroll
            for (int i = 0; i < 2; i++) kr[i] = k4[tid + i * 512];
        }

        // 1. wait S(kt) for both tiles
        mbar_wait(sbar, (uint32_t)(kt & 1));
        fence_after();

        // 2. issue SA(kt+1), SB(kt+1) immediately
        if (kt < SEQ / 64 - 1 && wid == 0) {
            if (elect_one()) {
                uint64_t kd = make_desc(sb + AT_K + ((kt + 1) & 1) * 16384);
                uint32_t off = (uint32_t)(((kt + 1) & 1) * 64);
#pragma unroll
                for (int s = 0; s < 8; s++)
                    mma_tf32_ss(SA_T + off, qdA + AOFF(s), kd + BOFF(s), IDESC_TF32, s > 0);
#pragma unroll
                for (int s = 0; s < 8; s++)
                    mma_tf32_ss(SB_T + off, qdB + AOFF(s), kd + BOFF(s), IDESC_TF32, s > 0);
                tc_commit(sbar);
            }
        }

        // 3. wait O(kt-1) (frees PA/PB and VT buf (kt-1)&1)
        if (kt >= 1) mbar_wait(obar, (uint32_t)((kt + 1) & 1));

        // 4. softmax: each warp handles its (tile, half) 32-col chunk.
        //    16 warps run tile A and tile B concurrently.
        {
            uint32_t v[32];
            ld32(v, S_T + (uint32_t)((kt & 1) * 64 + half * 32));
            tc_wait_ld();
#pragma unroll
            for (int c = 0; c < 32; c++) {
                float e = ex2f(__uint_as_float(v[c]));
                rsum += e;
                v[c] = __float_as_uint(cvt_tf32(e));
            }
            st32(P_T + (uint32_t)(half * 32) + wsub, v);
            tc_wait_st();
        }

        // 5. stage K(kt+2) into buf kt&1
        if (do_stage) stageK(kr, kt & 1);
        // 6. stage VT(kt+1)
        if (kt + 1 < SEQ / 64) stageVT((kt + 1) & 1, (kt + 1) & 1);

        fence_async();
        fence_before();
        __syncthreads();

        // 7. issue OA(kt), OB(kt)
        if (wid == 0) {
            fence_after();
            if (elect_one()) {
                uint64_t vd = make_desc(sb + AT_VT + (kt & 1) * 16384);
                uint32_t en0 = (kt > 0);
#pragma unroll
                for (int s = 0; s < 8; s++)
                    mma_tf32_ts(OA_T, PA_T + (uint32_t)(s * 8), vd + BOFF(s),
                                IDESC_TF32, en0 || (s > 0));
#pragma unroll
                for (int s = 0; s < 8; s++)
                    mma_tf32_ts(OB_T, PB_T + (uint32_t)(s * 8), vd + BOFF(s),
                                IDESC_TF32, en0 || (s > 0));
                tc_commit(obar);
            }
        }
    }

    // final: O(63) = flip 64, parity 1
    mbar_wait(obar, 1u);
    fence_after();

    *(float*)(smem + AT_RS(tile * 2 + half) + row * 4) = rsum;
    __syncthreads();

    const float inv = 1.0f / (*(float*)(smem + AT_RS(tile * 2)     + row * 4) +
                              *(float*)(smem + AT_RS(tile * 2 + 1) + row * 4));

    {
        uint32_t orr[32];
        const uint32_t O_T = tmem + 128 + (uint32_t)(tile * 256);
        ld32(orr, O_T + (uint32_t)(half * 32));
        tc_wait_ld();
        float* ob = out + ((size_t)blockIdx.z * SEQ + q0 + tile * 128 + row) * DIM
                        + blockIdx.y * HD + half * 32;
#pragma unroll
        for (int j = 0; j < 32; j += 4)
            *(float4*)(ob + j) = make_float4(__uint_as_float(orr[j]) * inv,
                                             __uint_as_float(orr[j + 1]) * inv,
                                             __uint_as_float(orr[j + 2]) * inv,
                                             __uint_as_float(orr[j + 3]) * inv);
    }

    fence_before();
    __syncthreads();
    if (tid == 0) { mbar_inval(sbar); mbar_inval(obar); }
    if (wid == 0) tc_dealloc(tmem, 512);

#else
    // -------- wmma fallback: 512 threads, halves process their own q-subtile
    // sharing the K buffers. --------
    extern __shared__ float smf[];
    float* Ks0    = smf;                       // 64*LDS
    float* Ks1    = smf + 64 * LDS;            // 64*LDS
    float* PsBase = smf + 128 * LDS;           // 2 x 128*LDS
    float* rowinv = smf + 384 * LDS;           // 256

    const int tid  = threadIdx.x;
    const int htid = tid & 255;                // thread id within half
    const int tile = tid >> 8;                 // 0 or 1
    const int warp = htid >> 5;
    const int lane = tid & 31;
    const int bh   = blockIdx.z * NH + blockIdx.y;
    const int q0   = blockIdx.x * 256 + tile * 128;

    float* Ps = PsBase + tile * 128 * LDS;
    const float* qb = g_q + (size_t)bh * SEQ * HD + (size_t)q0 * HD;
    const float* kb = g_k + (size_t)bh * SEQ * HD;
    const float scale = 0.04419417382415922f;

#pragma unroll
    for (int i = 0; i < 32; i++) {
        int idx = htid + i * 256;
        int r = idx >> 6, c = idx & 63;
        Ps[r * LDS + c] = wmma::__float_to_tf32(qb[idx] * scale);
    }
    __syncthreads();

    FragA qa[8];
#pragma unroll
    for (int kk = 0; kk < 8; kk++)
        wmma::load_matrix_sync(qa[kk], Ps + warp * 16 * LDS + kk * 8, LDS);

    // K tile 0 staged by all 512 threads (shared between halves)
#pragma unroll
    for (int i = 0; i < 8; i++) {
        int idx = tid + i * 512;
        int r = idx >> 6, c = idx & 63;
        Ks0[r * LDS + c] = wmma::__float_to_tf32(kb[idx]);
    }
    __syncthreads();

    FragC oacc[4];
#pragma unroll
    for (int n = 0; n < 4; n++) wmma::fill_fragment(oacc[n], 0.0f);

    float rsum = 0.0f;
    float* Pw = Ps + warp * 16 * LDS;

    for (int kt = 0; kt < SEQ / 64; kt++) {
        float* cur = (kt & 1) ? Ks1 : Ks0;
        float* nxt = (kt & 1) ? Ks0 : Ks1;

        if (kt < SEQ / 64 - 1) {
            const float* kp = kb + (size_t)(kt + 1) * 64 * HD;
#pragma unroll
            for (int i = 0; i < 8; i++) {
                int idx = tid + i * 512;
                int r = idx >> 6, c = idx & 63;
                nxt[r * LDS + c] = wmma::__float_to_tf32(kp[idx]);
            }
        }

        FragC sacc[4];
#pragma unroll
        for (int n = 0; n < 4; n++) wmma::fill_fragment(sacc[n], 0.0f);
#pragma unroll
        for (int kk = 0; kk < 8; kk++) {
#pragma unroll
            for (int n = 0; n < 4; n++) {
                FragBc b;
                wmma::load_matrix_sync(b, cur + n * 16 * LDS + kk * 8, LDS);
                wmma::mma_sync(sacc[n], qa[kk], b, sacc[n]);
            }
        }

#pragma unroll
        for (int n = 0; n < 4; n++) {
#pragma unroll
            for (int e = 0; e < sacc[n].num_elements; e++)
                sacc[n].x[e] = wmma::__float_to_tf32(__expf(sacc[n].x[e]));
            wmma::store_matrix_sync(Pw + n * 16, sacc[n], LDS, wmma::mem_row_major);
        }
        __syncwarp();

        {
            const float* pp = Pw + (lane >> 1) * LDS + (lane & 1) * 32;
            float part = 0.0f;
#pragma unroll
            for (int c = 0; c < 32; c++) part += pp[c];
            rsum += part;
        }

#pragma unroll
        for (int kk = 0; kk < 8; kk++) {
            FragA a;
            wmma::load_matrix_sync(a, Pw + kk * 8, LDS);
#pragma unroll
            for (int n = 0; n < 4; n++) {
                FragBr b;
                wmma::load_matrix_sync(b, cur + kk * 8 * LDS + n * 16, LDS);
                wmma::mma_sync(oacc[n], a, b, oacc[n]);
            }
        }

        __syncthreads();
    }

    rsum += __shfl_xor_sync(0xffffffffu, rsum, 1);
    if ((lane & 1) == 0) rowinv[tile * 128 + warp * 16 + (lane >> 1)] = 1.0f / rsum;

#pragma unroll
    for (int n = 0; n < 4; n++)
        wmma::store_matrix_sync(Pw + n * 16, oacc[n], LDS, wmma::mem_row_major);
    __syncthreads();

    float* ob = out + ((size_t)blockIdx.z * SEQ + q0) * DIM + blockIdx.y * HD;
#pragma unroll
    for (int i = 0; i < 32; i++) {
        int idx = htid + i * 256;
        int r = idx >> 6, c = idx & 63;
        ob[(size_t)r * DIM + c] = Ps[r * LDS + c] * rowinv[tile * 128 + r];
    }
#endif
}

// ---------------------------------------------------------------------------
extern "C" void kernel_launch(void* const* d_in, const int* in_sizes, int n_in,
                              void* d_out, int out_size)
{
    const float* x  = (const float*)d_in[0];
    const float* Wq = (const float*)d_in[1];
    const float* bq = (const float*)d_in[2];
    const float* Wk = (const float*)d_in[3];
    const float* bk = (const float*)d_in[4];
    float* out = (float*)d_out;

    cudaFuncSetAttribute(proj_kernel, cudaFuncAttributeMaxDynamicSharedMemorySize, PJ_TOTAL);
    dim3 pg((BATCH * SEQ) / 128, DIM / 64, 2);
    proj_kernel<<<pg, 256, PJ_TOTAL>>>(x, Wq, bq, Wk, bk);

    cudaFuncSetAttribute(attn_kernel, cudaFuncAttributeMaxDynamicSharedMemorySize, ATTN_TOTAL);
    dim3 ag(SEQ / 256, NH, BATCH);
    attn_kernel<<<ag, 512, ATTN_TOTAL>>>(out);
}

// round 16
// speedup vs baseline: 6.5070x; 1.0240x over previous
#include <cuda_runtime.h>
#include <cuda_bf16.h>
#include <mma.h>
#include <cstdint>

using namespace nvcuda;

#define BATCH 2
#define SEQ   4096
#define DIM   512
#define NH    8
#define HD    64
#define LDS   68
#define LDSB  36

#if defined(__CUDA_ARCH__) && defined(__CUDA_ARCH_HAS_FEATURE__)
#if __CUDA_ARCH_HAS_FEATURE__(SM103_ALL)
#define TC_OK 1
#endif
#endif
#ifndef TC_OK
#define TC_OK 0
#endif

__device__ float g_q[(size_t)BATCH * NH * SEQ * HD];
__device__ float g_k[(size_t)BATCH * NH * SEQ * HD];

using FragA  = wmma::fragment<wmma::matrix_a, 16, 16, 8, wmma::precision::tf32, wmma::row_major>;
using FragBc = wmma::fragment<wmma::matrix_b, 16, 16, 8, wmma::precision::tf32, wmma::col_major>;
using FragBr = wmma::fragment<wmma::matrix_b, 16, 16, 8, wmma::precision::tf32, wmma::row_major>;
using FragC  = wmma::fragment<wmma::accumulator, 16, 16, 8, float>;

// ===========================================================================
// helpers
// ===========================================================================
__device__ __forceinline__ uint32_t smem_u32(const void* p) {
    uint32_t a;
    asm("{ .reg .u64 t; cvta.to.shared.u64 t, %1; cvt.u32.u64 %0, t; }" : "=r"(a) : "l"(p));
    return a;
}
__device__ __forceinline__ float cvt_tf32(float x) {
    float r; asm("cvt.rna.tf32.f32 %0, %1;" : "=f"(r) : "f"(x)); return r;
}
__device__ __forceinline__ float ex2f(float x) {
    float r; asm("ex2.approx.f32 %0, %1;" : "=f"(r) : "f"(x)); return r;
}

#if TC_OK
__device__ __forceinline__ uint32_t elect_one() {
    uint32_t p;
    asm volatile("{\n .reg .pred p;\n elect.sync _|p, 0xFFFFFFFF;\n selp.b32 %0, 1, 0, p;\n}" : "=r"(p));
    return p;
}
__device__ __forceinline__ void mbar_init(uint32_t mbar, uint32_t cnt) {
    asm volatile("mbarrier.init.shared.b64 [%0], %1;" :: "r"(mbar), "r"(cnt) : "memory");
}
__device__ __forceinline__ void mbar_inval(uint32_t mbar) {
    asm volatile("mbarrier.inval.shared.b64 [%0];" :: "r"(mbar) : "memory");
}
__device__ __forceinline__ void mbar_wait(uint32_t mbar, uint32_t parity) {
    asm volatile(
        "{\n .reg .pred P;\n"
        "W%=: mbarrier.try_wait.parity.acquire.cta.shared::cta.b64 P, [%0], %1, 0x989680;\n"
        " @P bra D%=;\n bra W%=;\n D%=:\n}"
        :: "r"(mbar), "r"(parity) : "memory");
}
__device__ __forceinline__ void tc_alloc(uint32_t smem_dst, uint32_t ncols) {
    asm volatile("tcgen05.alloc.cta_group::1.sync.aligned.shared::cta.b32 [%0], %1;"
                 :: "r"(smem_dst), "r"(ncols) : "memory");
}
__device__ __forceinline__ void tc_dealloc(uint32_t tmem, uint32_t ncols) {
    asm volatile("tcgen05.dealloc.cta_group::1.sync.aligned.b32 %0, %1;" :: "r"(tmem), "r"(ncols));
}
__device__ __forceinline__ void tc_commit(uint32_t mbar) {
    asm volatile("tcgen05.commit.cta_group::1.mbarrier::arrive::one.shared::cluster.b64 [%0];"
                 :: "r"(mbar) : "memory");
}
__device__ __forceinline__ void fence_before() { asm volatile("tcgen05.fence::before_thread_sync;" ::: "memory"); }
__device__ __forceinline__ void fence_after()  { asm volatile("tcgen05.fence::after_thread_sync;" ::: "memory"); }
__device__ __forceinline__ void fence_async()  { asm volatile("fence.proxy.async.shared::cta;" ::: "memory"); }
__device__ __forceinline__ void tc_wait_ld()   { asm volatile("tcgen05.wait::ld.sync.aligned;" ::: "memory"); }
__device__ __forceinline__ void tc_wait_st()   { asm volatile("tcgen05.wait::st.sync.aligned;" ::: "memory"); }

__device__ __forceinline__ void mma_tf32_ss(uint32_t d, uint64_t a, uint64_t b,
                                            uint32_t idesc, uint32_t en) {
    asm volatile(
        "{\n .reg .pred p;\n setp.ne.u32 p, %5, 0;\n"
        " tcgen05.mma.cta_group::1.kind::tf32 [%0], %1, %2, %3, {%4, %4, %4, %4}, p;\n}"
        :: "r"(d), "l"(a), "l"(b), "r"(idesc), "r"(0u), "r"(en) : "memory");
}
__device__ __forceinline__ void mma_tf32_ts(uint32_t d, uint32_t a, uint64_t b,
                                            uint32_t idesc, uint32_t en) {
    asm volatile(
        "{\n .reg .pred p;\n setp.ne.u32 p, %5, 0;\n"
        " tcgen05.mma.cta_group::1.kind::tf32 [%0], [%1], %2, %3, {%4, %4, %4, %4}, p;\n}"
        :: "r"(d), "r"(a), "l"(b), "r"(idesc), "r"(0u), "r"(en) : "memory");
}

__device__ __forceinline__ void ld32(uint32_t* r, uint32_t addr) {
    asm volatile(
        "tcgen05.ld.sync.aligned.32x32b.x32.b32 "
        "{%0,%1,%2,%3,%4,%5,%6,%7,%8,%9,%10,%11,%12,%13,%14,%15,"
        "%16,%17,%18,%19,%20,%21,%22,%23,%24,%25,%26,%27,%28,%29,%30,%31}, [%32];"
        : "=r"(r[0]),"=r"(r[1]),"=r"(r[2]),"=r"(r[3]),"=r"(r[4]),"=r"(r[5]),"=r"(r[6]),"=r"(r[7]),
          "=r"(r[8]),"=r"(r[9]),"=r"(r[10]),"=r"(r[11]),"=r"(r[12]),"=r"(r[13]),"=r"(r[14]),"=r"(r[15]),
          "=r"(r[16]),"=r"(r[17]),"=r"(r[18]),"=r"(r[19]),"=r"(r[20]),"=r"(r[21]),"=r"(r[22]),"=r"(r[23]),
          "=r"(r[24]),"=r"(r[25]),"=r"(r[26]),"=r"(r[27]),"=r"(r[28]),"=r"(r[29]),"=r"(r[30]),"=r"(r[31])
        : "r"(addr));
}
__device__ __forceinline__ void st32(uint32_t addr, const uint32_t* r) {
    asm volatile(
        "tcgen05.st.sync.aligned.32x32b.x32.b32 [%0], "
        "{%1,%2,%3,%4,%5,%6,%7,%8,%9,%10,%11,%12,%13,%14,%15,%16,"
        "%17,%18,%19,%20,%21,%22,%23,%24,%25,%26,%27,%28,%29,%30,%31,%32};"
        :: "r"(addr),
           "r"(r[0]),"r"(r[1]),"r"(r[2]),"r"(r[3]),"r"(r[4]),"r"(r[5]),"r"(r[6]),"r"(r[7]),
           "r"(r[8]),"r"(r[9]),"r"(r[10]),"r"(r[11]),"r"(r[12]),"r"(r[13]),"r"(r[14]),"r"(r[15]),
           "r"(r[16]),"r"(r[17]),"r"(r[18]),"r"(r[19]),"r"(r[20]),"r"(r[21]),"r"(r[22]),"r"(r[23]),
           "r"(r[24]),"r"(r[25]),"r"(r[26]),"r"(r[27]),"r"(r[28]),"r"(r[29]),"r"(r[30]),"r"(r[31])
        : "memory");
}

// K-major SW128 descriptor: SBO=64, LBO=1, version=1
__device__ __forceinline__ uint64_t make_desc(uint32_t addr) {
    const uint64_t base = (uint64_t(2) << 61) | (uint64_t(1) << 46) |
                          (uint64_t(64) << 32) | (uint64_t(1) << 16);
    return base | ((uint64_t)(addr >> 4) & 0x3FFF);
}
#endif  // TC_OK

#define IDESC_TF32 ((1u<<4) | (2u<<7) | (2u<<10) | (8u<<17) | (8u<<24))  // F32 acc, tf32 a/b, N=64, M=128

#define AOFF(s) ((s) < 4 ? (uint64_t)((s) * 2) : (uint64_t)(1024 + ((s) - 4) * 2))
#define BOFF(s) ((s) < 4 ? (uint64_t)((s) * 2) : (uint64_t)(512  + ((s) - 4) * 2))

// ===========================================================================
// Projection (unchanged from R6): grid (64, 8, 2), 256 thr.
// ===========================================================================
#define PJ_TMEMP   0
#define PJ_BAR(i)  (8 + (i) * 8)
#define PJ_X       1024
#define PJ_XSTR    16384
#define PJ_W       (1024 + 3 * 16384)
#define PJ_WSTR    8192
#define PJ_TOTAL   74880

__global__ void __launch_bounds__(256, 2)
proj_kernel(const float* __restrict__ x,
            const float* __restrict__ Wq, const float* __restrict__ bq,
            const float* __restrict__ Wk, const float* __restrict__ bk)
{
    const int which = blockIdx.z;
    const float* W    = which ? Wk : Wq;
    const float* bias = which ? bk : bq;

#if TC_OK
    extern __shared__ __align__(1024) char smem[];
    const uint32_t sb = smem_u32(smem);

    const int tid  = threadIdx.x;
    const int wid  = tid >> 5;
    const int lane = tid & 31;
    const int half = wid >> 2;
    const int row  = (wid & 3) * 32 + lane;
    const int m0   = blockIdx.x * 128;
    const int e0   = blockIdx.y * 64;

    if (wid == 0) tc_alloc(sb + PJ_TMEMP, 64);
    if (tid == 0) {
        mbar_init(sb + PJ_BAR(0), 1);
        mbar_init(sb + PJ_BAR(1), 1);
        mbar_init(sb + PJ_BAR(2), 1);
    }

    auto stageX = [&](int k0, int b) {
#pragma unroll
        for (int i = 0; i < 4; i++) {
            int idx4 = tid + i * 256;
            int r = idx4 >> 3, c4 = (idx4 & 7) * 4;
            float4 v = *(const float4*)(x + (size_t)(m0 + r) * DIM + k0 + c4);
            uint32_t off = ((uint32_t)(r >> 3) * 1024 + (r & 7) * 128 + c4 * 4)
                           ^ ((uint32_t)(r & 7) << 4);
            *(float4*)(smem + PJ_X + b * PJ_XSTR + off) = make_float4(
                cvt_tf32(v.x), cvt_tf32(v.y), cvt_tf32(v.z), cvt_tf32(v.w));
        }
    };
    auto stageW = [&](int k0, int b) {
#pragma unroll
        for (int i = 0; i < 2; i++) {
            int idx4 = tid + i * 256;
            int r = idx4 >> 3, c4 = (idx4 & 7) * 4;
            float4 v = *(const float4*)(W + (size_t)(e0 + r) * DIM + k0 + c4);
            uint32_t off = ((uint32_t)(r >> 3) * 1024 + (r & 7) * 128 + c4 * 4)
                           ^ ((uint32_t)(r & 7) << 4);
            *(float4*)(smem + PJ_W + b * PJ_WSTR + off) = make_float4(
                cvt_tf32(v.x), cvt_tf32(v.y), cvt_tf32(v.z), cvt_tf32(v.w));
        }
    };

    stageX(0, 0);  stageW(0, 0);
    stageX(32, 1); stageW(32, 1);
    fence_async();
    fence_before();
    __syncthreads();

    uint32_t tmem;
    asm volatile("ld.shared.b32 %0, [%1];" : "=r"(tmem) : "r"(sb + PJ_TMEMP));

    int ph0 = 0, ph1 = 0, ph2 = 0;
#pragma unroll
    for (int c = 0; c < 16; c++) {
        if (wid == 0) {
            fence_after();
            if (elect_one()) {
                uint64_t ad = make_desc(sb + PJ_X + (c % 3) * PJ_XSTR);
                uint64_t bd = make_desc(sb + PJ_W + (c % 3) * PJ_WSTR);
#pragma unroll
                for (int s = 0; s < 4; s++)
                    mma_tf32_ss(tmem, ad + s * 2, bd + s * 2, IDESC_TF32, (c > 0) || (s > 0));
                tc_commit(sb + PJ_BAR(c % 3));
            }
        }
        if (c + 2 < 16) {
            const int b2 = (c + 2) % 3;
            if (c + 2 >= 3) {
                if (b2 == 0)      { mbar_wait(sb + PJ_BAR(0), (uint32_t)ph0); ph0 ^= 1; }
                else if (b2 == 1) { mbar_wait(sb + PJ_BAR(1), (uint32_t)ph1); ph1 ^= 1; }
                else              { mbar_wait(sb + PJ_BAR(2), (uint32_t)ph2); ph2 ^= 1; }
            }
            stageX((c + 2) * 32, b2);
            stageW((c + 2) * 32, b2);
            fence_async();
            fence_before();
            __syncthreads();
        }
    }

    mbar_wait(sb + PJ_BAR(0), (uint32_t)ph0);
    fence_after();

    uint32_t orr[32];
    ld32(orr, tmem + (uint32_t)(half * 32));
    tc_wait_ld();

    const int m = m0 + row;
    const int b = m >> 12;
    const int nn = m & (SEQ - 1);
    float* dst = (which ? g_k : g_q)
               + (((size_t)b * NH + blockIdx.y) * SEQ + nn) * HD + half * 32;
    const float* bp = bias + e0 + half * 32;
#pragma unroll
    for (int j = 0; j < 32; j += 4)
        *(float4*)(dst + j) = make_float4(__uint_as_float(orr[j])     + bp[j],
                                          __uint_as_float(orr[j + 1]) + bp[j + 1],
                                          __uint_as_float(orr[j + 2]) + bp[j + 2],
                                          __uint_as_float(orr[j + 3]) + bp[j + 3]);

    fence_before();
    __syncthreads();
    if (tid == 0) { mbar_inval(sb + PJ_BAR(0)); mbar_inval(sb + PJ_BAR(1)); mbar_inval(sb + PJ_BAR(2)); }
    if (wid == 0) tc_dealloc(tmem, 64);

#else
    // -------- wmma fallback --------
    extern __shared__ float smf[];
    float* As = smf;
    float* Bs = smf + 128 * LDSB;

    const int tid  = threadIdx.x;
    const int warp = tid >> 5;
    const int m0   = blockIdx.x * 128;
    const int e0   = blockIdx.y * 64;

    FragC acc[4];
#pragma unroll
    for (int n = 0; n < 4; n++) wmma::fill_fragment(acc[n], 0.0f);

    float xr[16], wr[8];
#pragma unroll
    for (int i = 0; i < 16; i++) {
        int idx = tid + i * 256, r = idx >> 5, c = idx & 31;
        xr[i] = x[(size_t)(m0 + r) * DIM + c];
    }
#pragma unroll
    for (int i = 0; i < 8; i++) {
        int idx = tid + i * 256, r = idx >> 5, c = idx & 31;
        wr[i] = W[(size_t)(e0 + r) * DIM + c];
    }

    for (int kt = 0; kt < 16; kt++) {
#pragma unroll
        for (int i = 0; i < 16; i++) {
            int idx = tid + i * 256, r = idx >> 5, c = idx & 31;
            As[r * LDSB + c] = wmma::__float_to_tf32(xr[i]);
        }
#pragma unroll
        for (int i = 0; i < 8; i++) {
            int idx = tid + i * 256, r = idx >> 5, c = idx & 31;
            Bs[r * LDSB + c] = wmma::__float_to_tf32(wr[i]);
        }
        __syncthreads();

        if (kt < 15) {
            const int k0 = (kt + 1) * 32;
#pragma unroll
            for (int i = 0; i < 16; i++) {
                int idx = tid + i * 256, r = idx >> 5, c = idx & 31;
                xr[i] = x[(size_t)(m0 + r) * DIM + k0 + c];
            }
#pragma unroll
            for (int i = 0; i < 8; i++) {
                int idx = tid + i * 256, r = idx >> 5, c = idx & 31;
                wr[i] = W[(size_t)(e0 + r) * DIM + k0 + c];
            }
        }

#pragma unroll
        for (int kk = 0; kk < 4; kk++) {
            FragA a;
            wmma::load_matrix_sync(a, As + warp * 16 * LDSB + kk * 8, LDSB);
#pragma unroll
            for (int n = 0; n < 4; n++) {
                FragBc b;
                wmma::load_matrix_sync(b, Bs + n * 16 * LDSB + kk * 8, LDSB);
                wmma::mma_sync(acc[n], a, b, acc[n]);
            }
        }
        __syncthreads();
    }

#pragma unroll
    for (int n = 0; n < 4; n++)
        wmma::store_matrix_sync(smf + warp * 16 * LDS + n * 16, acc[n], LDS, wmma::mem_row_major);
    __syncthreads();

    float* dst = which ? g_k : g_q;
    const int h = blockIdx.y;
#pragma unroll
    for (int i = 0; i < 32; i++) {
        int idx = tid + i * 256;
        int r = idx >> 6, c = idx & 63;
        int m = m0 + r;
        int b = m >> 12;
        int nn = m & (SEQ - 1);
        dst[(((size_t)b * NH + h) * SEQ + nn) * HD + c] = smf[r * LDS + c] + bias[e0 + c];
    }
#endif
}

// ===========================================================================
// Attention: TWO q-tiles per CTA, 512 threads (16 warps), R15 structure with
// the O-mma UNEXPOSED:
//   - obar wait moved between ex2 and STTM (hidden behind LDTM+MUFU)
//   - O(kt) issued right after the post-STTM sync; staging overlaps the O-mma
// Grid (16, 8, 2). TMEM (512): SA0/SA1/OA/PA | SB0/SB1/OB/PB.
// ===========================================================================
#define AT_TMEMP  0
#define AT_SBAR   8
#define AT_OBAR   16
#define AT_RS(i)  (32 + (i) * 512)
#define AT_Q      3072
#define AT_K      68608                    /* 2 x 16384 */
#define AT_VT     101376                   /* 2 x 16384 */
#define ATTN_TOTAL 134144

__global__ void __launch_bounds__(512, 1)
attn_kernel(float* __restrict__ out)
{
#if TC_OK
    extern __shared__ __align__(1024) char smem[];
    const uint32_t sb = smem_u32(smem);

    const int tid  = threadIdx.x;
    const int wid  = tid >> 5;
    const int lane = tid & 31;
    const int tile = wid >> 3;
    const int wg   = wid & 7;
    const int half = wg >> 2;
    const int row  = (wg & 3) * 32 + lane;

    const int bh = blockIdx.z * NH + blockIdx.y;
    const int q0 = blockIdx.x * 256;
    const float* qb = g_q + (size_t)bh * SEQ * HD + (size_t)q0 * HD;
    const float* kb = g_k + (size_t)bh * SEQ * HD;
    const float scale = 0.063758746f;   // 512^-0.5 * log2(e)

    if (wid == 0) tc_alloc(sb + AT_TMEMP, 512);

    // Stage Q tiles A and B
#pragma unroll
    for (int t = 0; t < 2; t++) {
        const float4* q4 = (const float4*)(qb + (size_t)t * 128 * HD);
        char* Qb = smem + AT_Q + t * 32768;
#pragma unroll
        for (int i = 0; i < 4; i++) {
            int idx4 = tid + i * 512;
            int eb = idx4 * 4;
            int r = eb >> 6, c = eb & 63;
            float4 v = q4[idx4];
            uint32_t atom = (uint32_t)((r >> 3) + ((c >> 5) << 4));
            uint32_t off = (atom * 1024 + (r & 7) * 128 + (c & 31) * 4)
                           ^ ((uint32_t)(r & 7) << 4);
            *(float4*)(Qb + off) = make_float4(
                cvt_tf32(v.x * scale), cvt_tf32(v.y * scale),
                cvt_tf32(v.z * scale), cvt_tf32(v.w * scale));
        }
    }

    // Loop-invariant staging offsets
    uint32_t kOff[2];
#pragma unroll
    for (int i = 0; i < 2; i++) {
        int idx4 = tid + i * 512;
        int eb = idx4 * 4;
        int key = eb >> 6, h0 = eb & 63;
        kOff[i] = (((uint32_t)((key >> 3) + ((h0 >> 5) << 3)) * 1024
                    + (key & 7) * 128 + (h0 & 31) * 4) ^ ((uint32_t)(key & 7) << 4));
    }
    uint32_t vtW[2];
#pragma unroll
    for (int j = 0; j < 2; j++) {
        int idx = tid + j * 512;
        int hd = idx & 63, kq = idx >> 6;
        vtW[j] = (((uint32_t)((hd >> 3) + ((kq >> 3) << 3)) * 1024
                   + (hd & 7) * 128 + ((kq * 4) & 31) * 4) ^ ((uint32_t)(hd & 7) << 4));
    }

    auto stageK = [&](const float4* kr, int b) {
        char* Kb = smem + AT_K + b * 16384;
#pragma unroll
        for (int i = 0; i < 2; i++) {
            float4 v = kr[i];
            *(float4*)(Kb + kOff[i]) = make_float4(
                cvt_tf32(v.x), cvt_tf32(v.y), cvt_tf32(v.z), cvt_tf32(v.w));
        }
    };

    auto stageVT = [&](int kbuf, int vbuf) {
        char* Kb = smem + AT_K  + kbuf * 16384;
        char* Vb = smem + AT_VT + vbuf * 16384;
#pragma unroll
        for (int j = 0; j < 2; j++) {
            int idx = tid + j * 512;
            int hd = idx & 63, kq = idx >> 6;
            float v[4];
#pragma unroll
            for (int r = 0; r < 4; r++) {
                int key = kq * 4 + r;
                uint32_t offr = ((uint32_t)((key >> 3) + ((hd >> 5) << 3)) * 1024
                                 + (key & 7) * 128 + (hd & 31) * 4)
                                ^ ((uint32_t)(key & 7) << 4);
                v[r] = *(const float*)(Kb + offr);
            }
            *(float4*)(Vb + vtW[j]) = make_float4(v[0], v[1], v[2], v[3]);
        }
    };

    // Prologue: stage K tiles 0 and 1
    {
        float4 kr[2];
#pragma unroll
        for (int i = 0; i < 2; i++) kr[i] = ((const float4*)kb)[tid + i * 512];
        stageK(kr, 0);
#pragma unroll
        for (int i = 0; i < 2; i++) kr[i] = ((const float4*)(kb + (size_t)64 * HD))[tid + i * 512];
        stageK(kr, 1);
    }

    if (tid == 0) { mbar_init(sb + AT_SBAR, 1); mbar_init(sb + AT_OBAR, 1); }
    fence_async();
    fence_before();
    __syncthreads();

    uint32_t tmem;
    asm volatile("ld.shared.b32 %0, [%1];" : "=r"(tmem) : "r"(sb + AT_TMEMP));
    const uint32_t S_T  = tmem + (uint32_t)(tile * 256);
    const uint32_t P_T  = tmem + 192 + (uint32_t)(tile * 256);
    const uint32_t SA_T = tmem;
    const uint32_t OA_T = tmem + 128;
    const uint32_t PA_T = tmem + 192;
    const uint32_t SB_T = tmem + 256;
    const uint32_t OB_T = tmem + 384;
    const uint32_t PB_T = tmem + 448;
    const uint32_t sbar = sb + AT_SBAR;
    const uint32_t obar = sb + AT_OBAR;
    const uint64_t qdA  = make_desc(sb + AT_Q);
    const uint64_t qdB  = make_desc(sb + AT_Q + 32768);
    const uint32_t wsub = (uint32_t)(wid & 3) << 21;

    // issue SA(0), SB(0); single commit
    if (wid == 0) {
        fence_after();
        if (elect_one()) {
            uint64_t kd = make_desc(sb + AT_K);
#pragma unroll
            for (int s = 0; s < 8; s++)
                mma_tf32_ss(SA_T, qdA + AOFF(s), kd + BOFF(s), IDESC_TF32, s > 0);
#pragma unroll
            for (int s = 0; s < 8; s++)
                mma_tf32_ss(SB_T, qdB + AOFF(s), kd + BOFF(s), IDESC_TF32, s > 0);
            tc_commit(sbar);
        }
    }

    stageVT(0, 0);
    fence_async();
    fence_before();
    __syncthreads();   // VT(0) visible before O(0) issue

    float rsum = 0.0f;

    for (int kt = 0; kt < SEQ / 64; kt++) {
        // 0. early LDG of K(kt+2)
        float4 kr[2];
        const bool do_stage = (kt + 2 < SEQ / 64);
        if (do_stage) {
            const float4* k4 = (const float4*)(kb + (size_t)(kt + 2) * 64 * HD);
#pragma unroll
            for (int i = 0; i < 2; i++) kr[i] = k4[tid + i * 512];
        }

        // 1. wait S(kt)
        mbar_wait(sbar, (uint32_t)(kt & 1));
        fence_after();

        // 2. issue SA(kt+1), SB(kt+1) immediately
        if (kt < SEQ / 64 - 1 && wid == 0) {
            if (elect_one()) {
                uint64_t kd = make_desc(sb + AT_K + ((kt + 1) & 1) * 16384);
                uint32_t off = (uint32_t)(((kt + 1) & 1) * 64);
#pragma unroll
                for (int s = 0; s < 8; s++)
                    mma_tf32_ss(SA_T + off, qdA + AOFF(s), kd + BOFF(s), IDESC_TF32, s > 0);
#pragma unroll
                for (int s = 0; s < 8; s++)
                    mma_tf32_ss(SB_T + off, qdB + AOFF(s), kd + BOFF(s), IDESC_TF32, s > 0);
                tc_commit(sbar);
            }
        }

        // 3. softmax: LDTM + ex2 first (hides the O(kt-1) wait), THEN the
        //    obar wait (P/VT protection), then STTM.
        {
            uint32_t v[32];
            ld32(v, S_T + (uint32_t)((kt & 1) * 64 + half * 32));
            tc_wait_ld();
#pragma unroll
            for (int c = 0; c < 32; c++) {
                float e = ex2f(__uint_as_float(v[c]));
                rsum += e;
                v[c] = __float_as_uint(cvt_tf32(e));
            }
            if (kt >= 1) mbar_wait(obar, (uint32_t)((kt + 1) & 1));
            st32(P_T + (uint32_t)(half * 32) + wsub, v);
            tc_wait_st();
        }

        // 4. join: all STTM visible, then issue O(kt) IMMEDIATELY
        fence_before();
        __syncthreads();

        if (wid == 0) {
            fence_after();
            if (elect_one()) {
                uint64_t vd = make_desc(sb + AT_VT + (kt & 1) * 16384);
                uint32_t en0 = (kt > 0);
#pragma unroll
                for (int s = 0; s < 8; s++)
                    mma_tf32_ts(OA_T, PA_T + (uint32_t)(s * 8), vd + BOFF(s),
                                IDESC_TF32, en0 || (s > 0));
#pragma unroll
                for (int s = 0; s < 8; s++)
                    mma_tf32_ts(OB_T, PB_T + (uint32_t)(s * 8), vd + BOFF(s),
                                IDESC_TF32, en0 || (s > 0));
                tc_commit(obar);
            }
        }

        // 5. staging overlaps the in-flight O(kt) mma
        if (do_stage) stageK(kr, kt & 1);
        if (kt + 1 < SEQ / 64) stageVT((kt + 1) & 1, (kt + 1) & 1);

        fence_async();
        fence_before();
        __syncthreads();
    }

    // final: O(63) = flip 64, parity 1
    mbar_wait(obar, 1u);
    fence_after();

    *(float*)(smem + AT_RS(tile * 2 + half) + row * 4) = rsum;
    __syncthreads();

    const float inv = 1.0f / (*(float*)(smem + AT_RS(tile * 2)     + row * 4) +
                              *(float*)(smem + AT_RS(tile * 2 + 1) + row * 4));

    {
        uint32_t orr[32];
        const uint32_t O_T = tmem + 128 + (uint32_t)(tile * 256);
        ld32(orr, O_T + (uint32_t)(half * 32));
        tc_wait_ld();
        float* ob = out + ((size_t)blockIdx.z * SEQ + q0 + tile * 128 + row) * DIM
                        + blockIdx.y * HD + half * 32;
#pragma unroll
        for (int j = 0; j < 32; j += 4)
            *(float4*)(ob + j) = make_float4(__uint_as_float(orr[j]) * inv,
                                             __uint_as_float(orr[j + 1]) * inv,
                                             __uint_as_float(orr[j + 2]) * inv,
                                             __uint_as_float(orr[j + 3]) * inv);
    }

    fence_before();
    __syncthreads();
    if (tid == 0) { mbar_inval(sbar); mbar_inval(obar); }
    if (wid == 0) tc_dealloc(tmem, 512);

#else
    // -------- wmma fallback: 512 threads, halves process their own q-subtile
    extern __shared__ float smf[];
    float* Ks0    = smf;
    float* Ks1    = smf + 64 * LDS;
    float* PsBase = smf + 128 * LDS;
    float* rowinv = smf + 384 * LDS;

    const int tid  = threadIdx.x;
    const int htid = tid & 255;
    const int tile = tid >> 8;
    const int warp = htid >> 5;
    const int lane = tid & 31;
    const int bh   = blockIdx.z * NH + blockIdx.y;
    const int q0   = blockIdx.x * 256 + tile * 128;

    float* Ps = PsBase + tile * 128 * LDS;
    const float* qb = g_q + (size_t)bh * SEQ * HD + (size_t)q0 * HD;
    const float* kb = g_k + (size_t)bh * SEQ * HD;
    const float scale = 0.04419417382415922f;

#pragma unroll
    for (int i = 0; i < 32; i++) {
        int idx = htid + i * 256;
        int r = idx >> 6, c = idx & 63;
        Ps[r * LDS + c] = wmma::__float_to_tf32(qb[idx] * scale);
    }
    __syncthreads();

    FragA qa[8];
#pragma unroll
    for (int kk = 0; kk < 8; kk++)
        wmma::load_matrix_sync(qa[kk], Ps + warp * 16 * LDS + kk * 8, LDS);

#pragma unroll
    for (int i = 0; i < 8; i++) {
        int idx = tid + i * 512;
        int r = idx >> 6, c = idx & 63;
        Ks0[r * LDS + c] = wmma::__float_to_tf32(kb[idx]);
    }
    __syncthreads();

    FragC oacc[4];
#pragma unroll
    for (int n = 0; n < 4; n++) wmma::fill_fragment(oacc[n], 0.0f);

    float rsum = 0.0f;
    float* Pw = Ps + warp * 16 * LDS;

    for (int kt = 0; kt < SEQ / 64; kt++) {
        float* cur = (kt & 1) ? Ks1 : Ks0;
        float* nxt = (kt & 1) ? Ks0 : Ks1;

        if (kt < SEQ / 64 - 1) {
            const float* kp = kb + (size_t)(kt + 1) * 64 * HD;
#pragma unroll
            for (int i = 0; i < 8; i++) {
                int idx = tid + i * 512;
                int r = idx >> 6, c = idx & 63;
                nxt[r * LDS + c] = wmma::__float_to_tf32(kp[idx]);
            }
        }

        FragC sacc[4];
#pragma unroll
        for (int n = 0; n < 4; n++) wmma::fill_fragment(sacc[n], 0.0f);
#pragma unroll
        for (int kk = 0; kk < 8; kk++) {
#pragma unroll
            for (int n = 0; n < 4; n++) {
                FragBc b;
                wmma::load_matrix_sync(b, cur + n * 16 * LDS + kk * 8, LDS);
                wmma::mma_sync(sacc[n], qa[kk], b, sacc[n]);
            }
        }

#pragma unroll
        for (int n = 0; n < 4; n++) {
#pragma unroll
            for (int e = 0; e < sacc[n].num_elements; e++)
                sacc[n].x[e] = wmma::__float_to_tf32(__expf(sacc[n].x[e]));
            wmma::store_matrix_sync(Pw + n * 16, sacc[n], LDS, wmma::mem_row_major);
        }
        __syncwarp();

        {
            const float* pp = Pw + (lane >> 1) * LDS + (lane & 1) * 32;
            float part = 0.0f;
#pragma unroll
            for (int c = 0; c < 32; c++) part += pp[c];
            rsum += part;
        }

#pragma unroll
        for (int kk = 0; kk < 8; kk++) {
            FragA a;
            wmma::load_matrix_sync(a, Pw + kk * 8, LDS);
#pragma unroll
            for (int n = 0; n < 4; n++) {
                FragBr b;
                wmma::load_matrix_sync(b, cur + kk * 8 * LDS + n * 16, LDS);
                wmma::mma_sync(oacc[n], a, b, oacc[n]);
            }
        }

        __syncthreads();
    }

    rsum += __shfl_xor_sync(0xffffffffu, rsum, 1);
    if ((lane & 1) == 0) rowinv[tile * 128 + warp * 16 + (lane >> 1)] = 1.0f / rsum;

#pragma unroll
    for (int n = 0; n < 4; n++)
        wmma::store_matrix_sync(Pw + n * 16, oacc[n], LDS, wmma::mem_row_major);
    __syncthreads();

    float* ob = out + ((size_t)blockIdx.z * SEQ + q0) * DIM + blockIdx.y * HD;
#pragma unroll
    for (int i = 0; i < 32; i++) {
        int idx = htid + i * 256;
        int r = idx >> 6, c = idx & 63;
        ob[(size_t)r * DIM + c] = Ps[r * LDS + c] * rowinv[tile * 128 + r];
    }
#endif
}

// ---------------------------------------------------------------------------
extern "C" void kernel_launch(void* const* d_in, const int* in_sizes, int n_in,
                              void* d_out, int out_size)
{
    const float* x  = (const float*)d_in[0];
    const float* Wq = (const float*)d_in[1];
    const float* bq = (const float*)d_in[2];
    const float* Wk = (const float*)d_in[3];
    const float* bk = (const float*)d_in[4];
    float* out = (float*)d_out;

    cudaFuncSetAttribute(proj_kernel, cudaFuncAttributeMaxDynamicSharedMemorySize, PJ_TOTAL);
    dim3 pg((BATCH * SEQ) / 128, DIM / 64, 2);
    proj_kernel<<<pg, 256, PJ_TOTAL>>>(x, Wq, bq, Wk, bk);

    cudaFuncSetAttribute(attn_kernel, cudaFuncAttributeMaxDynamicSharedMemorySize, ATTN_TOTAL);
    dim3 ag(SEQ / 256, NH, BATCH);
    attn_kernel<<<ag, 512, ATTN_TOTAL>>>(out);
}